// round 7
// baseline (speedup 1.0000x reference)
#include <cuda_runtime.h>
#include <math.h>
#include <stdint.h>

// Problem constants
#define NB      2
#define SEQ     2048
#define HDIM    2048
#define NHEADS  16
#define KVHEADS 4
#define HEADD   128
#define KVDIM   (KVHEADS * HEADD)   // 512
#define MROWS   (NB * SEQ)          // 4096
#define QSTRIDE (NHEADS * HEADD)    // 2048
#define KSTRIDE (KVHEADS * HEADD)   // 512

// Scratch (static device arrays; no runtime allocation allowed)
__device__ float g_Q[(size_t)MROWS * HDIM];   // (b,s,h,d) packed: ((b*S+s)*nh+h)*hd+d
__device__ float g_K[(size_t)MROWS * KVDIM];
__device__ float g_V[(size_t)MROWS * KVDIM];
__device__ float g_O[(size_t)MROWS * HDIM];

// ---------------------------------------------------------------------------
// SGEMM: C[M,N] = A[M,K] @ W[N,K]^T + bias[N]   (row-major, fp32)
// 128x128 block tile, K-step 8, 256 threads, 8x8 per thread.
// ---------------------------------------------------------------------------
__global__ void __launch_bounds__(256) sgemm_nt(
    const float* __restrict__ A, const float* __restrict__ W,
    const float* __restrict__ bias, float* __restrict__ C,
    int K, int N)
{
    __shared__ float As[8][128];   // As[k][m]
    __shared__ float Bs[8][128];   // Bs[k][n]

    const int tid = threadIdx.x;
    const int tx  = tid & 15;
    const int ty  = tid >> 4;
    const int m0  = blockIdx.y * 128;
    const int n0  = blockIdx.x * 128;

    const int r  = tid >> 1;        // 0..127
    const int s4 = (tid & 1) * 4;   // 0 or 4

    const float* Ap = A + (size_t)(m0 + r) * K + s4;
    const float* Wp = W + (size_t)(n0 + r) * K + s4;

    float acc[8][8];
    #pragma unroll
    for (int i = 0; i < 8; i++)
        #pragma unroll
        for (int j = 0; j < 8; j++) acc[i][j] = 0.0f;

    for (int kt = 0; kt < K; kt += 8) {
        float4 av = *(const float4*)(Ap + kt);
        float4 wv = *(const float4*)(Wp + kt);
        __syncthreads();   // previous tile fully consumed
        As[s4 + 0][r] = av.x; As[s4 + 1][r] = av.y;
        As[s4 + 2][r] = av.z; As[s4 + 3][r] = av.w;
        Bs[s4 + 0][r] = wv.x; Bs[s4 + 1][r] = wv.y;
        Bs[s4 + 2][r] = wv.z; Bs[s4 + 3][r] = wv.w;
        __syncthreads();

        #pragma unroll
        for (int k = 0; k < 8; k++) {
            float4 a0 = *(const float4*)&As[k][ty * 4];
            float4 a1 = *(const float4*)&As[k][64 + ty * 4];
            float4 b0 = *(const float4*)&Bs[k][tx * 4];
            float4 b1 = *(const float4*)&Bs[k][64 + tx * 4];
            float a[8] = {a0.x, a0.y, a0.z, a0.w, a1.x, a1.y, a1.z, a1.w};
            float b[8] = {b0.x, b0.y, b0.z, b0.w, b1.x, b1.y, b1.z, b1.w};
            #pragma unroll
            for (int i = 0; i < 8; i++)
                #pragma unroll
                for (int j = 0; j < 8; j++)
                    acc[i][j] += a[i] * b[j];
        }
    }

    // Epilogue with fused bias
    #pragma unroll
    for (int i = 0; i < 8; i++) {
        int row = (i < 4) ? (ty * 4 + i) : (64 + ty * 4 + (i - 4));
        float* Crow = C + (size_t)(m0 + row) * N + n0;
        #pragma unroll
        for (int jh = 0; jh < 2; jh++) {
            int c = jh * 64 + tx * 4;
            float4 o;
            o.x = acc[i][jh * 4 + 0] + bias[n0 + c + 0];
            o.y = acc[i][jh * 4 + 1] + bias[n0 + c + 1];
            o.z = acc[i][jh * 4 + 2] + bias[n0 + c + 2];
            o.w = acc[i][jh * 4 + 3] + bias[n0 + c + 3];
            *(float4*)(Crow + c) = o;
        }
    }
}

// ---------------------------------------------------------------------------
// RoPE in-place on a (B,S,heads,128) tensor. One thread per (b,s,h,d<64) pair.
// out[d]    = x[d]*cos[s,d]   - x[d+64]*sin[s,d]
// out[d+64] = x[d+64]*cos[s,d] + x[d]*sin[s,d]     (cos/sin halves identical)
// ---------------------------------------------------------------------------
__global__ void rope_kernel(float* __restrict__ T,
                            const float* __restrict__ cosb,
                            const float* __restrict__ sinb,
                            int heads, int total)
{
    int idx = blockIdx.x * blockDim.x + threadIdx.x;
    if (idx >= total) return;
    int d  = idx & 63;
    int h  = (idx >> 6) % heads;
    int bs = idx / (64 * heads);
    int s  = bs % SEQ;
    float c  = cosb[s * HEADD + d];
    float sn = sinb[s * HEADD + d];
    float* p = T + ((size_t)bs * heads + h) * HEADD;
    float q0 = p[d], q1 = p[d + 64];
    p[d]      = q0 * c - q1 * sn;
    p[d + 64] = q1 * c + q0 * sn;
}

// ---------------------------------------------------------------------------
// Flash attention, causal, GQA (rep=4). BQ=BK=64, hd=128, 256 threads.
// Q and K stored d-major (transposed) in smem; V natural; P staged in smem.
// smem: Qst[128][64] + Kst[128][64] + Vs[64][128] + Ps[64][64] = 112 KB
// ---------------------------------------------------------------------------
#define BQ 64
#define BK 64
#define ATTN_SMEM ((2 * 128 * 64 + 64 * 128 + 64 * 64) * 4)  // 114688 bytes

__global__ void __launch_bounds__(256) attn_kernel()
{
    extern __shared__ float sm[];
    float (*Qst)[64]  = (float(*)[64]) sm;                          // [128][64]
    float (*Kst)[64]  = (float(*)[64])(sm + 128 * 64);              // [128][64]
    float (*Vs)[128]  = (float(*)[128])(sm + 2 * 128 * 64);         // [64][128]
    float (*Ps)[64]   = (float(*)[64]) (sm + 2 * 128 * 64 + 64 * 128); // [64][64]

    const int tid = threadIdx.x;
    const int tx  = tid & 15;
    const int ty  = tid >> 4;

    // heavier (large q0) blocks first
    const int q0 = (gridDim.x - 1 - blockIdx.x) * BQ;
    const int bh = blockIdx.y;
    const int b  = bh / NHEADS;
    const int h  = bh % NHEADS;
    const int kh = h / (NHEADS / KVHEADS);

    const float* Qbase = g_Q + ((size_t)b * SEQ * NHEADS  + h)  * HEADD;
    const float* Kbase = g_K + ((size_t)b * SEQ * KVHEADS + kh) * HEADD;
    const float* Vbase = g_V + ((size_t)b * SEQ * KVHEADS + kh) * HEADD;

    const float SCALE = 0.08838834764831845f;  // 1/sqrt(128)

    // ---- load Q tile transposed (pre-scaled) ----
    #pragma unroll
    for (int it = 0; it < 2; it++) {
        int sb   = tid + it * 256;     // 0..511
        int rb   = sb & 15;            // row block
        int db   = sb >> 4;            // d block (0..31)
        int row0 = rb * 4, d0 = db * 4;
        float4 r0 = *(const float4*)(Qbase + (size_t)(q0 + row0 + 0) * QSTRIDE + d0);
        float4 r1 = *(const float4*)(Qbase + (size_t)(q0 + row0 + 1) * QSTRIDE + d0);
        float4 r2 = *(const float4*)(Qbase + (size_t)(q0 + row0 + 2) * QSTRIDE + d0);
        float4 r3 = *(const float4*)(Qbase + (size_t)(q0 + row0 + 3) * QSTRIDE + d0);
        float4 c;
        c.x = r0.x * SCALE; c.y = r1.x * SCALE; c.z = r2.x * SCALE; c.w = r3.x * SCALE;
        *(float4*)&Qst[d0 + 0][row0] = c;
        c.x = r0.y * SCALE; c.y = r1.y * SCALE; c.z = r2.y * SCALE; c.w = r3.y * SCALE;
        *(float4*)&Qst[d0 + 1][row0] = c;
        c.x = r0.z * SCALE; c.y = r1.z * SCALE; c.z = r2.z * SCALE; c.w = r3.z * SCALE;
        *(float4*)&Qst[d0 + 2][row0] = c;
        c.x = r0.w * SCALE; c.y = r1.w * SCALE; c.z = r2.w * SCALE; c.w = r3.w * SCALE;
        *(float4*)&Qst[d0 + 3][row0] = c;
    }

    float m_i[4], l_i[4];
    float4 o_acc[4][2];
    #pragma unroll
    for (int i = 0; i < 4; i++) {
        m_i[i] = -INFINITY;
        l_i[i] = 0.0f;
        o_acc[i][0] = make_float4(0.f, 0.f, 0.f, 0.f);
        o_acc[i][1] = make_float4(0.f, 0.f, 0.f, 0.f);
    }

    const int ktiles = q0 / BK + 1;
    for (int kt = 0; kt < ktiles; kt++) {
        const int kv0 = kt * BK;
        __syncthreads();   // previous iteration's Ps/Vs reads complete

        // ---- load K tile transposed ----
        #pragma unroll
        for (int it = 0; it < 2; it++) {
            int sb   = tid + it * 256;
            int rb   = sb & 15;
            int db   = sb >> 4;
            int row0 = rb * 4, d0 = db * 4;
            float4 r0 = *(const float4*)(Kbase + (size_t)(kv0 + row0 + 0) * KSTRIDE + d0);
            float4 r1 = *(const float4*)(Kbase + (size_t)(kv0 + row0 + 1) * KSTRIDE + d0);
            float4 r2 = *(const float4*)(Kbase + (size_t)(kv0 + row0 + 2) * KSTRIDE + d0);
            float4 r3 = *(const float4*)(Kbase + (size_t)(kv0 + row0 + 3) * KSTRIDE + d0);
            float4 c;
            c.x = r0.x; c.y = r1.x; c.z = r2.x; c.w = r3.x; *(float4*)&Kst[d0 + 0][row0] = c;
            c.x = r0.y; c.y = r1.y; c.z = r2.y; c.w = r3.y; *(float4*)&Kst[d0 + 1][row0] = c;
            c.x = r0.z; c.y = r1.z; c.z = r2.z; c.w = r3.z; *(float4*)&Kst[d0 + 2][row0] = c;
            c.x = r0.w; c.y = r1.w; c.z = r2.w; c.w = r3.w; *(float4*)&Kst[d0 + 3][row0] = c;
        }
        // ---- load V tile (natural layout, fully coalesced) ----
        #pragma unroll
        for (int it = 0; it < 8; it++) {
            int lin4 = it * 256 + tid;        // float4 index, 0..2047
            int row  = lin4 >> 5;
            int d4   = (lin4 & 31) * 4;
            *(float4*)&Vs[row][d4] =
                *(const float4*)(Vbase + (size_t)(kv0 + row) * KSTRIDE + d4);
        }
        __syncthreads();

        // ---- S = Q K^T (64x64, each thread 4x4) ----
        float sc[4][4];
        #pragma unroll
        for (int i = 0; i < 4; i++)
            #pragma unroll
            for (int j = 0; j < 4; j++) sc[i][j] = 0.0f;

        #pragma unroll 4
        for (int d = 0; d < 128; d++) {
            float4 qa = *(const float4*)&Qst[d][ty * 4];
            float4 kb = *(const float4*)&Kst[d][tx * 4];
            float a[4] = {qa.x, qa.y, qa.z, qa.w};
            float bb[4] = {kb.x, kb.y, kb.z, kb.w};
            #pragma unroll
            for (int i = 0; i < 4; i++)
                #pragma unroll
                for (int j = 0; j < 4; j++)
                    sc[i][j] += a[i] * bb[j];
        }

        // ---- causal mask (diagonal tile only) ----
        if (kv0 == q0) {
            #pragma unroll
            for (int i = 0; i < 4; i++)
                #pragma unroll
                for (int j = 0; j < 4; j++)
                    if (tx * 4 + j > ty * 4 + i) sc[i][j] = -1.0e30f;
        }

        // ---- online softmax per row (reduce across 16 lanes of same ty) ----
        #pragma unroll
        for (int i = 0; i < 4; i++) {
            float mx = fmaxf(fmaxf(sc[i][0], sc[i][1]), fmaxf(sc[i][2], sc[i][3]));
            #pragma unroll
            for (int w = 8; w >= 1; w >>= 1)
                mx = fmaxf(mx, __shfl_xor_sync(0xffffffffu, mx, w));
            float m_new = fmaxf(m_i[i], mx);
            float corr  = __expf(m_i[i] - m_new);
            float sum = 0.0f;
            #pragma unroll
            for (int j = 0; j < 4; j++) {
                float p = __expf(sc[i][j] - m_new);
                sc[i][j] = p;
                sum += p;
            }
            #pragma unroll
            for (int w = 8; w >= 1; w >>= 1)
                sum += __shfl_xor_sync(0xffffffffu, sum, w);
            l_i[i] = l_i[i] * corr + sum;
            m_i[i] = m_new;
            o_acc[i][0].x *= corr; o_acc[i][0].y *= corr;
            o_acc[i][0].z *= corr; o_acc[i][0].w *= corr;
            o_acc[i][1].x *= corr; o_acc[i][1].y *= corr;
            o_acc[i][1].z *= corr; o_acc[i][1].w *= corr;
            float4 pv = make_float4(sc[i][0], sc[i][1], sc[i][2], sc[i][3]);
            *(float4*)&Ps[ty * 4 + i][tx * 4] = pv;
        }
        __syncthreads();

        // ---- O += P V (each thread 4 rows x 8 cols) ----
        #pragma unroll 4
        for (int k = 0; k < BK; k++) {
            float4 v0 = *(const float4*)&Vs[k][tx * 4];
            float4 v1 = *(const float4*)&Vs[k][64 + tx * 4];
            #pragma unroll
            for (int i = 0; i < 4; i++) {
                float p = Ps[ty * 4 + i][k];
                o_acc[i][0].x += p * v0.x; o_acc[i][0].y += p * v0.y;
                o_acc[i][0].z += p * v0.z; o_acc[i][0].w += p * v0.w;
                o_acc[i][1].x += p * v1.x; o_acc[i][1].y += p * v1.y;
                o_acc[i][1].z += p * v1.z; o_acc[i][1].w += p * v1.w;
            }
        }
    }

    // ---- epilogue: normalize and write to g_O ----
    #pragma unroll
    for (int i = 0; i < 4; i++) {
        float inv = 1.0f / l_i[i];
        int s = q0 + ty * 4 + i;
        float* Orow = g_O + ((size_t)(b * SEQ + s) * NHEADS + h) * HEADD;
        float4 o0 = o_acc[i][0], o1 = o_acc[i][1];
        o0.x *= inv; o0.y *= inv; o0.z *= inv; o0.w *= inv;
        o1.x *= inv; o1.y *= inv; o1.z *= inv; o1.w *= inv;
        *(float4*)(Orow + tx * 4)      = o0;
        *(float4*)(Orow + 64 + tx * 4) = o1;
    }
}

// ---------------------------------------------------------------------------
extern "C" void kernel_launch(void* const* d_in, const int* in_sizes, int n_in,
                              void* d_out, int out_size)
{
    const float* x    = (const float*)d_in[0];
    const float* wq   = (const float*)d_in[1];
    const float* bq   = (const float*)d_in[2];
    const float* wk   = (const float*)d_in[3];
    const float* bk   = (const float*)d_in[4];
    const float* wv   = (const float*)d_in[5];
    const float* bv   = (const float*)d_in[6];
    const float* wo   = (const float*)d_in[7];
    const float* bo   = (const float*)d_in[8];
    const float* cosb = (const float*)d_in[9];
    const float* sinb = (const float*)d_in[10];
    float* out = (float*)d_out;

    float *Qp, *Kp, *Vp, *Op;
    cudaGetSymbolAddress((void**)&Qp, g_Q);
    cudaGetSymbolAddress((void**)&Kp, g_K);
    cudaGetSymbolAddress((void**)&Vp, g_V);
    cudaGetSymbolAddress((void**)&Op, g_O);

    cudaFuncSetAttribute(attn_kernel,
                         cudaFuncAttributeMaxDynamicSharedMemorySize, ATTN_SMEM);

    // 1-3. QKV projections (+bias)
    sgemm_nt<<<dim3(HDIM / 128,  MROWS / 128), 256>>>(x, wq, bq, Qp, HDIM, HDIM);
    sgemm_nt<<<dim3(KVDIM / 128, MROWS / 128), 256>>>(x, wk, bk, Kp, HDIM, KVDIM);
    sgemm_nt<<<dim3(KVDIM / 128, MROWS / 128), 256>>>(x, wv, bv, Vp, HDIM, KVDIM);

    // 4-5. RoPE on Q and K
    {
        int totq = NB * SEQ * NHEADS * 64;
        rope_kernel<<<(totq + 255) / 256, 256>>>(Qp, cosb, sinb, NHEADS, totq);
        int totk = NB * SEQ * KVHEADS * 64;
        rope_kernel<<<(totk + 255) / 256, 256>>>(Kp, cosb, sinb, KVHEADS, totk);
    }

    // 6. Causal GQA flash attention
    attn_kernel<<<dim3(SEQ / BQ, NB * NHEADS), 256, ATTN_SMEM>>>();

    // 7. Output projection (+bias) straight into d_out
    sgemm_nt<<<dim3(HDIM / 128, MROWS / 128), 256>>>(Op, wo, bo, out, HDIM, HDIM);
}

// round 8
// speedup vs baseline: 1.0062x; 1.0062x over previous
#include <cuda_runtime.h>
#include <math.h>
#include <stdint.h>

// Problem constants
#define NB      2
#define SEQ     2048
#define HDIM    2048
#define NHEADS  16
#define KVHEADS 4
#define HEADD   128
#define KVDIM   (KVHEADS * HEADD)   // 512
#define MROWS   (NB * SEQ)          // 4096
#define QSTRIDE (NHEADS * HEADD)    // 2048
#define KSTRIDE (KVHEADS * HEADD)   // 512

// Scratch (static device arrays; no runtime allocation allowed)
__device__ float g_Q[(size_t)MROWS * HDIM];   // (b,s,h,d) packed: ((b*S+s)*nh+h)*hd+d
__device__ float g_K[(size_t)MROWS * KVDIM];
__device__ float g_V[(size_t)MROWS * KVDIM];
__device__ float g_O[(size_t)MROWS * HDIM];

// ---------------------------------------------------------------------------
// SGEMM: C[M,N] = A[M,K] @ W[N,K]^T + bias[N]   (row-major, fp32)
// 128x128 block tile, K-step 8, 256 threads, 8x8 per thread.
// ---------------------------------------------------------------------------
__global__ void __launch_bounds__(256) sgemm_nt(
    const float* __restrict__ A, const float* __restrict__ W,
    const float* __restrict__ bias, float* __restrict__ C,
    int K, int N)
{
    __shared__ float As[8][128];   // As[k][m]
    __shared__ float Bs[8][128];   // Bs[k][n]

    const int tid = threadIdx.x;
    const int tx  = tid & 15;
    const int ty  = tid >> 4;
    const int m0  = blockIdx.y * 128;
    const int n0  = blockIdx.x * 128;

    const int r  = tid >> 1;        // 0..127
    const int s4 = (tid & 1) * 4;   // 0 or 4

    const float* Ap = A + (size_t)(m0 + r) * K + s4;
    const float* Wp = W + (size_t)(n0 + r) * K + s4;

    float acc[8][8];
    #pragma unroll
    for (int i = 0; i < 8; i++)
        #pragma unroll
        for (int j = 0; j < 8; j++) acc[i][j] = 0.0f;

    for (int kt = 0; kt < K; kt += 8) {
        float4 av = *(const float4*)(Ap + kt);
        float4 wv = *(const float4*)(Wp + kt);
        __syncthreads();   // previous tile fully consumed
        As[s4 + 0][r] = av.x; As[s4 + 1][r] = av.y;
        As[s4 + 2][r] = av.z; As[s4 + 3][r] = av.w;
        Bs[s4 + 0][r] = wv.x; Bs[s4 + 1][r] = wv.y;
        Bs[s4 + 2][r] = wv.z; Bs[s4 + 3][r] = wv.w;
        __syncthreads();

        #pragma unroll
        for (int k = 0; k < 8; k++) {
            float4 a0 = *(const float4*)&As[k][ty * 4];
            float4 a1 = *(const float4*)&As[k][64 + ty * 4];
            float4 b0 = *(const float4*)&Bs[k][tx * 4];
            float4 b1 = *(const float4*)&Bs[k][64 + tx * 4];
            float a[8] = {a0.x, a0.y, a0.z, a0.w, a1.x, a1.y, a1.z, a1.w};
            float b[8] = {b0.x, b0.y, b0.z, b0.w, b1.x, b1.y, b1.z, b1.w};
            #pragma unroll
            for (int i = 0; i < 8; i++)
                #pragma unroll
                for (int j = 0; j < 8; j++)
                    acc[i][j] += a[i] * b[j];
        }
    }

    // Epilogue with fused bias
    #pragma unroll
    for (int i = 0; i < 8; i++) {
        int row = (i < 4) ? (ty * 4 + i) : (64 + ty * 4 + (i - 4));
        float* Crow = C + (size_t)(m0 + row) * N + n0;
        #pragma unroll
        for (int jh = 0; jh < 2; jh++) {
            int c = jh * 64 + tx * 4;
            float4 o;
            o.x = acc[i][jh * 4 + 0] + bias[n0 + c + 0];
            o.y = acc[i][jh * 4 + 1] + bias[n0 + c + 1];
            o.z = acc[i][jh * 4 + 2] + bias[n0 + c + 2];
            o.w = acc[i][jh * 4 + 3] + bias[n0 + c + 3];
            *(float4*)(Crow + c) = o;
        }
    }
}

// ---------------------------------------------------------------------------
// RoPE in-place on a (B,S,heads,128) tensor. One thread per (b,s,h,d<64) pair.
// out[d]    = x[d]*cos[s,d]   - x[d+64]*sin[s,d]
// out[d+64] = x[d+64]*cos[s,d] + x[d]*sin[s,d]     (cos/sin halves identical)
// ---------------------------------------------------------------------------
__global__ void rope_kernel(float* __restrict__ T,
                            const float* __restrict__ cosb,
                            const float* __restrict__ sinb,
                            int heads, int total)
{
    int idx = blockIdx.x * blockDim.x + threadIdx.x;
    if (idx >= total) return;
    int d  = idx & 63;
    int h  = (idx >> 6) % heads;
    int bs = idx / (64 * heads);
    int s  = bs % SEQ;
    float c  = cosb[s * HEADD + d];
    float sn = sinb[s * HEADD + d];
    float* p = T + ((size_t)bs * heads + h) * HEADD;
    float q0 = p[d], q1 = p[d + 64];
    p[d]      = q0 * c - q1 * sn;
    p[d + 64] = q1 * c + q0 * sn;
}

// ---------------------------------------------------------------------------
// Flash attention, causal, GQA (rep=4). BQ=BK=64, hd=128, 256 threads.
// Q and K stored d-major (transposed) in smem; V natural; P staged in smem.
// smem: Qst[128][64] + Kst[128][64] + Vs[64][128] + Ps[64][64] = 112 KB
// ---------------------------------------------------------------------------
#define BQ 64
#define BK 64
#define ATTN_SMEM ((2 * 128 * 64 + 64 * 128 + 64 * 64) * 4)  // 114688 bytes

__global__ void __launch_bounds__(256) attn_kernel()
{
    extern __shared__ float sm[];
    float (*Qst)[64]  = (float(*)[64]) sm;                          // [128][64]
    float (*Kst)[64]  = (float(*)[64])(sm + 128 * 64);              // [128][64]
    float (*Vs)[128]  = (float(*)[128])(sm + 2 * 128 * 64);         // [64][128]
    float (*Ps)[64]   = (float(*)[64]) (sm + 2 * 128 * 64 + 64 * 128); // [64][64]

    const int tid = threadIdx.x;
    const int tx  = tid & 15;
    const int ty  = tid >> 4;

    // heavier (large q0) blocks first
    const int q0 = (gridDim.x - 1 - blockIdx.x) * BQ;
    const int bh = blockIdx.y;
    const int b  = bh / NHEADS;
    const int h  = bh % NHEADS;
    const int kh = h / (NHEADS / KVHEADS);

    const float* Qbase = g_Q + ((size_t)b * SEQ * NHEADS  + h)  * HEADD;
    const float* Kbase = g_K + ((size_t)b * SEQ * KVHEADS + kh) * HEADD;
    const float* Vbase = g_V + ((size_t)b * SEQ * KVHEADS + kh) * HEADD;

    const float SCALE = 0.08838834764831845f;  // 1/sqrt(128)

    // ---- load Q tile transposed (pre-scaled) ----
    #pragma unroll
    for (int it = 0; it < 2; it++) {
        int sb   = tid + it * 256;     // 0..511
        int rb   = sb & 15;            // row block
        int db   = sb >> 4;            // d block (0..31)
        int row0 = rb * 4, d0 = db * 4;
        float4 r0 = *(const float4*)(Qbase + (size_t)(q0 + row0 + 0) * QSTRIDE + d0);
        float4 r1 = *(const float4*)(Qbase + (size_t)(q0 + row0 + 1) * QSTRIDE + d0);
        float4 r2 = *(const float4*)(Qbase + (size_t)(q0 + row0 + 2) * QSTRIDE + d0);
        float4 r3 = *(const float4*)(Qbase + (size_t)(q0 + row0 + 3) * QSTRIDE + d0);
        float4 c;
        c.x = r0.x * SCALE; c.y = r1.x * SCALE; c.z = r2.x * SCALE; c.w = r3.x * SCALE;
        *(float4*)&Qst[d0 + 0][row0] = c;
        c.x = r0.y * SCALE; c.y = r1.y * SCALE; c.z = r2.y * SCALE; c.w = r3.y * SCALE;
        *(float4*)&Qst[d0 + 1][row0] = c;
        c.x = r0.z * SCALE; c.y = r1.z * SCALE; c.z = r2.z * SCALE; c.w = r3.z * SCALE;
        *(float4*)&Qst[d0 + 2][row0] = c;
        c.x = r0.w * SCALE; c.y = r1.w * SCALE; c.z = r2.w * SCALE; c.w = r3.w * SCALE;
        *(float4*)&Qst[d0 + 3][row0] = c;
    }

    float m_i[4], l_i[4];
    float4 o_acc[4][2];
    #pragma unroll
    for (int i = 0; i < 4; i++) {
        m_i[i] = -INFINITY;
        l_i[i] = 0.0f;
        o_acc[i][0] = make_float4(0.f, 0.f, 0.f, 0.f);
        o_acc[i][1] = make_float4(0.f, 0.f, 0.f, 0.f);
    }

    const int ktiles = q0 / BK + 1;
    for (int kt = 0; kt < ktiles; kt++) {
        const int kv0 = kt * BK;
        __syncthreads();   // previous iteration's Ps/Vs reads complete

        // ---- load K tile transposed ----
        #pragma unroll
        for (int it = 0; it < 2; it++) {
            int sb   = tid + it * 256;
            int rb   = sb & 15;
            int db   = sb >> 4;
            int row0 = rb * 4, d0 = db * 4;
            float4 r0 = *(const float4*)(Kbase + (size_t)(kv0 + row0 + 0) * KSTRIDE + d0);
            float4 r1 = *(const float4*)(Kbase + (size_t)(kv0 + row0 + 1) * KSTRIDE + d0);
            float4 r2 = *(const float4*)(Kbase + (size_t)(kv0 + row0 + 2) * KSTRIDE + d0);
            float4 r3 = *(const float4*)(Kbase + (size_t)(kv0 + row0 + 3) * KSTRIDE + d0);
            float4 c;
            c.x = r0.x; c.y = r1.x; c.z = r2.x; c.w = r3.x; *(float4*)&Kst[d0 + 0][row0] = c;
            c.x = r0.y; c.y = r1.y; c.z = r2.y; c.w = r3.y; *(float4*)&Kst[d0 + 1][row0] = c;
            c.x = r0.z; c.y = r1.z; c.z = r2.z; c.w = r3.z; *(float4*)&Kst[d0 + 2][row0] = c;
            c.x = r0.w; c.y = r1.w; c.z = r2.w; c.w = r3.w; *(float4*)&Kst[d0 + 3][row0] = c;
        }
        // ---- load V tile (natural layout, fully coalesced) ----
        #pragma unroll
        for (int it = 0; it < 8; it++) {
            int lin4 = it * 256 + tid;        // float4 index, 0..2047
            int row  = lin4 >> 5;
            int d4   = (lin4 & 31) * 4;
            *(float4*)&Vs[row][d4] =
                *(const float4*)(Vbase + (size_t)(kv0 + row) * KSTRIDE + d4);
        }
        __syncthreads();

        // ---- S = Q K^T (64x64, each thread 4x4) ----
        float sc[4][4];
        #pragma unroll
        for (int i = 0; i < 4; i++)
            #pragma unroll
            for (int j = 0; j < 4; j++) sc[i][j] = 0.0f;

        #pragma unroll 4
        for (int d = 0; d < 128; d++) {
            float4 qa = *(const float4*)&Qst[d][ty * 4];
            float4 kb = *(const float4*)&Kst[d][tx * 4];
            float a[4] = {qa.x, qa.y, qa.z, qa.w};
            float bb[4] = {kb.x, kb.y, kb.z, kb.w};
            #pragma unroll
            for (int i = 0; i < 4; i++)
                #pragma unroll
                for (int j = 0; j < 4; j++)
                    sc[i][j] += a[i] * bb[j];
        }

        // ---- causal mask (diagonal tile only) ----
        if (kv0 == q0) {
            #pragma unroll
            for (int i = 0; i < 4; i++)
                #pragma unroll
                for (int j = 0; j < 4; j++)
                    if (tx * 4 + j > ty * 4 + i) sc[i][j] = -1.0e30f;
        }

        // ---- online softmax per row (reduce across 16 lanes of same ty) ----
        #pragma unroll
        for (int i = 0; i < 4; i++) {
            float mx = fmaxf(fmaxf(sc[i][0], sc[i][1]), fmaxf(sc[i][2], sc[i][3]));
            #pragma unroll
            for (int w = 8; w >= 1; w >>= 1)
                mx = fmaxf(mx, __shfl_xor_sync(0xffffffffu, mx, w));
            float m_new = fmaxf(m_i[i], mx);
            float corr  = __expf(m_i[i] - m_new);
            float sum = 0.0f;
            #pragma unroll
            for (int j = 0; j < 4; j++) {
                float p = __expf(sc[i][j] - m_new);
                sc[i][j] = p;
                sum += p;
            }
            #pragma unroll
            for (int w = 8; w >= 1; w >>= 1)
                sum += __shfl_xor_sync(0xffffffffu, sum, w);
            l_i[i] = l_i[i] * corr + sum;
            m_i[i] = m_new;
            o_acc[i][0].x *= corr; o_acc[i][0].y *= corr;
            o_acc[i][0].z *= corr; o_acc[i][0].w *= corr;
            o_acc[i][1].x *= corr; o_acc[i][1].y *= corr;
            o_acc[i][1].z *= corr; o_acc[i][1].w *= corr;
            float4 pv = make_float4(sc[i][0], sc[i][1], sc[i][2], sc[i][3]);
            *(float4*)&Ps[ty * 4 + i][tx * 4] = pv;
        }
        __syncthreads();

        // ---- O += P V (each thread 4 rows x 8 cols) ----
        #pragma unroll 4
        for (int k = 0; k < BK; k++) {
            float4 v0 = *(const float4*)&Vs[k][tx * 4];
            float4 v1 = *(const float4*)&Vs[k][64 + tx * 4];
            #pragma unroll
            for (int i = 0; i < 4; i++) {
                float p = Ps[ty * 4 + i][k];
                o_acc[i][0].x += p * v0.x; o_acc[i][0].y += p * v0.y;
                o_acc[i][0].z += p * v0.z; o_acc[i][0].w += p * v0.w;
                o_acc[i][1].x += p * v1.x; o_acc[i][1].y += p * v1.y;
                o_acc[i][1].z += p * v1.z; o_acc[i][1].w += p * v1.w;
            }
        }
    }

    // ---- epilogue: normalize and write to g_O ----
    #pragma unroll
    for (int i = 0; i < 4; i++) {
        float inv = 1.0f / l_i[i];
        int s = q0 + ty * 4 + i;
        float* Orow = g_O + ((size_t)(b * SEQ + s) * NHEADS + h) * HEADD;
        float4 o0 = o_acc[i][0], o1 = o_acc[i][1];
        o0.x *= inv; o0.y *= inv; o0.z *= inv; o0.w *= inv;
        o1.x *= inv; o1.y *= inv; o1.z *= inv; o1.w *= inv;
        *(float4*)(Orow + tx * 4)      = o0;
        *(float4*)(Orow + 64 + tx * 4) = o1;
    }
}

// ---------------------------------------------------------------------------
extern "C" void kernel_launch(void* const* d_in, const int* in_sizes, int n_in,
                              void* d_out, int out_size)
{
    const float* x    = (const float*)d_in[0];
    const float* wq   = (const float*)d_in[1];
    const float* bq   = (const float*)d_in[2];
    const float* wk   = (const float*)d_in[3];
    const float* bk   = (const float*)d_in[4];
    const float* wv   = (const float*)d_in[5];
    const float* bv   = (const float*)d_in[6];
    const float* wo   = (const float*)d_in[7];
    const float* bo   = (const float*)d_in[8];
    const float* cosb = (const float*)d_in[9];
    const float* sinb = (const float*)d_in[10];
    float* out = (float*)d_out;

    float *Qp, *Kp, *Vp, *Op;
    cudaGetSymbolAddress((void**)&Qp, g_Q);
    cudaGetSymbolAddress((void**)&Kp, g_K);
    cudaGetSymbolAddress((void**)&Vp, g_V);
    cudaGetSymbolAddress((void**)&Op, g_O);

    cudaFuncSetAttribute(attn_kernel,
                         cudaFuncAttributeMaxDynamicSharedMemorySize, ATTN_SMEM);

    // 1-3. QKV projections (+bias)
    sgemm_nt<<<dim3(HDIM / 128,  MROWS / 128), 256>>>(x, wq, bq, Qp, HDIM, HDIM);
    sgemm_nt<<<dim3(KVDIM / 128, MROWS / 128), 256>>>(x, wk, bk, Kp, HDIM, KVDIM);
    sgemm_nt<<<dim3(KVDIM / 128, MROWS / 128), 256>>>(x, wv, bv, Vp, HDIM, KVDIM);

    // 4-5. RoPE on Q and K
    {
        int totq = NB * SEQ * NHEADS * 64;
        rope_kernel<<<(totq + 255) / 256, 256>>>(Qp, cosb, sinb, NHEADS, totq);
        int totk = NB * SEQ * KVHEADS * 64;
        rope_kernel<<<(totk + 255) / 256, 256>>>(Kp, cosb, sinb, KVHEADS, totk);
    }

    // 6. Causal GQA flash attention
    attn_kernel<<<dim3(SEQ / BQ, NB * NHEADS), 256, ATTN_SMEM>>>();

    // 7. Output projection (+bias) straight into d_out
    sgemm_nt<<<dim3(HDIM / 128, MROWS / 128), 256>>>(Op, wo, bo, out, HDIM, HDIM);
}

// round 10
// speedup vs baseline: 1.7144x; 1.7038x over previous
#include <cuda_runtime.h>
#include <cuda_bf16.h>
#include <math.h>
#include <stdint.h>

// Problem constants
#define NB      2
#define SEQ     2048
#define HDIM    2048
#define NHEADS  16
#define KVHEADS 4
#define HEADD   128
#define KVDIM   (KVHEADS * HEADD)   // 512
#define MROWS   (NB * SEQ)          // 4096
#define QSTRIDE (NHEADS * HEADD)    // 2048
#define KSTRIDE (KVHEADS * HEADD)   // 512

// Scratch (static device arrays; no runtime allocation allowed)
__device__ float g_Q[(size_t)MROWS * HDIM];
__device__ float g_K[(size_t)MROWS * KVDIM];
__device__ float g_V[(size_t)MROWS * KVDIM];
__device__ float g_O[(size_t)MROWS * HDIM];

// ===========================================================================
// Helpers
// ===========================================================================
__device__ __forceinline__ uint32_t smem_to_u32(const void* p) {
    uint32_t a;
    asm("{ .reg .u64 t; cvta.to.shared.u64 t, %1; cvt.u32.u64 %0, t; }"
        : "=r"(a) : "l"(p));
    return a;
}

// bf16x3 split: (a,b) -> packed hi bf16x2 + packed lo bf16x2
__device__ __forceinline__ void split3(float a, float b, uint32_t& hi, uint32_t& lo)
{
    __nv_bfloat162 h = __floats2bfloat162_rn(a, b);
    float2 hf = __bfloat1622float2(h);
    __nv_bfloat162 l = __floats2bfloat162_rn(a - hf.x, b - hf.y);
    hi = *reinterpret_cast<uint32_t*>(&h);
    lo = *reinterpret_cast<uint32_t*>(&l);
}

__device__ __forceinline__ void ldsm_x4(uint32_t* r, uint32_t addr)
{
    asm volatile("ldmatrix.sync.aligned.m8n8.x4.shared.b16 {%0,%1,%2,%3}, [%4];"
        : "=r"(r[0]), "=r"(r[1]), "=r"(r[2]), "=r"(r[3]) : "r"(addr));
}

__device__ __forceinline__ void mma16816(float* d, const uint32_t* a,
                                         uint32_t b0, uint32_t b1)
{
    asm volatile(
        "mma.sync.aligned.m16n8k16.row.col.f32.bf16.bf16.f32 "
        "{%0,%1,%2,%3}, {%4,%5,%6,%7}, {%8,%9}, {%0,%1,%2,%3};"
        : "+f"(d[0]), "+f"(d[1]), "+f"(d[2]), "+f"(d[3])
        : "r"(a[0]), "r"(a[1]), "r"(a[2]), "r"(a[3]), "r"(b0), "r"(b1));
}

// ===========================================================================
// bf16x3 tensor-core GEMM: C[M,N] = A[M,K] @ W[N,K]^T + bias[N] (fp32 in/out)
// CTA 128x128, K-chunk 32, 8 warps (warp tile 32x64), double-buffered smem.
// smem stage (32KB): Ahi[128][32] | Alo | Bhi[128][32] | Blo  (bf16, swizzled)
// Swizzle: 64B rows of 4 16B-chunks; chunk c stored at c ^ ((row>>1)&3).
// ===========================================================================
#define GEMM_SMEM (2 * 32768)

// Load + split one 128x32 fp32 tile into hi/lo bf16 smem tiles.
__device__ __forceinline__ void load_tile_pair(
    const float* __restrict__ src, int ld, int base0,
    char* dsthi, char* dstlo, int kc, int tid)
{
    #pragma unroll
    for (int j = 0; j < 2; j++) {
        int job = tid + j * 256;            // 0..511
        int row = job >> 2, c16 = job & 3;  // 16B chunk = 8 k-values
        const float* p = src + (size_t)(base0 + row) * ld + kc + c16 * 8;
        float4 f0 = *(const float4*)p;
        float4 f1 = *(const float4*)(p + 4);
        uint32_t h0, l0, h1, l1, h2, l2, h3, l3;
        split3(f0.x, f0.y, h0, l0);
        split3(f0.z, f0.w, h1, l1);
        split3(f1.x, f1.y, h2, l2);
        split3(f1.z, f1.w, h3, l3);
        uint32_t off = (uint32_t)row * 64 + ((c16 ^ ((row >> 1) & 3)) << 4);
        *(uint4*)(dsthi + off) = make_uint4(h0, h1, h2, h3);
        *(uint4*)(dstlo + off) = make_uint4(l0, l1, l2, l3);
    }
}

__global__ void __launch_bounds__(256, 2) gemm_mma_bf16x3(
    const float* __restrict__ A, const float* __restrict__ W,
    const float* __restrict__ bias, float* __restrict__ C,
    int K, int N)
{
    extern __shared__ char smem[];
    const uint32_t sb32 = smem_to_u32(smem);

    const int tid  = threadIdx.x;
    const int lane = tid & 31;
    const int wid  = tid >> 5;
    const int wm   = (wid >> 1) * 32;   // warp m-offset: 0,32,64,96
    const int wn   = (wid & 1) * 64;    // warp n-offset: 0,64
    const int m0   = blockIdx.y * 128;
    const int n0   = blockIdx.x * 128;

    float acc[2][8][4];
    #pragma unroll
    for (int i = 0; i < 2; i++)
        #pragma unroll
        for (int j = 0; j < 8; j++)
            #pragma unroll
            for (int q = 0; q < 4; q++) acc[i][j][q] = 0.0f;

    const int NCH = K >> 5;   // K-chunks of 32

    // prologue: chunk 0 -> stage 0
    load_tile_pair(A, K, m0, smem,          smem + 8192,  0, tid);
    load_tile_pair(W, K, n0, smem + 16384,  smem + 24576, 0, tid);
    __syncthreads();

    for (int c = 0; c < NCH; c++) {
        // prefetch chunk c+1 into the other stage (safe: that stage's MMAs
        // finished before the sync at end of iteration c-1)
        if (c + 1 < NCH) {
            char* st = smem + (((c + 1) & 1) << 15);
            load_tile_pair(A, K, m0, st,          st + 8192,  (c + 1) << 5, tid);
            load_tile_pair(W, K, n0, st + 16384,  st + 24576, (c + 1) << 5, tid);
        }

        const uint32_t stb = sb32 + ((c & 1) << 15);

        #pragma unroll
        for (int ks = 0; ks < 2; ks++) {     // two k16 steps per chunk
            // ---- A fragments (hi + lo), 2 m-tiles ----
            uint32_t ah[2][4], al[2][4];
            #pragma unroll
            for (int mt = 0; mt < 2; mt++) {
                int row = wm + mt * 16 + (lane & 15);
                int c16 = ks * 2 + (lane >> 4);
                uint32_t ad = stb + (uint32_t)row * 64 +
                              ((c16 ^ ((row >> 1) & 3)) << 4);
                ldsm_x4(ah[mt], ad);
                ldsm_x4(al[mt], ad + 8192);
            }
            // ---- B groups of 2 n-tiles ----
            #pragma unroll
            for (int g = 0; g < 4; g++) {
                int n   = wn + g * 16 + ((lane >> 4) & 1) * 8 + (lane & 7);
                int c16 = ks * 2 + ((lane >> 3) & 1);
                uint32_t bd = stb + 16384 + (uint32_t)n * 64 +
                              ((c16 ^ ((n >> 1) & 3)) << 4);
                uint32_t bh[4], bl[4];
                ldsm_x4(bh, bd);
                ldsm_x4(bl, bd + 8192);
                #pragma unroll
                for (int mt = 0; mt < 2; mt++) {
                    #pragma unroll
                    for (int nt = 0; nt < 2; nt++) {
                        float* d = acc[mt][g * 2 + nt];
                        mma16816(d, ah[mt], bh[nt * 2], bh[nt * 2 + 1]); // hi*hi
                        mma16816(d, ah[mt], bl[nt * 2], bl[nt * 2 + 1]); // hi*lo
                        mma16816(d, al[mt], bh[nt * 2], bh[nt * 2 + 1]); // lo*hi
                    }
                }
            }
        }
        __syncthreads();
    }

    // ---- epilogue: fused bias, float2 stores ----
    #pragma unroll
    for (int mt = 0; mt < 2; mt++) {
        int row0 = m0 + wm + mt * 16 + (lane >> 2);
        int row1 = row0 + 8;
        #pragma unroll
        for (int n8 = 0; n8 < 8; n8++) {
            int col = n0 + wn + n8 * 8 + (lane & 3) * 2;
            float b0 = bias[col], b1 = bias[col + 1];
            float2 o0 = make_float2(acc[mt][n8][0] + b0, acc[mt][n8][1] + b1);
            float2 o1 = make_float2(acc[mt][n8][2] + b0, acc[mt][n8][3] + b1);
            *(float2*)(C + (size_t)row0 * N + col) = o0;
            *(float2*)(C + (size_t)row1 * N + col) = o1;
        }
    }
}

// ---------------------------------------------------------------------------
// RoPE in-place on a (B,S,heads,128) tensor.
// ---------------------------------------------------------------------------
__global__ void rope_kernel(float* __restrict__ T,
                            const float* __restrict__ cosb,
                            const float* __restrict__ sinb,
                            int heads, int total)
{
    int idx = blockIdx.x * blockDim.x + threadIdx.x;
    if (idx >= total) return;
    int d  = idx & 63;
    int h  = (idx >> 6) % heads;
    int bs = idx / (64 * heads);
    int s  = bs % SEQ;
    float c  = cosb[s * HEADD + d];
    float sn = sinb[s * HEADD + d];
    float* p = T + ((size_t)bs * heads + h) * HEADD;
    float q0 = p[d], q1 = p[d + 64];
    p[d]      = q0 * c - q1 * sn;
    p[d + 64] = q1 * c + q0 * sn;
}

// ---------------------------------------------------------------------------
// Flash attention, causal, GQA (rep=4). BQ=BK=64, hd=128, 256 threads. fp32.
// (unchanged from the 3489us passing kernel)
// ---------------------------------------------------------------------------
#define BQ 64
#define BK 64
#define ATTN_SMEM ((2 * 128 * 64 + 64 * 128 + 64 * 64) * 4)  // 114688 bytes

__global__ void __launch_bounds__(256) attn_kernel()
{
    extern __shared__ float sm[];
    float (*Qst)[64]  = (float(*)[64]) sm;                              // [128][64]
    float (*Kst)[64]  = (float(*)[64])(sm + 128 * 64);                  // [128][64]
    float (*Vs)[128]  = (float(*)[128])(sm + 2 * 128 * 64);             // [64][128]
    float (*Ps)[64]   = (float(*)[64]) (sm + 2 * 128 * 64 + 64 * 128);  // [64][64]

    const int tid = threadIdx.x;
    const int tx  = tid & 15;
    const int ty  = tid >> 4;

    const int q0 = (gridDim.x - 1 - blockIdx.x) * BQ;
    const int bh = blockIdx.y;
    const int b  = bh / NHEADS;
    const int h  = bh % NHEADS;
    const int kh = h / (NHEADS / KVHEADS);

    const float* Qbase = g_Q + ((size_t)b * SEQ * NHEADS  + h)  * HEADD;
    const float* Kbase = g_K + ((size_t)b * SEQ * KVHEADS + kh) * HEADD;
    const float* Vbase = g_V + ((size_t)b * SEQ * KVHEADS + kh) * HEADD;

    const float SCALE = 0.08838834764831845f;

    #pragma unroll
    for (int it = 0; it < 2; it++) {
        int sb   = tid + it * 256;
        int rb   = sb & 15;
        int db   = sb >> 4;
        int row0 = rb * 4, d0 = db * 4;
        float4 r0 = *(const float4*)(Qbase + (size_t)(q0 + row0 + 0) * QSTRIDE + d0);
        float4 r1 = *(const float4*)(Qbase + (size_t)(q0 + row0 + 1) * QSTRIDE + d0);
        float4 r2 = *(const float4*)(Qbase + (size_t)(q0 + row0 + 2) * QSTRIDE + d0);
        float4 r3 = *(const float4*)(Qbase + (size_t)(q0 + row0 + 3) * QSTRIDE + d0);
        float4 c;
        c.x = r0.x * SCALE; c.y = r1.x * SCALE; c.z = r2.x * SCALE; c.w = r3.x * SCALE;
        *(float4*)&Qst[d0 + 0][row0] = c;
        c.x = r0.y * SCALE; c.y = r1.y * SCALE; c.z = r2.y * SCALE; c.w = r3.y * SCALE;
        *(float4*)&Qst[d0 + 1][row0] = c;
        c.x = r0.z * SCALE; c.y = r1.z * SCALE; c.z = r2.z * SCALE; c.w = r3.z * SCALE;
        *(float4*)&Qst[d0 + 2][row0] = c;
        c.x = r0.w * SCALE; c.y = r1.w * SCALE; c.z = r2.w * SCALE; c.w = r3.w * SCALE;
        *(float4*)&Qst[d0 + 3][row0] = c;
    }

    float m_i[4], l_i[4];
    float4 o_acc[4][2];
    #pragma unroll
    for (int i = 0; i < 4; i++) {
        m_i[i] = -INFINITY;
        l_i[i] = 0.0f;
        o_acc[i][0] = make_float4(0.f, 0.f, 0.f, 0.f);
        o_acc[i][1] = make_float4(0.f, 0.f, 0.f, 0.f);
    }

    const int ktiles = q0 / BK + 1;
    for (int kt = 0; kt < ktiles; kt++) {
        const int kv0 = kt * BK;
        __syncthreads();

        #pragma unroll
        for (int it = 0; it < 2; it++) {
            int sb   = tid + it * 256;
            int rb   = sb & 15;
            int db   = sb >> 4;
            int row0 = rb * 4, d0 = db * 4;
            float4 r0 = *(const float4*)(Kbase + (size_t)(kv0 + row0 + 0) * KSTRIDE + d0);
            float4 r1 = *(const float4*)(Kbase + (size_t)(kv0 + row0 + 1) * KSTRIDE + d0);
            float4 r2 = *(const float4*)(Kbase + (size_t)(kv0 + row0 + 2) * KSTRIDE + d0);
            float4 r3 = *(const float4*)(Kbase + (size_t)(kv0 + row0 + 3) * KSTRIDE + d0);
            float4 c;
            c.x = r0.x; c.y = r1.x; c.z = r2.x; c.w = r3.x; *(float4*)&Kst[d0 + 0][row0] = c;
            c.x = r0.y; c.y = r1.y; c.z = r2.y; c.w = r3.y; *(float4*)&Kst[d0 + 1][row0] = c;
            c.x = r0.z; c.y = r1.z; c.z = r2.z; c.w = r3.z; *(float4*)&Kst[d0 + 2][row0] = c;
            c.x = r0.w; c.y = r1.w; c.z = r2.w; c.w = r3.w; *(float4*)&Kst[d0 + 3][row0] = c;
        }
        #pragma unroll
        for (int it = 0; it < 8; it++) {
            int lin4 = it * 256 + tid;
            int row  = lin4 >> 5;
            int d4   = (lin4 & 31) * 4;
            *(float4*)&Vs[row][d4] =
                *(const float4*)(Vbase + (size_t)(kv0 + row) * KSTRIDE + d4);
        }
        __syncthreads();

        float sc[4][4];
        #pragma unroll
        for (int i = 0; i < 4; i++)
            #pragma unroll
            for (int j = 0; j < 4; j++) sc[i][j] = 0.0f;

        #pragma unroll 4
        for (int d = 0; d < 128; d++) {
            float4 qa = *(const float4*)&Qst[d][ty * 4];
            float4 kb = *(const float4*)&Kst[d][tx * 4];
            float a[4] = {qa.x, qa.y, qa.z, qa.w};
            float bb[4] = {kb.x, kb.y, kb.z, kb.w};
            #pragma unroll
            for (int i = 0; i < 4; i++)
                #pragma unroll
                for (int j = 0; j < 4; j++)
                    sc[i][j] += a[i] * bb[j];
        }

        if (kv0 == q0) {
            #pragma unroll
            for (int i = 0; i < 4; i++)
                #pragma unroll
                for (int j = 0; j < 4; j++)
                    if (tx * 4 + j > ty * 4 + i) sc[i][j] = -1.0e30f;
        }

        #pragma unroll
        for (int i = 0; i < 4; i++) {
            float mx = fmaxf(fmaxf(sc[i][0], sc[i][1]), fmaxf(sc[i][2], sc[i][3]));
            #pragma unroll
            for (int w = 8; w >= 1; w >>= 1)
                mx = fmaxf(mx, __shfl_xor_sync(0xffffffffu, mx, w));
            float m_new = fmaxf(m_i[i], mx);
            float corr  = __expf(m_i[i] - m_new);
            float sum = 0.0f;
            #pragma unroll
            for (int j = 0; j < 4; j++) {
                float p = __expf(sc[i][j] - m_new);
                sc[i][j] = p;
                sum += p;
            }
            #pragma unroll
            for (int w = 8; w >= 1; w >>= 1)
                sum += __shfl_xor_sync(0xffffffffu, sum, w);
            l_i[i] = l_i[i] * corr + sum;
            m_i[i] = m_new;
            o_acc[i][0].x *= corr; o_acc[i][0].y *= corr;
            o_acc[i][0].z *= corr; o_acc[i][0].w *= corr;
            o_acc[i][1].x *= corr; o_acc[i][1].y *= corr;
            o_acc[i][1].z *= corr; o_acc[i][1].w *= corr;
            float4 pv = make_float4(sc[i][0], sc[i][1], sc[i][2], sc[i][3]);
            *(float4*)&Ps[ty * 4 + i][tx * 4] = pv;
        }
        __syncthreads();

        #pragma unroll 4
        for (int k = 0; k < BK; k++) {
            float4 v0 = *(const float4*)&Vs[k][tx * 4];
            float4 v1 = *(const float4*)&Vs[k][64 + tx * 4];
            #pragma unroll
            for (int i = 0; i < 4; i++) {
                float p = Ps[ty * 4 + i][k];
                o_acc[i][0].x += p * v0.x; o_acc[i][0].y += p * v0.y;
                o_acc[i][0].z += p * v0.z; o_acc[i][0].w += p * v0.w;
                o_acc[i][1].x += p * v1.x; o_acc[i][1].y += p * v1.y;
                o_acc[i][1].z += p * v1.z; o_acc[i][1].w += p * v1.w;
            }
        }
    }

    #pragma unroll
    for (int i = 0; i < 4; i++) {
        float inv = 1.0f / l_i[i];
        int s = q0 + ty * 4 + i;
        float* Orow = g_O + ((size_t)(b * SEQ + s) * NHEADS + h) * HEADD;
        float4 o0 = o_acc[i][0], o1 = o_acc[i][1];
        o0.x *= inv; o0.y *= inv; o0.z *= inv; o0.w *= inv;
        o1.x *= inv; o1.y *= inv; o1.z *= inv; o1.w *= inv;
        *(float4*)(Orow + tx * 4)      = o0;
        *(float4*)(Orow + 64 + tx * 4) = o1;
    }
}

// ---------------------------------------------------------------------------
extern "C" void kernel_launch(void* const* d_in, const int* in_sizes, int n_in,
                              void* d_out, int out_size)
{
    const float* x    = (const float*)d_in[0];
    const float* wq   = (const float*)d_in[1];
    const float* bq   = (const float*)d_in[2];
    const float* wk   = (const float*)d_in[3];
    const float* bk   = (const float*)d_in[4];
    const float* wv   = (const float*)d_in[5];
    const float* bv   = (const float*)d_in[6];
    const float* wo   = (const float*)d_in[7];
    const float* bo   = (const float*)d_in[8];
    const float* cosb = (const float*)d_in[9];
    const float* sinb = (const float*)d_in[10];
    float* out = (float*)d_out;

    float *Qp, *Kp, *Vp, *Op;
    cudaGetSymbolAddress((void**)&Qp, g_Q);
    cudaGetSymbolAddress((void**)&Kp, g_K);
    cudaGetSymbolAddress((void**)&Vp, g_V);
    cudaGetSymbolAddress((void**)&Op, g_O);

    cudaFuncSetAttribute(gemm_mma_bf16x3,
                         cudaFuncAttributeMaxDynamicSharedMemorySize, GEMM_SMEM);
    cudaFuncSetAttribute(attn_kernel,
                         cudaFuncAttributeMaxDynamicSharedMemorySize, ATTN_SMEM);

    // 1-3. QKV projections (+bias) on tensor cores (bf16x3)
    gemm_mma_bf16x3<<<dim3(HDIM / 128,  MROWS / 128), 256, GEMM_SMEM>>>(x, wq, bq, Qp, HDIM, HDIM);
    gemm_mma_bf16x3<<<dim3(KVDIM / 128, MROWS / 128), 256, GEMM_SMEM>>>(x, wk, bk, Kp, HDIM, KVDIM);
    gemm_mma_bf16x3<<<dim3(KVDIM / 128, MROWS / 128), 256, GEMM_SMEM>>>(x, wv, bv, Vp, HDIM, KVDIM);

    // 4-5. RoPE on Q and K
    {
        int totq = NB * SEQ * NHEADS * 64;
        rope_kernel<<<(totq + 255) / 256, 256>>>(Qp, cosb, sinb, NHEADS, totq);
        int totk = NB * SEQ * KVHEADS * 64;
        rope_kernel<<<(totk + 255) / 256, 256>>>(Kp, cosb, sinb, KVHEADS, totk);
    }

    // 6. Causal GQA flash attention (fp32)
    attn_kernel<<<dim3(SEQ / BQ, NB * NHEADS), 256, ATTN_SMEM>>>();

    // 7. Output projection (+bias) straight into d_out
    gemm_mma_bf16x3<<<dim3(HDIM / 128, MROWS / 128), 256, GEMM_SMEM>>>(Op, wo, bo, out, HDIM, HDIM);
}

// round 11
// speedup vs baseline: 2.7736x; 1.6179x over previous
#include <cuda_runtime.h>
#include <cuda_bf16.h>
#include <math.h>
#include <stdint.h>

// Problem constants
#define NB      2
#define SEQ     2048
#define HDIM    2048
#define NHEADS  16
#define KVHEADS 4
#define HEADD   128
#define KVDIM   (KVHEADS * HEADD)   // 512
#define MROWS   (NB * SEQ)          // 4096
#define QSTRIDE (NHEADS * HEADD)    // 2048
#define KSTRIDE (KVHEADS * HEADD)   // 512

// Scratch (static device arrays; no runtime allocation allowed)
__device__ float g_Q[(size_t)MROWS * HDIM];
__device__ float g_K[(size_t)MROWS * KVDIM];
__device__ float g_V[(size_t)MROWS * KVDIM];
__device__ float g_O[(size_t)MROWS * HDIM];

// ===========================================================================
// Helpers
// ===========================================================================
__device__ __forceinline__ uint32_t smem_to_u32(const void* p) {
    uint32_t a;
    asm("{ .reg .u64 t; cvta.to.shared.u64 t, %1; cvt.u32.u64 %0, t; }"
        : "=r"(a) : "l"(p));
    return a;
}

// bf16x3 split: (a,b) -> packed hi bf16x2 + packed lo bf16x2
__device__ __forceinline__ void split3(float a, float b, uint32_t& hi, uint32_t& lo)
{
    __nv_bfloat162 h = __floats2bfloat162_rn(a, b);
    float2 hf = __bfloat1622float2(h);
    __nv_bfloat162 l = __floats2bfloat162_rn(a - hf.x, b - hf.y);
    hi = *reinterpret_cast<uint32_t*>(&h);
    lo = *reinterpret_cast<uint32_t*>(&l);
}

__device__ __forceinline__ void ldsm_x4(uint32_t* r, uint32_t addr)
{
    asm volatile("ldmatrix.sync.aligned.m8n8.x4.shared.b16 {%0,%1,%2,%3}, [%4];"
        : "=r"(r[0]), "=r"(r[1]), "=r"(r[2]), "=r"(r[3]) : "r"(addr));
}

__device__ __forceinline__ void ldsm_x4_trans(uint32_t* r, uint32_t addr)
{
    asm volatile("ldmatrix.sync.aligned.m8n8.x4.trans.shared.b16 {%0,%1,%2,%3}, [%4];"
        : "=r"(r[0]), "=r"(r[1]), "=r"(r[2]), "=r"(r[3]) : "r"(addr));
}

__device__ __forceinline__ void mma16816(float* d, const uint32_t* a,
                                         uint32_t b0, uint32_t b1)
{
    asm volatile(
        "mma.sync.aligned.m16n8k16.row.col.f32.bf16.bf16.f32 "
        "{%0,%1,%2,%3}, {%4,%5,%6,%7}, {%8,%9}, {%0,%1,%2,%3};"
        : "+f"(d[0]), "+f"(d[1]), "+f"(d[2]), "+f"(d[3])
        : "r"(a[0]), "r"(a[1]), "r"(a[2]), "r"(a[3]), "r"(b0), "r"(b1));
}

// ===========================================================================
// bf16x3 tensor-core GEMM: C[M,N] = A[M,K] @ W[N,K]^T + bias[N] (fp32 in/out)
// (unchanged from R10 passing kernel)
// ===========================================================================
#define GEMM_SMEM (2 * 32768)

__device__ __forceinline__ void load_tile_pair(
    const float* __restrict__ src, int ld, int base0,
    char* dsthi, char* dstlo, int kc, int tid)
{
    #pragma unroll
    for (int j = 0; j < 2; j++) {
        int job = tid + j * 256;            // 0..511
        int row = job >> 2, c16 = job & 3;  // 16B chunk = 8 k-values
        const float* p = src + (size_t)(base0 + row) * ld + kc + c16 * 8;
        float4 f0 = *(const float4*)p;
        float4 f1 = *(const float4*)(p + 4);
        uint32_t h0, l0, h1, l1, h2, l2, h3, l3;
        split3(f0.x, f0.y, h0, l0);
        split3(f0.z, f0.w, h1, l1);
        split3(f1.x, f1.y, h2, l2);
        split3(f1.z, f1.w, h3, l3);
        uint32_t off = (uint32_t)row * 64 + ((c16 ^ ((row >> 1) & 3)) << 4);
        *(uint4*)(dsthi + off) = make_uint4(h0, h1, h2, h3);
        *(uint4*)(dstlo + off) = make_uint4(l0, l1, l2, l3);
    }
}

__global__ void __launch_bounds__(256, 2) gemm_mma_bf16x3(
    const float* __restrict__ A, const float* __restrict__ W,
    const float* __restrict__ bias, float* __restrict__ C,
    int K, int N)
{
    extern __shared__ char smem[];
    const uint32_t sb32 = smem_to_u32(smem);

    const int tid  = threadIdx.x;
    const int lane = tid & 31;
    const int wid  = tid >> 5;
    const int wm   = (wid >> 1) * 32;
    const int wn   = (wid & 1) * 64;
    const int m0   = blockIdx.y * 128;
    const int n0   = blockIdx.x * 128;

    float acc[2][8][4];
    #pragma unroll
    for (int i = 0; i < 2; i++)
        #pragma unroll
        for (int j = 0; j < 8; j++)
            #pragma unroll
            for (int q = 0; q < 4; q++) acc[i][j][q] = 0.0f;

    const int NCH = K >> 5;

    load_tile_pair(A, K, m0, smem,          smem + 8192,  0, tid);
    load_tile_pair(W, K, n0, smem + 16384,  smem + 24576, 0, tid);
    __syncthreads();

    for (int c = 0; c < NCH; c++) {
        if (c + 1 < NCH) {
            char* st = smem + (((c + 1) & 1) << 15);
            load_tile_pair(A, K, m0, st,          st + 8192,  (c + 1) << 5, tid);
            load_tile_pair(W, K, n0, st + 16384,  st + 24576, (c + 1) << 5, tid);
        }

        const uint32_t stb = sb32 + ((c & 1) << 15);

        #pragma unroll
        for (int ks = 0; ks < 2; ks++) {
            uint32_t ah[2][4], al[2][4];
            #pragma unroll
            for (int mt = 0; mt < 2; mt++) {
                int row = wm + mt * 16 + (lane & 15);
                int c16 = ks * 2 + (lane >> 4);
                uint32_t ad = stb + (uint32_t)row * 64 +
                              ((c16 ^ ((row >> 1) & 3)) << 4);
                ldsm_x4(ah[mt], ad);
                ldsm_x4(al[mt], ad + 8192);
            }
            #pragma unroll
            for (int g = 0; g < 4; g++) {
                int n   = wn + g * 16 + ((lane >> 4) & 1) * 8 + (lane & 7);
                int c16 = ks * 2 + ((lane >> 3) & 1);
                uint32_t bd = stb + 16384 + (uint32_t)n * 64 +
                              ((c16 ^ ((n >> 1) & 3)) << 4);
                uint32_t bh[4], bl[4];
                ldsm_x4(bh, bd);
                ldsm_x4(bl, bd + 8192);
                #pragma unroll
                for (int mt = 0; mt < 2; mt++) {
                    #pragma unroll
                    for (int nt = 0; nt < 2; nt++) {
                        float* d = acc[mt][g * 2 + nt];
                        mma16816(d, ah[mt], bh[nt * 2], bh[nt * 2 + 1]);
                        mma16816(d, ah[mt], bl[nt * 2], bl[nt * 2 + 1]);
                        mma16816(d, al[mt], bh[nt * 2], bh[nt * 2 + 1]);
                    }
                }
            }
        }
        __syncthreads();
    }

    #pragma unroll
    for (int mt = 0; mt < 2; mt++) {
        int row0 = m0 + wm + mt * 16 + (lane >> 2);
        int row1 = row0 + 8;
        #pragma unroll
        for (int n8 = 0; n8 < 8; n8++) {
            int col = n0 + wn + n8 * 8 + (lane & 3) * 2;
            float b0 = bias[col], b1 = bias[col + 1];
            float2 o0 = make_float2(acc[mt][n8][0] + b0, acc[mt][n8][1] + b1);
            float2 o1 = make_float2(acc[mt][n8][2] + b0, acc[mt][n8][3] + b1);
            *(float2*)(C + (size_t)row0 * N + col) = o0;
            *(float2*)(C + (size_t)row1 * N + col) = o1;
        }
    }
}

// ---------------------------------------------------------------------------
// RoPE in-place on a (B,S,heads,128) tensor.
// ---------------------------------------------------------------------------
__global__ void rope_kernel(float* __restrict__ T,
                            const float* __restrict__ cosb,
                            const float* __restrict__ sinb,
                            int heads, int total)
{
    int idx = blockIdx.x * blockDim.x + threadIdx.x;
    if (idx >= total) return;
    int d  = idx & 63;
    int h  = (idx >> 6) % heads;
    int bs = idx / (64 * heads);
    int s  = bs % SEQ;
    float c  = cosb[s * HEADD + d];
    float sn = sinb[s * HEADD + d];
    float* p = T + ((size_t)bs * heads + h) * HEADD;
    float q0 = p[d], q1 = p[d + 64];
    p[d]      = q0 * c - q1 * sn;
    p[d + 64] = q1 * c + q0 * sn;
}

// ===========================================================================
// Tensor-core flash attention (bf16x3), causal, GQA rep=4.
// BQ=128, BK=64, 8 warps (each warp: 16 q-rows). 1 CTA/SM, 128KB smem.
// smem planes (bf16, 256B rows, chunk-XOR swizzle c^(row&7)):
//   Qhi @0 (32KB) | Qlo @32768 | Khi @65536 (16KB) | Klo @81920
//   Vhi @98304 (16KB) | Vlo @114688
// S = QK^T via mma m16n8k16 (QhKh+QhKl+QlKh); softmax in accumulator layout
// (quad shuffles); P stays in registers (C-frag == A-frag identity);
// O += PV via mma with ldmatrix.trans B-frags from natural-layout V
// (PhVh+PhVl+PlVh).
// ===========================================================================
#define ATTN_SMEM 131072

__global__ void __launch_bounds__(256) attn_mma_kernel()
{
    extern __shared__ char sb[];
    const uint32_t sb32 = smem_to_u32(sb);

    const int tid  = threadIdx.x;
    const int lane = tid & 31;
    const int wid  = tid >> 5;
    const int wm   = wid * 16;          // warp q-row base within tile

    const int q0 = (gridDim.x - 1 - blockIdx.x) * 128;   // heavy blocks first
    const int bh = blockIdx.y;
    const int b  = bh / NHEADS;
    const int h  = bh % NHEADS;
    const int kh = h / (NHEADS / KVHEADS);

    const float* Qbase = g_Q + ((size_t)b * SEQ * NHEADS  + h)  * HEADD;
    const float* Kbase = g_K + ((size_t)b * SEQ * KVHEADS + kh) * HEADD;
    const float* Vbase = g_V + ((size_t)b * SEQ * KVHEADS + kh) * HEADD;
    const float SCALE = 0.08838834764831845f;   // 1/sqrt(128)

    // ---- load Q tile (128 rows x 16 chunks), pre-scaled, hi/lo split ----
    #pragma unroll
    for (int i = 0; i < 8; i++) {
        int job = tid + i * 256;          // 0..2047
        int row = job >> 4, ch = job & 15;
        const float* p = Qbase + (size_t)(q0 + row) * QSTRIDE + ch * 8;
        float4 f0 = *(const float4*)p;
        float4 f1 = *(const float4*)(p + 4);
        uint32_t h0, l0, h1, l1, h2, l2, h3, l3;
        split3(f0.x * SCALE, f0.y * SCALE, h0, l0);
        split3(f0.z * SCALE, f0.w * SCALE, h1, l1);
        split3(f1.x * SCALE, f1.y * SCALE, h2, l2);
        split3(f1.z * SCALE, f1.w * SCALE, h3, l3);
        uint32_t off = (uint32_t)row * 256 + ((ch ^ (row & 7)) << 4);
        *(uint4*)(sb + off)         = make_uint4(h0, h1, h2, h3);
        *(uint4*)(sb + 32768 + off) = make_uint4(l0, l1, l2, l3);
    }

    float oacc[16][4];
    #pragma unroll
    for (int t = 0; t < 16; t++)
        #pragma unroll
        for (int q = 0; q < 4; q++) oacc[t][q] = 0.0f;
    float m0r = -INFINITY, m1r = -INFINITY;
    float l0r = 0.0f, l1r = 0.0f;

    const int ktiles = q0 / 64 + 2;
    for (int kti = 0; kti < ktiles; kti++) {
        const int kv0 = kti * 64;
        __syncthreads();   // prior iteration's K/V reads done

        // ---- load K and V tiles (64 rows x 16 chunks each), hi/lo split ----
        #pragma unroll
        for (int i = 0; i < 4; i++) {
            int job = tid + i * 256;      // 0..1023
            int row = job >> 4, ch = job & 15;
            uint32_t off = (uint32_t)row * 256 + ((ch ^ (row & 7)) << 4);
            {
                const float* p = Kbase + (size_t)(kv0 + row) * KSTRIDE + ch * 8;
                float4 f0 = *(const float4*)p;
                float4 f1 = *(const float4*)(p + 4);
                uint32_t h0, l0, h1, l1, h2, l2, h3, l3;
                split3(f0.x, f0.y, h0, l0);
                split3(f0.z, f0.w, h1, l1);
                split3(f1.x, f1.y, h2, l2);
                split3(f1.z, f1.w, h3, l3);
                *(uint4*)(sb + 65536 + off) = make_uint4(h0, h1, h2, h3);
                *(uint4*)(sb + 81920 + off) = make_uint4(l0, l1, l2, l3);
            }
            {
                const float* p = Vbase + (size_t)(kv0 + row) * KSTRIDE + ch * 8;
                float4 f0 = *(const float4*)p;
                float4 f1 = *(const float4*)(p + 4);
                uint32_t h0, l0, h1, l1, h2, l2, h3, l3;
                split3(f0.x, f0.y, h0, l0);
                split3(f0.z, f0.w, h1, l1);
                split3(f1.x, f1.y, h2, l2);
                split3(f1.z, f1.w, h3, l3);
                *(uint4*)(sb + 98304  + off) = make_uint4(h0, h1, h2, h3);
                *(uint4*)(sb + 114688 + off) = make_uint4(l0, l1, l2, l3);
            }
        }
        __syncthreads();

        // fully-masked warp for this k-tile: skip compute
        if (kv0 > q0 + wm + 15) continue;

        // ---- S = Q K^T (warp: 16 q-rows x 64 kv), bf16x3 ----
        float sc[8][4];
        #pragma unroll
        for (int t = 0; t < 8; t++)
            #pragma unroll
            for (int q = 0; q < 4; q++) sc[t][q] = 0.0f;

        #pragma unroll
        for (int ks = 0; ks < 8; ks++) {
            int arow = wm + (lane & 15);
            int ach  = 2 * ks + (lane >> 4);
            uint32_t aaddr = sb32 + (uint32_t)arow * 256 +
                             ((ach ^ (arow & 7)) << 4);
            uint32_t ah[4], al_[4];
            ldsm_x4(ah, aaddr);
            ldsm_x4(al_, aaddr + 32768);
            #pragma unroll
            for (int g = 0; g < 4; g++) {
                int nrow = g * 16 + ((lane >> 4) & 1) * 8 + (lane & 7);
                int nch  = 2 * ks + ((lane >> 3) & 1);
                uint32_t baddr = sb32 + 65536 + (uint32_t)nrow * 256 +
                                 ((nch ^ (nrow & 7)) << 4);
                uint32_t bh_[4], bl_[4];
                ldsm_x4(bh_, baddr);
                ldsm_x4(bl_, baddr + 16384);
                #pragma unroll
                for (int nt = 0; nt < 2; nt++) {
                    float* d = sc[g * 2 + nt];
                    mma16816(d, ah,  bh_[nt * 2], bh_[nt * 2 + 1]);
                    mma16816(d, ah,  bl_[nt * 2], bl_[nt * 2 + 1]);
                    mma16816(d, al_, bh_[nt * 2], bh_[nt * 2 + 1]);
                }
            }
        }

        // ---- causal mask (only near the diagonal) ----
        if (kv0 + 63 > q0 + wm) {
            int r0g = q0 + wm + (lane >> 2);
            int r1g = r0g + 8;
            #pragma unroll
            for (int t = 0; t < 8; t++) {
                int kva = kv0 + t * 8 + (lane & 3) * 2;
                int kvb = kva + 1;
                if (kva > r0g) sc[t][0] = -1.0e30f;
                if (kvb > r0g) sc[t][1] = -1.0e30f;
                if (kva > r1g) sc[t][2] = -1.0e30f;
                if (kvb > r1g) sc[t][3] = -1.0e30f;
            }
        }

        // ---- online softmax in accumulator layout (quad reductions) ----
        float mx0 = m0r, mx1 = m1r;
        #pragma unroll
        for (int t = 0; t < 8; t++) {
            mx0 = fmaxf(mx0, fmaxf(sc[t][0], sc[t][1]));
            mx1 = fmaxf(mx1, fmaxf(sc[t][2], sc[t][3]));
        }
        mx0 = fmaxf(mx0, __shfl_xor_sync(0xffffffffu, mx0, 1));
        mx0 = fmaxf(mx0, __shfl_xor_sync(0xffffffffu, mx0, 2));
        mx1 = fmaxf(mx1, __shfl_xor_sync(0xffffffffu, mx1, 1));
        mx1 = fmaxf(mx1, __shfl_xor_sync(0xffffffffu, mx1, 2));

        float corr0 = __expf(m0r - mx0);
        float corr1 = __expf(m1r - mx1);
        m0r = mx0; m1r = mx1;

        float sum0 = 0.0f, sum1 = 0.0f;
        #pragma unroll
        for (int t = 0; t < 8; t++) {
            sc[t][0] = __expf(sc[t][0] - mx0); sum0 += sc[t][0];
            sc[t][1] = __expf(sc[t][1] - mx0); sum0 += sc[t][1];
            sc[t][2] = __expf(sc[t][2] - mx1); sum1 += sc[t][2];
            sc[t][3] = __expf(sc[t][3] - mx1); sum1 += sc[t][3];
        }
        sum0 += __shfl_xor_sync(0xffffffffu, sum0, 1);
        sum0 += __shfl_xor_sync(0xffffffffu, sum0, 2);
        sum1 += __shfl_xor_sync(0xffffffffu, sum1, 1);
        sum1 += __shfl_xor_sync(0xffffffffu, sum1, 2);
        l0r = l0r * corr0 + sum0;
        l1r = l1r * corr1 + sum1;

        #pragma unroll
        for (int t = 0; t < 16; t++) {
            oacc[t][0] *= corr0; oacc[t][1] *= corr0;
            oacc[t][2] *= corr1; oacc[t][3] *= corr1;
        }

        // ---- O += P V (P in registers: C-frag == A-frag), bf16x3 ----
        #pragma unroll
        for (int kt = 0; kt < 4; kt++) {
            uint32_t pah[4], pal[4];
            split3(sc[2 * kt][0],     sc[2 * kt][1],     pah[0], pal[0]);
            split3(sc[2 * kt][2],     sc[2 * kt][3],     pah[1], pal[1]);
            split3(sc[2 * kt + 1][0], sc[2 * kt + 1][1], pah[2], pal[2]);
            split3(sc[2 * kt + 1][2], sc[2 * kt + 1][3], pah[3], pal[3]);
            #pragma unroll
            for (int dg = 0; dg < 8; dg++) {
                int vrow = kt * 16 + ((lane >> 3) & 1) * 8 + (lane & 7);
                int vch  = dg * 2 + (lane >> 4);
                uint32_t vaddr = sb32 + 98304 + (uint32_t)vrow * 256 +
                                 ((vch ^ (vrow & 7)) << 4);
                uint32_t vh[4], vl[4];
                ldsm_x4_trans(vh, vaddr);
                ldsm_x4_trans(vl, vaddr + 16384);
                #pragma unroll
                for (int nt = 0; nt < 2; nt++) {
                    float* d = oacc[dg * 2 + nt];
                    mma16816(d, pah, vh[nt * 2], vh[nt * 2 + 1]);
                    mma16816(d, pah, vl[nt * 2], vl[nt * 2 + 1]);
                    mma16816(d, pal, vh[nt * 2], vh[nt * 2 + 1]);
                }
            }
        }
    }

    // ---- epilogue: normalize and write to g_O ----
    {
        float inv0 = 1.0f / l0r, inv1 = 1.0f / l1r;
        int r0g = q0 + wm + (lane >> 2);
        int r1g = r0g + 8;
        float* O0 = g_O + ((size_t)(b * SEQ + r0g) * NHEADS + h) * HEADD;
        float* O1 = g_O + ((size_t)(b * SEQ + r1g) * NHEADS + h) * HEADD;
        #pragma unroll
        for (int t = 0; t < 16; t++) {
            int d = t * 8 + (lane & 3) * 2;
            *(float2*)(O0 + d) = make_float2(oacc[t][0] * inv0, oacc[t][1] * inv0);
            *(float2*)(O1 + d) = make_float2(oacc[t][2] * inv1, oacc[t][3] * inv1);
        }
    }
}

// ---------------------------------------------------------------------------
extern "C" void kernel_launch(void* const* d_in, const int* in_sizes, int n_in,
                              void* d_out, int out_size)
{
    const float* x    = (const float*)d_in[0];
    const float* wq   = (const float*)d_in[1];
    const float* bq   = (const float*)d_in[2];
    const float* wk   = (const float*)d_in[3];
    const float* bk   = (const float*)d_in[4];
    const float* wv   = (const float*)d_in[5];
    const float* bv   = (const float*)d_in[6];
    const float* wo   = (const float*)d_in[7];
    const float* bo   = (const float*)d_in[8];
    const float* cosb = (const float*)d_in[9];
    const float* sinb = (const float*)d_in[10];
    float* out = (float*)d_out;

    float *Qp, *Kp, *Vp, *Op;
    cudaGetSymbolAddress((void**)&Qp, g_Q);
    cudaGetSymbolAddress((void**)&Kp, g_K);
    cudaGetSymbolAddress((void**)&Vp, g_V);
    cudaGetSymbolAddress((void**)&Op, g_O);

    cudaFuncSetAttribute(gemm_mma_bf16x3,
                         cudaFuncAttributeMaxDynamicSharedMemorySize, GEMM_SMEM);
    cudaFuncSetAttribute(attn_mma_kernel,
                         cudaFuncAttributeMaxDynamicSharedMemorySize, ATTN_SMEM);

    // 1-3. QKV projections (+bias) on tensor cores (bf16x3)
    gemm_mma_bf16x3<<<dim3(HDIM / 128,  MROWS / 128), 256, GEMM_SMEM>>>(x, wq, bq, Qp, HDIM, HDIM);
    gemm_mma_bf16x3<<<dim3(KVDIM / 128, MROWS / 128), 256, GEMM_SMEM>>>(x, wk, bk, Kp, HDIM, KVDIM);
    gemm_mma_bf16x3<<<dim3(KVDIM / 128, MROWS / 128), 256, GEMM_SMEM>>>(x, wv, bv, Vp, HDIM, KVDIM);

    // 4-5. RoPE on Q and K
    {
        int totq = NB * SEQ * NHEADS * 64;
        rope_kernel<<<(totq + 255) / 256, 256>>>(Qp, cosb, sinb, NHEADS, totq);
        int totk = NB * SEQ * KVHEADS * 64;
        rope_kernel<<<(totk + 255) / 256, 256>>>(Kp, cosb, sinb, KVHEADS, totk);
    }

    // 6. Causal GQA flash attention on tensor cores (bf16x3)
    attn_mma_kernel<<<dim3(SEQ / 128, NB * NHEADS), 256, ATTN_SMEM>>>();

    // 7. Output projection (+bias) straight into d_out
    gemm_mma_bf16x3<<<dim3(HDIM / 128, MROWS / 128), 256, GEMM_SMEM>>>(Op, wo, bo, out, HDIM, HDIM);
}

// round 12
// speedup vs baseline: 3.0071x; 1.0842x over previous
#include <cuda_runtime.h>
#include <cuda_bf16.h>
#include <math.h>
#include <stdint.h>

// Problem constants
#define NB      2
#define SEQ     2048
#define HDIM    2048
#define NHEADS  16
#define KVHEADS 4
#define HEADD   128
#define KVDIM   (KVHEADS * HEADD)   // 512
#define MROWS   (NB * SEQ)          // 4096
#define QSTRIDE (NHEADS * HEADD)    // 2048
#define KSTRIDE (KVHEADS * HEADD)   // 512

// fp32 scratch (GEMM outputs pre-RoPE)
__device__ float g_Q[(size_t)MROWS * HDIM];
__device__ float g_K[(size_t)MROWS * KVDIM];

// bf16 hi/lo planes (pre-split operands)
__device__ __nv_bfloat16 g_xh[(size_t)MROWS * HDIM],  g_xl[(size_t)MROWS * HDIM];
__device__ __nv_bfloat16 g_wqh[(size_t)HDIM * HDIM],  g_wql[(size_t)HDIM * HDIM];
__device__ __nv_bfloat16 g_wkh[(size_t)KVDIM * HDIM], g_wkl[(size_t)KVDIM * HDIM];
__device__ __nv_bfloat16 g_wvh[(size_t)KVDIM * HDIM], g_wvl[(size_t)KVDIM * HDIM];
__device__ __nv_bfloat16 g_woh[(size_t)HDIM * HDIM],  g_wol[(size_t)HDIM * HDIM];
__device__ __nv_bfloat16 g_Qh[(size_t)MROWS * HDIM],  g_Ql[(size_t)MROWS * HDIM];
__device__ __nv_bfloat16 g_Kh[(size_t)MROWS * KVDIM], g_Kl[(size_t)MROWS * KVDIM];
__device__ __nv_bfloat16 g_Vh[(size_t)MROWS * KVDIM], g_Vl[(size_t)MROWS * KVDIM];
__device__ __nv_bfloat16 g_Oh[(size_t)MROWS * HDIM],  g_Ol[(size_t)MROWS * HDIM];

// ===========================================================================
// Helpers
// ===========================================================================
__device__ __forceinline__ uint32_t smem_to_u32(const void* p) {
    uint32_t a;
    asm("{ .reg .u64 t; cvta.to.shared.u64 t, %1; cvt.u32.u64 %0, t; }"
        : "=r"(a) : "l"(p));
    return a;
}

// bf16x3 split: (a,b) -> packed hi bf16x2 + packed lo bf16x2
__device__ __forceinline__ void split3(float a, float b, uint32_t& hi, uint32_t& lo)
{
    __nv_bfloat162 h = __floats2bfloat162_rn(a, b);
    float2 hf = __bfloat1622float2(h);
    __nv_bfloat162 l = __floats2bfloat162_rn(a - hf.x, b - hf.y);
    hi = *reinterpret_cast<uint32_t*>(&h);
    lo = *reinterpret_cast<uint32_t*>(&l);
}

__device__ __forceinline__ void ldsm_x4(uint32_t* r, uint32_t addr)
{
    asm volatile("ldmatrix.sync.aligned.m8n8.x4.shared.b16 {%0,%1,%2,%3}, [%4];"
        : "=r"(r[0]), "=r"(r[1]), "=r"(r[2]), "=r"(r[3]) : "r"(addr));
}

__device__ __forceinline__ void ldsm_x4_trans(uint32_t* r, uint32_t addr)
{
    asm volatile("ldmatrix.sync.aligned.m8n8.x4.trans.shared.b16 {%0,%1,%2,%3}, [%4];"
        : "=r"(r[0]), "=r"(r[1]), "=r"(r[2]), "=r"(r[3]) : "r"(addr));
}

__device__ __forceinline__ void mma16816(float* d, const uint32_t* a,
                                         uint32_t b0, uint32_t b1)
{
    asm volatile(
        "mma.sync.aligned.m16n8k16.row.col.f32.bf16.bf16.f32 "
        "{%0,%1,%2,%3}, {%4,%5,%6,%7}, {%8,%9}, {%0,%1,%2,%3};"
        : "+f"(d[0]), "+f"(d[1]), "+f"(d[2]), "+f"(d[3])
        : "r"(a[0]), "r"(a[1]), "r"(a[2]), "r"(a[3]), "r"(b0), "r"(b1));
}

#define CP_ASYNC16(dst, src) \
    asm volatile("cp.async.ca.shared.global [%0], [%1], 16;" \
        :: "r"(dst), "l"(src) : "memory")
#define CP_COMMIT() asm volatile("cp.async.commit_group;" ::: "memory")
#define CP_WAIT0()  asm volatile("cp.async.wait_group 0;" ::: "memory")
#define CP_WAIT1()  asm volatile("cp.async.wait_group 1;" ::: "memory")

// ===========================================================================
// One-shot fp32 -> hi/lo bf16 plane conversion (8 elems / thread)
// ===========================================================================
__global__ void split_kernel(const float* __restrict__ s,
                             __nv_bfloat16* __restrict__ hi,
                             __nv_bfloat16* __restrict__ lo, int n)
{
    int i = (blockIdx.x * blockDim.x + threadIdx.x) * 8;
    if (i >= n) return;
    float4 f0 = *(const float4*)(s + i);
    float4 f1 = *(const float4*)(s + i + 4);
    uint32_t h0, l0, h1, l1, h2, l2, h3, l3;
    split3(f0.x, f0.y, h0, l0);
    split3(f0.z, f0.w, h1, l1);
    split3(f1.x, f1.y, h2, l2);
    split3(f1.z, f1.w, h3, l3);
    *(uint4*)(hi + i) = make_uint4(h0, h1, h2, h3);
    *(uint4*)(lo + i) = make_uint4(l0, l1, l2, l3);
}

// ===========================================================================
// bf16x3 tensor-core GEMM on PRE-SPLIT operands.
// C[M,N] = (Ah+Al)[M,K] @ (Bh+Bl)[N,K]^T + bias[N]
// Output: fp32 C, or hi/lo bf16 planes (Ch/Cl) when C == nullptr.
// CTA 128x128, K-chunk 32, 8 warps, double-buffered smem, cp.async loads.
// Stage (32KB): Ahi[128][32] | Alo | Bhi | Blo  (bf16, chunk-XOR swizzle)
// ===========================================================================
#define GEMM_SMEM (2 * 32768)

__device__ __forceinline__ void load_chunk_async(
    const __nv_bfloat16* __restrict__ Ah, const __nv_bfloat16* __restrict__ Al,
    const __nv_bfloat16* __restrict__ Bh, const __nv_bfloat16* __restrict__ Bl,
    int K, int m0, int n0, int kc, uint32_t stage32, int tid)
{
    #pragma unroll
    for (int j = 0; j < 2; j++) {
        int job = tid + j * 256;            // 0..511
        int row = job >> 2, c16 = job & 3;  // 16B chunk = 8 bf16 k-values
        uint32_t off = (uint32_t)row * 64 + ((c16 ^ ((row >> 1) & 3)) << 4);
        size_t ga = (size_t)(m0 + row) * K + kc + c16 * 8;
        size_t gb = (size_t)(n0 + row) * K + kc + c16 * 8;
        CP_ASYNC16(stage32 + off,         Ah + ga);
        CP_ASYNC16(stage32 + 8192 + off,  Al + ga);
        CP_ASYNC16(stage32 + 16384 + off, Bh + gb);
        CP_ASYNC16(stage32 + 24576 + off, Bl + gb);
    }
}

__global__ void __launch_bounds__(256, 2) gemm_mma_presplit(
    const __nv_bfloat16* __restrict__ Ah, const __nv_bfloat16* __restrict__ Al,
    const __nv_bfloat16* __restrict__ Bh, const __nv_bfloat16* __restrict__ Bl,
    const float* __restrict__ bias,
    float* __restrict__ C,
    __nv_bfloat16* __restrict__ Ch, __nv_bfloat16* __restrict__ Cl,
    int K, int N)
{
    extern __shared__ char smem[];
    const uint32_t sb32 = smem_to_u32(smem);

    const int tid  = threadIdx.x;
    const int lane = tid & 31;
    const int wid  = tid >> 5;
    const int wm   = (wid >> 1) * 32;
    const int wn   = (wid & 1) * 64;
    const int m0   = blockIdx.y * 128;
    const int n0   = blockIdx.x * 128;

    float acc[2][8][4];
    #pragma unroll
    for (int i = 0; i < 2; i++)
        #pragma unroll
        for (int j = 0; j < 8; j++)
            #pragma unroll
            for (int q = 0; q < 4; q++) acc[i][j][q] = 0.0f;

    const int NCH = K >> 5;

    load_chunk_async(Ah, Al, Bh, Bl, K, m0, n0, 0, sb32, tid);
    CP_COMMIT();

    for (int c = 0; c < NCH; c++) {
        if (c + 1 < NCH) {
            load_chunk_async(Ah, Al, Bh, Bl, K, m0, n0, (c + 1) << 5,
                             sb32 + (((c + 1) & 1) << 15), tid);
            CP_COMMIT();
            CP_WAIT1();
        } else {
            CP_WAIT0();
        }
        __syncthreads();     // chunk c's data visible to all warps

        const uint32_t stb = sb32 + ((c & 1) << 15);

        #pragma unroll
        for (int ks = 0; ks < 2; ks++) {
            uint32_t ah[2][4], al[2][4];
            #pragma unroll
            for (int mt = 0; mt < 2; mt++) {
                int row = wm + mt * 16 + (lane & 15);
                int c16 = ks * 2 + (lane >> 4);
                uint32_t ad = stb + (uint32_t)row * 64 +
                              ((c16 ^ ((row >> 1) & 3)) << 4);
                ldsm_x4(ah[mt], ad);
                ldsm_x4(al[mt], ad + 8192);
            }
            #pragma unroll
            for (int g = 0; g < 4; g++) {
                int n   = wn + g * 16 + ((lane >> 4) & 1) * 8 + (lane & 7);
                int c16 = ks * 2 + ((lane >> 3) & 1);
                uint32_t bd = stb + 16384 + (uint32_t)n * 64 +
                              ((c16 ^ ((n >> 1) & 3)) << 4);
                uint32_t bh[4], bl[4];
                ldsm_x4(bh, bd);
                ldsm_x4(bl, bd + 8192);
                #pragma unroll
                for (int mt = 0; mt < 2; mt++) {
                    #pragma unroll
                    for (int nt = 0; nt < 2; nt++) {
                        float* d = acc[mt][g * 2 + nt];
                        mma16816(d, ah[mt], bh[nt * 2], bh[nt * 2 + 1]);
                        mma16816(d, ah[mt], bl[nt * 2], bl[nt * 2 + 1]);
                        mma16816(d, al[mt], bh[nt * 2], bh[nt * 2 + 1]);
                    }
                }
            }
        }
        __syncthreads();     // stage reads done before refill (iteration c+1)
    }

    // ---- epilogue: fused bias; fp32 or split-bf16 output ----
    #pragma unroll
    for (int mt = 0; mt < 2; mt++) {
        int row0 = m0 + wm + mt * 16 + (lane >> 2);
        int row1 = row0 + 8;
        #pragma unroll
        for (int n8 = 0; n8 < 8; n8++) {
            int col = n0 + wn + n8 * 8 + (lane & 3) * 2;
            float b0 = bias[col], b1 = bias[col + 1];
            float v00 = acc[mt][n8][0] + b0, v01 = acc[mt][n8][1] + b1;
            float v10 = acc[mt][n8][2] + b0, v11 = acc[mt][n8][3] + b1;
            if (C) {
                *(float2*)(C + (size_t)row0 * N + col) = make_float2(v00, v01);
                *(float2*)(C + (size_t)row1 * N + col) = make_float2(v10, v11);
            } else {
                uint32_t h, l;
                split3(v00, v01, h, l);
                *(uint32_t*)(Ch + (size_t)row0 * N + col) = h;
                *(uint32_t*)(Cl + (size_t)row0 * N + col) = l;
                split3(v10, v11, h, l);
                *(uint32_t*)(Ch + (size_t)row1 * N + col) = h;
                *(uint32_t*)(Cl + (size_t)row1 * N + col) = l;
            }
        }
    }
}

// ---------------------------------------------------------------------------
// RoPE + optional scale + hi/lo split: fp32 (B,S,heads,128) -> bf16 planes.
// ---------------------------------------------------------------------------
__global__ void rope_split_kernel(const float* __restrict__ T,
                                  __nv_bfloat16* __restrict__ Th,
                                  __nv_bfloat16* __restrict__ Tl,
                                  const float* __restrict__ cosb,
                                  const float* __restrict__ sinb,
                                  int heads, float scale, int total)
{
    int idx = blockIdx.x * blockDim.x + threadIdx.x;
    if (idx >= total) return;
    int d  = idx & 63;
    int h  = (idx >> 6) % heads;
    int bs = idx / (64 * heads);
    int s  = bs % SEQ;
    float c  = cosb[s * HEADD + d];
    float sn = sinb[s * HEADD + d];
    size_t base = ((size_t)bs * heads + h) * HEADD;
    float q0 = T[base + d], q1 = T[base + d + 64];
    float v0 = (q0 * c - q1 * sn) * scale;
    float v1 = (q1 * c + q0 * sn) * scale;
    __nv_bfloat16 h0 = __float2bfloat16(v0);
    __nv_bfloat16 h1 = __float2bfloat16(v1);
    Th[base + d]      = h0;
    Tl[base + d]      = __float2bfloat16(v0 - __bfloat162float(h0));
    Th[base + d + 64] = h1;
    Tl[base + d + 64] = __float2bfloat16(v1 - __bfloat162float(h1));
}

// ===========================================================================
// Tensor-core flash attention (bf16x3), causal, GQA rep=4 — pre-split inputs.
// BQ=128, BK=64, 8 warps. 1 CTA/SM, 128KB smem. Layout identical to R11:
//   Qhi @0 | Qlo @32768 | Khi @65536 | Klo @81920 | Vhi @98304 | Vlo @114688
// Q already carries the 1/sqrt(d) scale (applied in rope_split).
// Output written as hi/lo bf16 planes for the O-projection.
// ===========================================================================
#define ATTN_SMEM 131072

__global__ void __launch_bounds__(256) attn_mma_kernel()
{
    extern __shared__ char sb[];
    const uint32_t sb32 = smem_to_u32(sb);

    const int tid  = threadIdx.x;
    const int lane = tid & 31;
    const int wid  = tid >> 5;
    const int wm   = wid * 16;

    const int q0 = (gridDim.x - 1 - blockIdx.x) * 128;   // heavy blocks first
    const int bh = blockIdx.y;
    const int b  = bh / NHEADS;
    const int h  = bh % NHEADS;
    const int kh = h / (NHEADS / KVHEADS);

    const size_t qoff = ((size_t)b * SEQ * NHEADS  + h)  * HEADD;
    const size_t koff = ((size_t)b * SEQ * KVHEADS + kh) * HEADD;
    const __nv_bfloat16* Qh = g_Qh + qoff;
    const __nv_bfloat16* Ql = g_Ql + qoff;
    const __nv_bfloat16* Kh = g_Kh + koff;
    const __nv_bfloat16* Kl = g_Kl + koff;
    const __nv_bfloat16* Vh = g_Vh + koff;
    const __nv_bfloat16* Vl = g_Vl + koff;

    // ---- load Q tile (pre-scaled, pre-split) via cp.async ----
    #pragma unroll
    for (int i = 0; i < 8; i++) {
        int job = tid + i * 256;          // 0..2047
        int row = job >> 4, ch = job & 15;
        uint32_t off = (uint32_t)row * 256 + ((ch ^ (row & 7)) << 4);
        size_t ga = (size_t)(q0 + row) * QSTRIDE + ch * 8;
        CP_ASYNC16(sb32 + off,         Qh + ga);
        CP_ASYNC16(sb32 + 32768 + off, Ql + ga);
    }
    CP_COMMIT();

    float oacc[16][4];
    #pragma unroll
    for (int t = 0; t < 16; t++)
        #pragma unroll
        for (int q = 0; q < 4; q++) oacc[t][q] = 0.0f;
    float m0r = -INFINITY, m1r = -INFINITY;
    float l0r = 0.0f, l1r = 0.0f;

    const int ktiles = q0 / 64 + 2;
    for (int kti = 0; kti < ktiles; kti++) {
        const int kv0 = kti * 64;
        __syncthreads();   // prior iteration's K/V reads done

        // ---- load K and V tiles via cp.async ----
        #pragma unroll
        for (int i = 0; i < 4; i++) {
            int job = tid + i * 256;      // 0..1023
            int row = job >> 4, ch = job & 15;
            uint32_t off = (uint32_t)row * 256 + ((ch ^ (row & 7)) << 4);
            size_t ga = (size_t)(kv0 + row) * KSTRIDE + ch * 8;
            CP_ASYNC16(sb32 + 65536  + off, Kh + ga);
            CP_ASYNC16(sb32 + 81920  + off, Kl + ga);
            CP_ASYNC16(sb32 + 98304  + off, Vh + ga);
            CP_ASYNC16(sb32 + 114688 + off, Vl + ga);
        }
        CP_COMMIT();
        CP_WAIT0();
        __syncthreads();

        if (kv0 > q0 + wm + 15) continue;   // fully-masked warp

        // ---- S = Q K^T, bf16x3 ----
        float sc[8][4];
        #pragma unroll
        for (int t = 0; t < 8; t++)
            #pragma unroll
            for (int q = 0; q < 4; q++) sc[t][q] = 0.0f;

        #pragma unroll
        for (int ks = 0; ks < 8; ks++) {
            int arow = wm + (lane & 15);
            int ach  = 2 * ks + (lane >> 4);
            uint32_t aaddr = sb32 + (uint32_t)arow * 256 +
                             ((ach ^ (arow & 7)) << 4);
            uint32_t ah[4], al_[4];
            ldsm_x4(ah, aaddr);
            ldsm_x4(al_, aaddr + 32768);
            #pragma unroll
            for (int g = 0; g < 4; g++) {
                int nrow = g * 16 + ((lane >> 4) & 1) * 8 + (lane & 7);
                int nch  = 2 * ks + ((lane >> 3) & 1);
                uint32_t baddr = sb32 + 65536 + (uint32_t)nrow * 256 +
                                 ((nch ^ (nrow & 7)) << 4);
                uint32_t bh_[4], bl_[4];
                ldsm_x4(bh_, baddr);
                ldsm_x4(bl_, baddr + 16384);
                #pragma unroll
                for (int nt = 0; nt < 2; nt++) {
                    float* d = sc[g * 2 + nt];
                    mma16816(d, ah,  bh_[nt * 2], bh_[nt * 2 + 1]);
                    mma16816(d, ah,  bl_[nt * 2], bl_[nt * 2 + 1]);
                    mma16816(d, al_, bh_[nt * 2], bh_[nt * 2 + 1]);
                }
            }
        }

        // ---- causal mask (near-diagonal tiles only) ----
        if (kv0 + 63 > q0 + wm) {
            int r0g = q0 + wm + (lane >> 2);
            int r1g = r0g + 8;
            #pragma unroll
            for (int t = 0; t < 8; t++) {
                int kva = kv0 + t * 8 + (lane & 3) * 2;
                int kvb = kva + 1;
                if (kva > r0g) sc[t][0] = -1.0e30f;
                if (kvb > r0g) sc[t][1] = -1.0e30f;
                if (kva > r1g) sc[t][2] = -1.0e30f;
                if (kvb > r1g) sc[t][3] = -1.0e30f;
            }
        }

        // ---- online softmax (quad reductions in accumulator layout) ----
        float mx0 = m0r, mx1 = m1r;
        #pragma unroll
        for (int t = 0; t < 8; t++) {
            mx0 = fmaxf(mx0, fmaxf(sc[t][0], sc[t][1]));
            mx1 = fmaxf(mx1, fmaxf(sc[t][2], sc[t][3]));
        }
        mx0 = fmaxf(mx0, __shfl_xor_sync(0xffffffffu, mx0, 1));
        mx0 = fmaxf(mx0, __shfl_xor_sync(0xffffffffu, mx0, 2));
        mx1 = fmaxf(mx1, __shfl_xor_sync(0xffffffffu, mx1, 1));
        mx1 = fmaxf(mx1, __shfl_xor_sync(0xffffffffu, mx1, 2));

        float corr0 = __expf(m0r - mx0);
        float corr1 = __expf(m1r - mx1);
        m0r = mx0; m1r = mx1;

        float sum0 = 0.0f, sum1 = 0.0f;
        #pragma unroll
        for (int t = 0; t < 8; t++) {
            sc[t][0] = __expf(sc[t][0] - mx0); sum0 += sc[t][0];
            sc[t][1] = __expf(sc[t][1] - mx0); sum0 += sc[t][1];
            sc[t][2] = __expf(sc[t][2] - mx1); sum1 += sc[t][2];
            sc[t][3] = __expf(sc[t][3] - mx1); sum1 += sc[t][3];
        }
        sum0 += __shfl_xor_sync(0xffffffffu, sum0, 1);
        sum0 += __shfl_xor_sync(0xffffffffu, sum0, 2);
        sum1 += __shfl_xor_sync(0xffffffffu, sum1, 1);
        sum1 += __shfl_xor_sync(0xffffffffu, sum1, 2);
        l0r = l0r * corr0 + sum0;
        l1r = l1r * corr1 + sum1;

        #pragma unroll
        for (int t = 0; t < 16; t++) {
            oacc[t][0] *= corr0; oacc[t][1] *= corr0;
            oacc[t][2] *= corr1; oacc[t][3] *= corr1;
        }

        // ---- O += P V (P in registers), bf16x3 ----
        #pragma unroll
        for (int kt = 0; kt < 4; kt++) {
            uint32_t pah[4], pal[4];
            split3(sc[2 * kt][0],     sc[2 * kt][1],     pah[0], pal[0]);
            split3(sc[2 * kt][2],     sc[2 * kt][3],     pah[1], pal[1]);
            split3(sc[2 * kt + 1][0], sc[2 * kt + 1][1], pah[2], pal[2]);
            split3(sc[2 * kt + 1][2], sc[2 * kt + 1][3], pah[3], pal[3]);
            #pragma unroll
            for (int dg = 0; dg < 8; dg++) {
                int vrow = kt * 16 + ((lane >> 3) & 1) * 8 + (lane & 7);
                int vch  = dg * 2 + (lane >> 4);
                uint32_t vaddr = sb32 + 98304 + (uint32_t)vrow * 256 +
                                 ((vch ^ (vrow & 7)) << 4);
                uint32_t vh[4], vl[4];
                ldsm_x4_trans(vh, vaddr);
                ldsm_x4_trans(vl, vaddr + 16384);
                #pragma unroll
                for (int nt = 0; nt < 2; nt++) {
                    float* d = oacc[dg * 2 + nt];
                    mma16816(d, pah, vh[nt * 2], vh[nt * 2 + 1]);
                    mma16816(d, pah, vl[nt * 2], vl[nt * 2 + 1]);
                    mma16816(d, pal, vh[nt * 2], vh[nt * 2 + 1]);
                }
            }
        }
    }

    // ---- epilogue: normalize, split, write hi/lo planes ----
    {
        float inv0 = 1.0f / l0r, inv1 = 1.0f / l1r;
        int r0g = q0 + wm + (lane >> 2);
        int r1g = r0g + 8;
        size_t b0 = ((size_t)(b * SEQ + r0g) * NHEADS + h) * HEADD;
        size_t b1 = ((size_t)(b * SEQ + r1g) * NHEADS + h) * HEADD;
        #pragma unroll
        for (int t = 0; t < 16; t++) {
            int d = t * 8 + (lane & 3) * 2;
            uint32_t hh, ll;
            split3(oacc[t][0] * inv0, oacc[t][1] * inv0, hh, ll);
            *(uint32_t*)(g_Oh + b0 + d) = hh;
            *(uint32_t*)(g_Ol + b0 + d) = ll;
            split3(oacc[t][2] * inv1, oacc[t][3] * inv1, hh, ll);
            *(uint32_t*)(g_Oh + b1 + d) = hh;
            *(uint32_t*)(g_Ol + b1 + d) = ll;
        }
    }
}

// ---------------------------------------------------------------------------
extern "C" void kernel_launch(void* const* d_in, const int* in_sizes, int n_in,
                              void* d_out, int out_size)
{
    const float* x    = (const float*)d_in[0];
    const float* wq   = (const float*)d_in[1];
    const float* bq   = (const float*)d_in[2];
    const float* wk   = (const float*)d_in[3];
    const float* bk   = (const float*)d_in[4];
    const float* wv   = (const float*)d_in[5];
    const float* bv   = (const float*)d_in[6];
    const float* wo   = (const float*)d_in[7];
    const float* bo   = (const float*)d_in[8];
    const float* cosb = (const float*)d_in[9];
    const float* sinb = (const float*)d_in[10];
    float* out = (float*)d_out;

    float *Qp, *Kp;
    cudaGetSymbolAddress((void**)&Qp, g_Q);
    cudaGetSymbolAddress((void**)&Kp, g_K);
    __nv_bfloat16 *xh, *xl, *wqh, *wql, *wkh, *wkl, *wvh, *wvl, *woh, *wol;
    __nv_bfloat16 *qh, *ql, *kH, *kL, *vh, *vl, *oh, *ol;
    cudaGetSymbolAddress((void**)&xh, g_xh);   cudaGetSymbolAddress((void**)&xl, g_xl);
    cudaGetSymbolAddress((void**)&wqh, g_wqh); cudaGetSymbolAddress((void**)&wql, g_wql);
    cudaGetSymbolAddress((void**)&wkh, g_wkh); cudaGetSymbolAddress((void**)&wkl, g_wkl);
    cudaGetSymbolAddress((void**)&wvh, g_wvh); cudaGetSymbolAddress((void**)&wvl, g_wvl);
    cudaGetSymbolAddress((void**)&woh, g_woh); cudaGetSymbolAddress((void**)&wol, g_wol);
    cudaGetSymbolAddress((void**)&qh, g_Qh);   cudaGetSymbolAddress((void**)&ql, g_Ql);
    cudaGetSymbolAddress((void**)&kH, g_Kh);   cudaGetSymbolAddress((void**)&kL, g_Kl);
    cudaGetSymbolAddress((void**)&vh, g_Vh);   cudaGetSymbolAddress((void**)&vl, g_Vl);
    cudaGetSymbolAddress((void**)&oh, g_Oh);   cudaGetSymbolAddress((void**)&ol, g_Ol);

    cudaFuncSetAttribute(gemm_mma_presplit,
                         cudaFuncAttributeMaxDynamicSharedMemorySize, GEMM_SMEM);
    cudaFuncSetAttribute(attn_mma_kernel,
                         cudaFuncAttributeMaxDynamicSharedMemorySize, ATTN_SMEM);

    // 0. One-shot conversions to hi/lo bf16 planes
    {
        int n;
        n = MROWS * HDIM;  split_kernel<<<n / 8 / 256, 256>>>(x,  xh,  xl,  n);
        n = HDIM * HDIM;   split_kernel<<<n / 8 / 256, 256>>>(wq, wqh, wql, n);
        n = KVDIM * HDIM;  split_kernel<<<n / 8 / 256, 256>>>(wk, wkh, wkl, n);
        n = KVDIM * HDIM;  split_kernel<<<n / 8 / 256, 256>>>(wv, wvh, wvl, n);
        n = HDIM * HDIM;   split_kernel<<<n / 8 / 256, 256>>>(wo, woh, wol, n);
    }

    // 1-3. QKV projections (+bias)
    gemm_mma_presplit<<<dim3(HDIM / 128,  MROWS / 128), 256, GEMM_SMEM>>>(
        xh, xl, wqh, wql, bq, Qp, nullptr, nullptr, HDIM, HDIM);
    gemm_mma_presplit<<<dim3(KVDIM / 128, MROWS / 128), 256, GEMM_SMEM>>>(
        xh, xl, wkh, wkl, bk, Kp, nullptr, nullptr, HDIM, KVDIM);
    gemm_mma_presplit<<<dim3(KVDIM / 128, MROWS / 128), 256, GEMM_SMEM>>>(
        xh, xl, wvh, wvl, bv, nullptr, vh, vl, HDIM, KVDIM);

    // 4-5. RoPE (+1/sqrt(d) scale on Q) + split
    {
        const float SCALE = 0.08838834764831845f;
        int totq = NB * SEQ * NHEADS * 64;
        rope_split_kernel<<<(totq + 255) / 256, 256>>>(Qp, qh, ql, cosb, sinb,
                                                       NHEADS, SCALE, totq);
        int totk = NB * SEQ * KVHEADS * 64;
        rope_split_kernel<<<(totk + 255) / 256, 256>>>(Kp, kH, kL, cosb, sinb,
                                                       KVHEADS, 1.0f, totk);
    }

    // 6. Causal GQA flash attention (bf16x3 tensor cores)
    attn_mma_kernel<<<dim3(SEQ / 128, NB * NHEADS), 256, ATTN_SMEM>>>();

    // 7. Output projection (+bias) straight into d_out
    gemm_mma_presplit<<<dim3(HDIM / 128, MROWS / 128), 256, GEMM_SMEM>>>(
        oh, ol, woh, wol, bo, out, nullptr, nullptr, HDIM, HDIM);
}

// round 13
// speedup vs baseline: 3.7221x; 1.2378x over previous
#include <cuda_runtime.h>
#include <cuda_bf16.h>
#include <cuda_fp16.h>
#include <math.h>
#include <stdint.h>

// Problem constants
#define NB      2
#define SEQ     2048
#define HDIM    2048
#define NHEADS  16
#define KVHEADS 4
#define HEADD   128
#define KVDIM   (KVHEADS * HEADD)   // 512
#define MROWS   (NB * SEQ)          // 4096
#define QSTRIDE (NHEADS * HEADD)    // 2048
#define KSTRIDE (KVHEADS * HEADD)   // 512

// fp32 scratch (Q/K GEMM outputs pre-RoPE)
__device__ float g_Q[(size_t)MROWS * HDIM];
__device__ float g_K[(size_t)MROWS * KVDIM];

// fp16 planes
__device__ __half g_xh[(size_t)MROWS * HDIM],  g_xl[(size_t)MROWS * HDIM];   // x hi/lo
__device__ __half g_wq[(size_t)HDIM * HDIM];                                  // weights (single)
__device__ __half g_wk[(size_t)KVDIM * HDIM];
__device__ __half g_wv[(size_t)KVDIM * HDIM];
__device__ __half g_wo[(size_t)HDIM * HDIM];
__device__ __half g_Qh[(size_t)MROWS * HDIM],  g_Ql[(size_t)MROWS * HDIM];   // post-rope Q hi/lo
__device__ __half g_Kh[(size_t)MROWS * KVDIM], g_Kl[(size_t)MROWS * KVDIM];
__device__ __half g_Vh[(size_t)MROWS * KVDIM], g_Vl[(size_t)MROWS * KVDIM];
__device__ __half g_Oh[(size_t)MROWS * HDIM],  g_Ol[(size_t)MROWS * HDIM];   // attn out hi/lo

// ===========================================================================
// Helpers
// ===========================================================================
__device__ __forceinline__ uint32_t smem_to_u32(const void* p) {
    uint32_t a;
    asm("{ .reg .u64 t; cvta.to.shared.u64 t, %1; cvt.u32.u64 %0, t; }"
        : "=r"(a) : "l"(p));
    return a;
}

// fp16x2 split: (a,b) -> packed hi half2 + packed lo half2 (exact to ~2^-22)
__device__ __forceinline__ void split3h(float a, float b, uint32_t& hi, uint32_t& lo)
{
    __half2 h = __floats2half2_rn(a, b);
    float2 hf = __half22float2(h);
    __half2 l = __floats2half2_rn(a - hf.x, b - hf.y);
    hi = *reinterpret_cast<uint32_t*>(&h);
    lo = *reinterpret_cast<uint32_t*>(&l);
}
__device__ __forceinline__ uint32_t pack_h2(float a, float b)
{
    __half2 h = __floats2half2_rn(a, b);
    return *reinterpret_cast<uint32_t*>(&h);
}

__device__ __forceinline__ void ldsm_x4(uint32_t* r, uint32_t addr)
{
    asm volatile("ldmatrix.sync.aligned.m8n8.x4.shared.b16 {%0,%1,%2,%3}, [%4];"
        : "=r"(r[0]), "=r"(r[1]), "=r"(r[2]), "=r"(r[3]) : "r"(addr));
}
__device__ __forceinline__ void ldsm_x4_trans(uint32_t* r, uint32_t addr)
{
    asm volatile("ldmatrix.sync.aligned.m8n8.x4.trans.shared.b16 {%0,%1,%2,%3}, [%4];"
        : "=r"(r[0]), "=r"(r[1]), "=r"(r[2]), "=r"(r[3]) : "r"(addr));
}

// fp16 MMA, fp32 accum
__device__ __forceinline__ void mma16816h(float* d, const uint32_t* a,
                                          uint32_t b0, uint32_t b1)
{
    asm volatile(
        "mma.sync.aligned.m16n8k16.row.col.f32.f16.f16.f32 "
        "{%0,%1,%2,%3}, {%4,%5,%6,%7}, {%8,%9}, {%0,%1,%2,%3};"
        : "+f"(d[0]), "+f"(d[1]), "+f"(d[2]), "+f"(d[3])
        : "r"(a[0]), "r"(a[1]), "r"(a[2]), "r"(a[3]), "r"(b0), "r"(b1));
}

#define CP_ASYNC16(dst, src) \
    asm volatile("cp.async.ca.shared.global [%0], [%1], 16;" \
        :: "r"(dst), "l"(src) : "memory")
#define CP_COMMIT() asm volatile("cp.async.commit_group;" ::: "memory")
#define CP_WAIT0()  asm volatile("cp.async.wait_group 0;" ::: "memory")
#define CP_WAIT1()  asm volatile("cp.async.wait_group 1;" ::: "memory")

// ===========================================================================
// One-shot fp32 -> fp16 conversions
// ===========================================================================
__global__ void split_h2_kernel(const float* __restrict__ s,
                                __half* __restrict__ hi,
                                __half* __restrict__ lo, int n)
{
    int i = (blockIdx.x * blockDim.x + threadIdx.x) * 8;
    if (i >= n) return;
    float4 f0 = *(const float4*)(s + i);
    float4 f1 = *(const float4*)(s + i + 4);
    uint32_t h0, l0, h1, l1, h2, l2, h3, l3;
    split3h(f0.x, f0.y, h0, l0);
    split3h(f0.z, f0.w, h1, l1);
    split3h(f1.x, f1.y, h2, l2);
    split3h(f1.z, f1.w, h3, l3);
    *(uint4*)(hi + i) = make_uint4(h0, h1, h2, h3);
    *(uint4*)(lo + i) = make_uint4(l0, l1, l2, l3);
}
__global__ void split_h1_kernel(const float* __restrict__ s,
                                __half* __restrict__ h, int n)
{
    int i = (blockIdx.x * blockDim.x + threadIdx.x) * 8;
    if (i >= n) return;
    float4 f0 = *(const float4*)(s + i);
    float4 f1 = *(const float4*)(s + i + 4);
    *(uint4*)(h + i) = make_uint4(pack_h2(f0.x, f0.y), pack_h2(f0.z, f0.w),
                                  pack_h2(f1.x, f1.y), pack_h2(f1.z, f1.w));
}

// ===========================================================================
// fp16 asymmetric-x2 tensor-core GEMM:
// C[M,N] = (Ah+Al)[M,K] @ Bh[N,K]^T + bias[N]
// A split exactly (fp16 pair); B quantized to single fp16 plane.
// 2 MMAs per fragment pair (ah*bh + al*bh).
// CTA 128x128, K-chunk 32, 8 warps, double-buffered cp.async smem.
// Stage (24KB): Ahi[128][32] | Alo | Bh  (fp16, chunk-XOR swizzle)
// Output: fp32 C, or fp16 hi/lo planes when C == nullptr.
// ===========================================================================
#define GEMM_SMEM (2 * 24576)

__device__ __forceinline__ void load_chunk_async(
    const __half* __restrict__ Ah, const __half* __restrict__ Al,
    const __half* __restrict__ Bh,
    int K, int m0, int n0, int kc, uint32_t stage32, int tid)
{
    #pragma unroll
    for (int j = 0; j < 2; j++) {
        int job = tid + j * 256;            // 0..511
        int row = job >> 2, c16 = job & 3;  // 16B chunk = 8 fp16 k-values
        uint32_t off = (uint32_t)row * 64 + ((c16 ^ ((row >> 1) & 3)) << 4);
        size_t ga = (size_t)(m0 + row) * K + kc + c16 * 8;
        size_t gb = (size_t)(n0 + row) * K + kc + c16 * 8;
        CP_ASYNC16(stage32 + off,         Ah + ga);
        CP_ASYNC16(stage32 + 8192 + off,  Al + ga);
        CP_ASYNC16(stage32 + 16384 + off, Bh + gb);
    }
}

__global__ void __launch_bounds__(256, 2) gemm_mma_h2(
    const __half* __restrict__ Ah, const __half* __restrict__ Al,
    const __half* __restrict__ Bh,
    const float* __restrict__ bias,
    float* __restrict__ C,
    __half* __restrict__ Ch, __half* __restrict__ Cl,
    int K, int N)
{
    extern __shared__ char smem[];
    const uint32_t sb32 = smem_to_u32(smem);

    const int tid  = threadIdx.x;
    const int lane = tid & 31;
    const int wid  = tid >> 5;
    const int wm   = (wid >> 1) * 32;
    const int wn   = (wid & 1) * 64;
    const int m0   = blockIdx.y * 128;
    const int n0   = blockIdx.x * 128;

    float acc[2][8][4];
    #pragma unroll
    for (int i = 0; i < 2; i++)
        #pragma unroll
        for (int j = 0; j < 8; j++)
            #pragma unroll
            for (int q = 0; q < 4; q++) acc[i][j][q] = 0.0f;

    const int NCH = K >> 5;

    load_chunk_async(Ah, Al, Bh, K, m0, n0, 0, sb32, tid);
    CP_COMMIT();

    for (int c = 0; c < NCH; c++) {
        if (c + 1 < NCH) {
            load_chunk_async(Ah, Al, Bh, K, m0, n0, (c + 1) << 5,
                             sb32 + ((c + 1) & 1) * 24576u, tid);
            CP_COMMIT();
            CP_WAIT1();
        } else {
            CP_WAIT0();
        }
        __syncthreads();

        const uint32_t stb = sb32 + (c & 1) * 24576u;

        #pragma unroll
        for (int ks = 0; ks < 2; ks++) {
            uint32_t ah[2][4], al[2][4];
            #pragma unroll
            for (int mt = 0; mt < 2; mt++) {
                int row = wm + mt * 16 + (lane & 15);
                int c16 = ks * 2 + (lane >> 4);
                uint32_t ad = stb + (uint32_t)row * 64 +
                              ((c16 ^ ((row >> 1) & 3)) << 4);
                ldsm_x4(ah[mt], ad);
                ldsm_x4(al[mt], ad + 8192);
            }
            #pragma unroll
            for (int g = 0; g < 4; g++) {
                int n   = wn + g * 16 + ((lane >> 4) & 1) * 8 + (lane & 7);
                int c16 = ks * 2 + ((lane >> 3) & 1);
                uint32_t bd = stb + 16384 + (uint32_t)n * 64 +
                              ((c16 ^ ((n >> 1) & 3)) << 4);
                uint32_t bh[4];
                ldsm_x4(bh, bd);
                #pragma unroll
                for (int mt = 0; mt < 2; mt++) {
                    #pragma unroll
                    for (int nt = 0; nt < 2; nt++) {
                        float* d = acc[mt][g * 2 + nt];
                        mma16816h(d, ah[mt], bh[nt * 2], bh[nt * 2 + 1]);
                        mma16816h(d, al[mt], bh[nt * 2], bh[nt * 2 + 1]);
                    }
                }
            }
        }
        __syncthreads();
    }

    // ---- epilogue: fused bias; fp32 or fp16-split output ----
    #pragma unroll
    for (int mt = 0; mt < 2; mt++) {
        int row0 = m0 + wm + mt * 16 + (lane >> 2);
        int row1 = row0 + 8;
        #pragma unroll
        for (int n8 = 0; n8 < 8; n8++) {
            int col = n0 + wn + n8 * 8 + (lane & 3) * 2;
            float b0 = bias[col], b1 = bias[col + 1];
            float v00 = acc[mt][n8][0] + b0, v01 = acc[mt][n8][1] + b1;
            float v10 = acc[mt][n8][2] + b0, v11 = acc[mt][n8][3] + b1;
            if (C) {
                *(float2*)(C + (size_t)row0 * N + col) = make_float2(v00, v01);
                *(float2*)(C + (size_t)row1 * N + col) = make_float2(v10, v11);
            } else {
                uint32_t h, l;
                split3h(v00, v01, h, l);
                *(uint32_t*)(Ch + (size_t)row0 * N + col) = h;
                *(uint32_t*)(Cl + (size_t)row0 * N + col) = l;
                split3h(v10, v11, h, l);
                *(uint32_t*)(Ch + (size_t)row1 * N + col) = h;
                *(uint32_t*)(Cl + (size_t)row1 * N + col) = l;
            }
        }
    }
}

// ---------------------------------------------------------------------------
// RoPE + fp16 hi/lo split (no scale; attention scales scores in fp32).
// ---------------------------------------------------------------------------
__global__ void rope_split_kernel(const float* __restrict__ T,
                                  __half* __restrict__ Th,
                                  __half* __restrict__ Tl,
                                  const float* __restrict__ cosb,
                                  const float* __restrict__ sinb,
                                  int heads, int total)
{
    int idx = blockIdx.x * blockDim.x + threadIdx.x;
    if (idx >= total) return;
    int d  = idx & 63;
    int h  = (idx >> 6) % heads;
    int bs = idx / (64 * heads);
    int s  = bs % SEQ;
    float c  = cosb[s * HEADD + d];
    float sn = sinb[s * HEADD + d];
    size_t base = ((size_t)bs * heads + h) * HEADD;
    float q0 = T[base + d], q1 = T[base + d + 64];
    float v0 = q0 * c - q1 * sn;
    float v1 = q1 * c + q0 * sn;
    __half h0 = __float2half_rn(v0);
    __half h1 = __float2half_rn(v1);
    Th[base + d]      = h0;
    Tl[base + d]      = __float2half_rn(v0 - __half2float(h0));
    Th[base + d + 64] = h1;
    Tl[base + d + 64] = __float2half_rn(v1 - __half2float(h1));
}

// ===========================================================================
// Tensor-core flash attention (fp16), causal, GQA rep=4 — pre-split inputs.
// BQ=128, BK=64, 8 warps. 1 CTA/SM, 128KB smem. Layout (fp16, same offsets):
//   Qhi @0 | Qlo @32768 | Khi @65536 | Klo @81920 | Vhi @98304 | Vlo @114688
// QK: 3 MMAs (qh*kh + qh*kl + ql*kh, error ~2^-22); scores scaled by 1/sqrt(d)
// in fp32 post-MMA. P single fp16; PV: 2 MMAs (p*vh + p*vl).
// Output written as fp16 hi/lo planes for the O-projection.
// ===========================================================================
#define ATTN_SMEM 131072

__global__ void __launch_bounds__(256) attn_mma_kernel()
{
    extern __shared__ char sb[];
    const uint32_t sb32 = smem_to_u32(sb);

    const int tid  = threadIdx.x;
    const int lane = tid & 31;
    const int wid  = tid >> 5;
    const int wm   = wid * 16;

    const int q0 = (gridDim.x - 1 - blockIdx.x) * 128;   // heavy blocks first
    const int bh = blockIdx.y;
    const int b  = bh / NHEADS;
    const int h  = bh % NHEADS;
    const int kh = h / (NHEADS / KVHEADS);

    const size_t qoff = ((size_t)b * SEQ * NHEADS  + h)  * HEADD;
    const size_t koff = ((size_t)b * SEQ * KVHEADS + kh) * HEADD;
    const __half* Qh = g_Qh + qoff;
    const __half* Ql = g_Ql + qoff;
    const __half* Kh = g_Kh + koff;
    const __half* Kl = g_Kl + koff;
    const __half* Vh = g_Vh + koff;
    const __half* Vl = g_Vl + koff;
    const float SCALE = 0.08838834764831845f;   // 1/sqrt(128)

    // ---- load Q tile via cp.async ----
    #pragma unroll
    for (int i = 0; i < 8; i++) {
        int job = tid + i * 256;          // 0..2047
        int row = job >> 4, ch = job & 15;
        uint32_t off = (uint32_t)row * 256 + ((ch ^ (row & 7)) << 4);
        size_t ga = (size_t)(q0 + row) * QSTRIDE + ch * 8;
        CP_ASYNC16(sb32 + off,         Qh + ga);
        CP_ASYNC16(sb32 + 32768 + off, Ql + ga);
    }
    CP_COMMIT();

    float oacc[16][4];
    #pragma unroll
    for (int t = 0; t < 16; t++)
        #pragma unroll
        for (int q = 0; q < 4; q++) oacc[t][q] = 0.0f;
    float m0r = -INFINITY, m1r = -INFINITY;
    float l0r = 0.0f, l1r = 0.0f;

    const int ktiles = q0 / 64 + 2;
    for (int kti = 0; kti < ktiles; kti++) {
        const int kv0 = kti * 64;
        __syncthreads();   // prior iteration's K/V reads done

        // ---- load K and V tiles via cp.async ----
        #pragma unroll
        for (int i = 0; i < 4; i++) {
            int job = tid + i * 256;      // 0..1023
            int row = job >> 4, ch = job & 15;
            uint32_t off = (uint32_t)row * 256 + ((ch ^ (row & 7)) << 4);
            size_t ga = (size_t)(kv0 + row) * KSTRIDE + ch * 8;
            CP_ASYNC16(sb32 + 65536  + off, Kh + ga);
            CP_ASYNC16(sb32 + 81920  + off, Kl + ga);
            CP_ASYNC16(sb32 + 98304  + off, Vh + ga);
            CP_ASYNC16(sb32 + 114688 + off, Vl + ga);
        }
        CP_COMMIT();
        CP_WAIT0();
        __syncthreads();

        if (kv0 > q0 + wm + 15) continue;   // fully-masked warp

        // ---- S = Q K^T, fp16x2 (3 MMAs) ----
        float sc[8][4];
        #pragma unroll
        for (int t = 0; t < 8; t++)
            #pragma unroll
            for (int q = 0; q < 4; q++) sc[t][q] = 0.0f;

        #pragma unroll
        for (int ks = 0; ks < 8; ks++) {
            int arow = wm + (lane & 15);
            int ach  = 2 * ks + (lane >> 4);
            uint32_t aaddr = sb32 + (uint32_t)arow * 256 +
                             ((ach ^ (arow & 7)) << 4);
            uint32_t ah[4], al_[4];
            ldsm_x4(ah, aaddr);
            ldsm_x4(al_, aaddr + 32768);
            #pragma unroll
            for (int g = 0; g < 4; g++) {
                int nrow = g * 16 + ((lane >> 4) & 1) * 8 + (lane & 7);
                int nch  = 2 * ks + ((lane >> 3) & 1);
                uint32_t baddr = sb32 + 65536 + (uint32_t)nrow * 256 +
                                 ((nch ^ (nrow & 7)) << 4);
                uint32_t bh_[4], bl_[4];
                ldsm_x4(bh_, baddr);
                ldsm_x4(bl_, baddr + 16384);
                #pragma unroll
                for (int nt = 0; nt < 2; nt++) {
                    float* d = sc[g * 2 + nt];
                    mma16816h(d, ah,  bh_[nt * 2], bh_[nt * 2 + 1]);
                    mma16816h(d, ah,  bl_[nt * 2], bl_[nt * 2 + 1]);
                    mma16816h(d, al_, bh_[nt * 2], bh_[nt * 2 + 1]);
                }
            }
        }

        // ---- scale scores (fp32) ----
        #pragma unroll
        for (int t = 0; t < 8; t++)
            #pragma unroll
            for (int q = 0; q < 4; q++) sc[t][q] *= SCALE;

        // ---- causal mask (near-diagonal tiles only) ----
        if (kv0 + 63 > q0 + wm) {
            int r0g = q0 + wm + (lane >> 2);
            int r1g = r0g + 8;
            #pragma unroll
            for (int t = 0; t < 8; t++) {
                int kva = kv0 + t * 8 + (lane & 3) * 2;
                int kvb = kva + 1;
                if (kva > r0g) sc[t][0] = -1.0e30f;
                if (kvb > r0g) sc[t][1] = -1.0e30f;
                if (kva > r1g) sc[t][2] = -1.0e30f;
                if (kvb > r1g) sc[t][3] = -1.0e30f;
            }
        }

        // ---- online softmax (quad reductions in accumulator layout) ----
        float mx0 = m0r, mx1 = m1r;
        #pragma unroll
        for (int t = 0; t < 8; t++) {
            mx0 = fmaxf(mx0, fmaxf(sc[t][0], sc[t][1]));
            mx1 = fmaxf(mx1, fmaxf(sc[t][2], sc[t][3]));
        }
        mx0 = fmaxf(mx0, __shfl_xor_sync(0xffffffffu, mx0, 1));
        mx0 = fmaxf(mx0, __shfl_xor_sync(0xffffffffu, mx0, 2));
        mx1 = fmaxf(mx1, __shfl_xor_sync(0xffffffffu, mx1, 1));
        mx1 = fmaxf(mx1, __shfl_xor_sync(0xffffffffu, mx1, 2));

        float corr0 = __expf(m0r - mx0);
        float corr1 = __expf(m1r - mx1);
        m0r = mx0; m1r = mx1;

        float sum0 = 0.0f, sum1 = 0.0f;
        #pragma unroll
        for (int t = 0; t < 8; t++) {
            sc[t][0] = __expf(sc[t][0] - mx0); sum0 += sc[t][0];
            sc[t][1] = __expf(sc[t][1] - mx0); sum0 += sc[t][1];
            sc[t][2] = __expf(sc[t][2] - mx1); sum1 += sc[t][2];
            sc[t][3] = __expf(sc[t][3] - mx1); sum1 += sc[t][3];
        }
        sum0 += __shfl_xor_sync(0xffffffffu, sum0, 1);
        sum0 += __shfl_xor_sync(0xffffffffu, sum0, 2);
        sum1 += __shfl_xor_sync(0xffffffffu, sum1, 1);
        sum1 += __shfl_xor_sync(0xffffffffu, sum1, 2);
        l0r = l0r * corr0 + sum0;
        l1r = l1r * corr1 + sum1;

        #pragma unroll
        for (int t = 0; t < 16; t++) {
            oacc[t][0] *= corr0; oacc[t][1] *= corr0;
            oacc[t][2] *= corr1; oacc[t][3] *= corr1;
        }

        // ---- O += P V (P single fp16 in registers), 2 MMAs ----
        #pragma unroll
        for (int kt = 0; kt < 4; kt++) {
            uint32_t pa[4];
            pa[0] = pack_h2(sc[2 * kt][0],     sc[2 * kt][1]);
            pa[1] = pack_h2(sc[2 * kt][2],     sc[2 * kt][3]);
            pa[2] = pack_h2(sc[2 * kt + 1][0], sc[2 * kt + 1][1]);
            pa[3] = pack_h2(sc[2 * kt + 1][2], sc[2 * kt + 1][3]);
            #pragma unroll
            for (int dg = 0; dg < 8; dg++) {
                int vrow = kt * 16 + ((lane >> 3) & 1) * 8 + (lane & 7);
                int vch  = dg * 2 + (lane >> 4);
                uint32_t vaddr = sb32 + 98304 + (uint32_t)vrow * 256 +
                                 ((vch ^ (vrow & 7)) << 4);
                uint32_t vh[4], vl[4];
                ldsm_x4_trans(vh, vaddr);
                ldsm_x4_trans(vl, vaddr + 16384);
                #pragma unroll
                for (int nt = 0; nt < 2; nt++) {
                    float* d = oacc[dg * 2 + nt];
                    mma16816h(d, pa, vh[nt * 2], vh[nt * 2 + 1]);
                    mma16816h(d, pa, vl[nt * 2], vl[nt * 2 + 1]);
                }
            }
        }
    }

    // ---- epilogue: normalize, split, write fp16 hi/lo planes ----
    {
        float inv0 = 1.0f / l0r, inv1 = 1.0f / l1r;
        int r0g = q0 + wm + (lane >> 2);
        int r1g = r0g + 8;
        size_t b0 = ((size_t)(b * SEQ + r0g) * NHEADS + h) * HEADD;
        size_t b1 = ((size_t)(b * SEQ + r1g) * NHEADS + h) * HEADD;
        #pragma unroll
        for (int t = 0; t < 16; t++) {
            int d = t * 8 + (lane & 3) * 2;
            uint32_t hh, ll;
            split3h(oacc[t][0] * inv0, oacc[t][1] * inv0, hh, ll);
            *(uint32_t*)(g_Oh + b0 + d) = hh;
            *(uint32_t*)(g_Ol + b0 + d) = ll;
            split3h(oacc[t][2] * inv1, oacc[t][3] * inv1, hh, ll);
            *(uint32_t*)(g_Oh + b1 + d) = hh;
            *(uint32_t*)(g_Ol + b1 + d) = ll;
        }
    }
}

// ---------------------------------------------------------------------------
extern "C" void kernel_launch(void* const* d_in, const int* in_sizes, int n_in,
                              void* d_out, int out_size)
{
    const float* x    = (const float*)d_in[0];
    const float* wq   = (const float*)d_in[1];
    const float* bq   = (const float*)d_in[2];
    const float* wk   = (const float*)d_in[3];
    const float* bk   = (const float*)d_in[4];
    const float* wv   = (const float*)d_in[5];
    const float* bv   = (const float*)d_in[6];
    const float* wo   = (const float*)d_in[7];
    const float* bo   = (const float*)d_in[8];
    const float* cosb = (const float*)d_in[9];
    const float* sinb = (const float*)d_in[10];
    float* out = (float*)d_out;

    float *Qp, *Kp;
    cudaGetSymbolAddress((void**)&Qp, g_Q);
    cudaGetSymbolAddress((void**)&Kp, g_K);
    __half *xh, *xl, *wqh, *wkh, *wvh, *woh;
    __half *qh, *ql, *kH, *kL, *vh, *vl, *oh, *ol;
    cudaGetSymbolAddress((void**)&xh, g_xh);   cudaGetSymbolAddress((void**)&xl, g_xl);
    cudaGetSymbolAddress((void**)&wqh, g_wq);  cudaGetSymbolAddress((void**)&wkh, g_wk);
    cudaGetSymbolAddress((void**)&wvh, g_wv);  cudaGetSymbolAddress((void**)&woh, g_wo);
    cudaGetSymbolAddress((void**)&qh, g_Qh);   cudaGetSymbolAddress((void**)&ql, g_Ql);
    cudaGetSymbolAddress((void**)&kH, g_Kh);   cudaGetSymbolAddress((void**)&kL, g_Kl);
    cudaGetSymbolAddress((void**)&vh, g_Vh);   cudaGetSymbolAddress((void**)&vl, g_Vl);
    cudaGetSymbolAddress((void**)&oh, g_Oh);   cudaGetSymbolAddress((void**)&ol, g_Ol);

    cudaFuncSetAttribute(gemm_mma_h2,
                         cudaFuncAttributeMaxDynamicSharedMemorySize, GEMM_SMEM);
    cudaFuncSetAttribute(attn_mma_kernel,
                         cudaFuncAttributeMaxDynamicSharedMemorySize, ATTN_SMEM);

    // 0. One-shot conversions
    {
        int n;
        n = MROWS * HDIM;  split_h2_kernel<<<n / 8 / 256, 256>>>(x,  xh, xl, n);
        n = HDIM * HDIM;   split_h1_kernel<<<n / 8 / 256, 256>>>(wq, wqh, n);
        n = KVDIM * HDIM;  split_h1_kernel<<<n / 8 / 256, 256>>>(wk, wkh, n);
        n = KVDIM * HDIM;  split_h1_kernel<<<n / 8 / 256, 256>>>(wv, wvh, n);
        n = HDIM * HDIM;   split_h1_kernel<<<n / 8 / 256, 256>>>(wo, woh, n);
    }

    // 1-3. QKV projections (+bias), fp16 asymmetric x2
    gemm_mma_h2<<<dim3(HDIM / 128,  MROWS / 128), 256, GEMM_SMEM>>>(
        xh, xl, wqh, bq, Qp, nullptr, nullptr, HDIM, HDIM);
    gemm_mma_h2<<<dim3(KVDIM / 128, MROWS / 128), 256, GEMM_SMEM>>>(
        xh, xl, wkh, bk, Kp, nullptr, nullptr, HDIM, KVDIM);
    gemm_mma_h2<<<dim3(KVDIM / 128, MROWS / 128), 256, GEMM_SMEM>>>(
        xh, xl, wvh, bv, nullptr, vh, vl, HDIM, KVDIM);

    // 4-5. RoPE + fp16 split (unscaled; attention applies 1/sqrt(d))
    {
        int totq = NB * SEQ * NHEADS * 64;
        rope_split_kernel<<<(totq + 255) / 256, 256>>>(Qp, qh, ql, cosb, sinb,
                                                       NHEADS, totq);
        int totk = NB * SEQ * KVHEADS * 64;
        rope_split_kernel<<<(totk + 255) / 256, 256>>>(Kp, kH, kL, cosb, sinb,
                                                       KVHEADS, totk);
    }

    // 6. Causal GQA flash attention (fp16 tensor cores)
    attn_mma_kernel<<<dim3(SEQ / 128, NB * NHEADS), 256, ATTN_SMEM>>>();

    // 7. Output projection (+bias) straight into d_out
    gemm_mma_h2<<<dim3(HDIM / 128, MROWS / 128), 256, GEMM_SMEM>>>(
        oh, ol, woh, bo, out, nullptr, nullptr, HDIM, HDIM);
}

// round 14
// speedup vs baseline: 3.9589x; 1.0636x over previous
#include <cuda_runtime.h>
#include <cuda_bf16.h>
#include <cuda_fp16.h>
#include <math.h>
#include <stdint.h>

// Problem constants
#define NB      2
#define SEQ     2048
#define HDIM    2048
#define NHEADS  16
#define KVHEADS 4
#define HEADD   128
#define KVDIM   (KVHEADS * HEADD)   // 512
#define MROWS   (NB * SEQ)          // 4096
#define QSTRIDE (NHEADS * HEADD)    // 2048
#define KSTRIDE (KVHEADS * HEADD)   // 512

// fp32 scratch (Q/K GEMM outputs pre-RoPE)
__device__ float g_Q[(size_t)MROWS * HDIM];
__device__ float g_K[(size_t)MROWS * KVDIM];

// fp16 planes
__device__ __half g_xh[(size_t)MROWS * HDIM],  g_xl[(size_t)MROWS * HDIM];   // x hi/lo
__device__ __half g_wq[(size_t)HDIM * HDIM];                                  // weights (single)
__device__ __half g_wk[(size_t)KVDIM * HDIM];
__device__ __half g_wv[(size_t)KVDIM * HDIM];
__device__ __half g_wo[(size_t)HDIM * HDIM];
__device__ __half g_Qh[(size_t)MROWS * HDIM],  g_Ql[(size_t)MROWS * HDIM];   // post-rope Q hi/lo
__device__ __half g_Kh[(size_t)MROWS * KVDIM], g_Kl[(size_t)MROWS * KVDIM];
__device__ __half g_Vh[(size_t)MROWS * KVDIM], g_Vl[(size_t)MROWS * KVDIM];
__device__ __half g_Oh[(size_t)MROWS * HDIM],  g_Ol[(size_t)MROWS * HDIM];   // attn out hi/lo

// ===========================================================================
// Helpers
// ===========================================================================
__device__ __forceinline__ uint32_t smem_to_u32(const void* p) {
    uint32_t a;
    asm("{ .reg .u64 t; cvta.to.shared.u64 t, %1; cvt.u32.u64 %0, t; }"
        : "=r"(a) : "l"(p));
    return a;
}

// fp16x2 split: (a,b) -> packed hi half2 + packed lo half2 (exact to ~2^-22)
__device__ __forceinline__ void split3h(float a, float b, uint32_t& hi, uint32_t& lo)
{
    __half2 h = __floats2half2_rn(a, b);
    float2 hf = __half22float2(h);
    __half2 l = __floats2half2_rn(a - hf.x, b - hf.y);
    hi = *reinterpret_cast<uint32_t*>(&h);
    lo = *reinterpret_cast<uint32_t*>(&l);
}
__device__ __forceinline__ uint32_t pack_h2(float a, float b)
{
    __half2 h = __floats2half2_rn(a, b);
    return *reinterpret_cast<uint32_t*>(&h);
}

__device__ __forceinline__ void ldsm_x4(uint32_t* r, uint32_t addr)
{
    asm volatile("ldmatrix.sync.aligned.m8n8.x4.shared.b16 {%0,%1,%2,%3}, [%4];"
        : "=r"(r[0]), "=r"(r[1]), "=r"(r[2]), "=r"(r[3]) : "r"(addr));
}
__device__ __forceinline__ void ldsm_x4_trans(uint32_t* r, uint32_t addr)
{
    asm volatile("ldmatrix.sync.aligned.m8n8.x4.trans.shared.b16 {%0,%1,%2,%3}, [%4];"
        : "=r"(r[0]), "=r"(r[1]), "=r"(r[2]), "=r"(r[3]) : "r"(addr));
}

// fp16 MMA, fp32 accum
__device__ __forceinline__ void mma16816h(float* d, const uint32_t* a,
                                          uint32_t b0, uint32_t b1)
{
    asm volatile(
        "mma.sync.aligned.m16n8k16.row.col.f32.f16.f16.f32 "
        "{%0,%1,%2,%3}, {%4,%5,%6,%7}, {%8,%9}, {%0,%1,%2,%3};"
        : "+f"(d[0]), "+f"(d[1]), "+f"(d[2]), "+f"(d[3])
        : "r"(a[0]), "r"(a[1]), "r"(a[2]), "r"(a[3]), "r"(b0), "r"(b1));
}

#define CP_ASYNC16(dst, src) \
    asm volatile("cp.async.ca.shared.global [%0], [%1], 16;" \
        :: "r"(dst), "l"(src) : "memory")
#define CP_COMMIT() asm volatile("cp.async.commit_group;" ::: "memory")
#define CP_WAIT0()  asm volatile("cp.async.wait_group 0;" ::: "memory")
#define CP_WAIT1()  asm volatile("cp.async.wait_group 1;" ::: "memory")

// ===========================================================================
// One-shot fp32 -> fp16 conversions
// ===========================================================================
__global__ void split_h2_kernel(const float* __restrict__ s,
                                __half* __restrict__ hi,
                                __half* __restrict__ lo, int n)
{
    int i = (blockIdx.x * blockDim.x + threadIdx.x) * 8;
    if (i >= n) return;
    float4 f0 = *(const float4*)(s + i);
    float4 f1 = *(const float4*)(s + i + 4);
    uint32_t h0, l0, h1, l1, h2, l2, h3, l3;
    split3h(f0.x, f0.y, h0, l0);
    split3h(f0.z, f0.w, h1, l1);
    split3h(f1.x, f1.y, h2, l2);
    split3h(f1.z, f1.w, h3, l3);
    *(uint4*)(hi + i) = make_uint4(h0, h1, h2, h3);
    *(uint4*)(lo + i) = make_uint4(l0, l1, l2, l3);
}
__global__ void split_h1_kernel(const float* __restrict__ s,
                                __half* __restrict__ h, int n)
{
    int i = (blockIdx.x * blockDim.x + threadIdx.x) * 8;
    if (i >= n) return;
    float4 f0 = *(const float4*)(s + i);
    float4 f1 = *(const float4*)(s + i + 4);
    *(uint4*)(h + i) = make_uint4(pack_h2(f0.x, f0.y), pack_h2(f0.z, f0.w),
                                  pack_h2(f1.x, f1.y), pack_h2(f1.z, f1.w));
}

// ===========================================================================
// fp16 asymmetric-x2 tensor-core GEMM core (shared by fused-QKV and O kernels)
// C[M,N] = (Ah+Al)[M,K] @ Bh[N,K]^T + bias[N], K = HDIM.
// CTA 128x128, K-chunk 32, 8 warps, double-buffered cp.async smem.
// Stage (24KB): Ahi[128][32] | Alo | Bh  (fp16, chunk-XOR swizzle)
// ===========================================================================
#define GEMM_SMEM (2 * 24576)

__device__ __forceinline__ void load_chunk_async(
    const __half* __restrict__ Ah, const __half* __restrict__ Al,
    const __half* __restrict__ Bh,
    int K, int m0, int n0, int kc, uint32_t stage32, int tid)
{
    #pragma unroll
    for (int j = 0; j < 2; j++) {
        int job = tid + j * 256;            // 0..511
        int row = job >> 2, c16 = job & 3;  // 16B chunk = 8 fp16 k-values
        uint32_t off = (uint32_t)row * 64 + ((c16 ^ ((row >> 1) & 3)) << 4);
        size_t ga = (size_t)(m0 + row) * K + kc + c16 * 8;
        size_t gb = (size_t)(n0 + row) * K + kc + c16 * 8;
        CP_ASYNC16(stage32 + off,         Ah + ga);
        CP_ASYNC16(stage32 + 8192 + off,  Al + ga);
        CP_ASYNC16(stage32 + 16384 + off, Bh + gb);
    }
}

__device__ __forceinline__ void gemm_core(
    const __half* __restrict__ Ah, const __half* __restrict__ Al,
    const __half* __restrict__ Bh,
    const float* __restrict__ bias,
    float* __restrict__ C,
    __half* __restrict__ Ch, __half* __restrict__ Cl,
    int N, int m0, int n0, uint32_t sb32)
{
    const int K = HDIM;
    const int tid  = threadIdx.x;
    const int lane = tid & 31;
    const int wid  = tid >> 5;
    const int wm   = (wid >> 1) * 32;
    const int wn   = (wid & 1) * 64;

    float acc[2][8][4];
    #pragma unroll
    for (int i = 0; i < 2; i++)
        #pragma unroll
        for (int j = 0; j < 8; j++)
            #pragma unroll
            for (int q = 0; q < 4; q++) acc[i][j][q] = 0.0f;

    const int NCH = K >> 5;

    load_chunk_async(Ah, Al, Bh, K, m0, n0, 0, sb32, tid);
    CP_COMMIT();

    for (int c = 0; c < NCH; c++) {
        if (c + 1 < NCH) {
            load_chunk_async(Ah, Al, Bh, K, m0, n0, (c + 1) << 5,
                             sb32 + ((c + 1) & 1) * 24576u, tid);
            CP_COMMIT();
            CP_WAIT1();
        } else {
            CP_WAIT0();
        }
        __syncthreads();

        const uint32_t stb = sb32 + (c & 1) * 24576u;

        #pragma unroll
        for (int ks = 0; ks < 2; ks++) {
            uint32_t ah[2][4], al[2][4];
            #pragma unroll
            for (int mt = 0; mt < 2; mt++) {
                int row = wm + mt * 16 + (lane & 15);
                int c16 = ks * 2 + (lane >> 4);
                uint32_t ad = stb + (uint32_t)row * 64 +
                              ((c16 ^ ((row >> 1) & 3)) << 4);
                ldsm_x4(ah[mt], ad);
                ldsm_x4(al[mt], ad + 8192);
            }
            #pragma unroll
            for (int g = 0; g < 4; g++) {
                int n   = wn + g * 16 + ((lane >> 4) & 1) * 8 + (lane & 7);
                int c16 = ks * 2 + ((lane >> 3) & 1);
                uint32_t bd = stb + 16384 + (uint32_t)n * 64 +
                              ((c16 ^ ((n >> 1) & 3)) << 4);
                uint32_t bh[4];
                ldsm_x4(bh, bd);
                #pragma unroll
                for (int mt = 0; mt < 2; mt++) {
                    #pragma unroll
                    for (int nt = 0; nt < 2; nt++) {
                        float* d = acc[mt][g * 2 + nt];
                        mma16816h(d, ah[mt], bh[nt * 2], bh[nt * 2 + 1]);
                        mma16816h(d, al[mt], bh[nt * 2], bh[nt * 2 + 1]);
                    }
                }
            }
        }
        __syncthreads();
    }

    // ---- epilogue: fused bias; fp32 or fp16-split output ----
    #pragma unroll
    for (int mt = 0; mt < 2; mt++) {
        int row0 = m0 + wm + mt * 16 + (lane >> 2);
        int row1 = row0 + 8;
        #pragma unroll
        for (int n8 = 0; n8 < 8; n8++) {
            int col = n0 + wn + n8 * 8 + (lane & 3) * 2;
            float b0 = bias[col], b1 = bias[col + 1];
            float v00 = acc[mt][n8][0] + b0, v01 = acc[mt][n8][1] + b1;
            float v10 = acc[mt][n8][2] + b0, v11 = acc[mt][n8][3] + b1;
            if (C) {
                *(float2*)(C + (size_t)row0 * N + col) = make_float2(v00, v01);
                *(float2*)(C + (size_t)row1 * N + col) = make_float2(v10, v11);
            } else {
                uint32_t h, l;
                split3h(v00, v01, h, l);
                *(uint32_t*)(Ch + (size_t)row0 * N + col) = h;
                *(uint32_t*)(Cl + (size_t)row0 * N + col) = l;
                split3h(v10, v11, h, l);
                *(uint32_t*)(Ch + (size_t)row1 * N + col) = h;
                *(uint32_t*)(Cl + (size_t)row1 * N + col) = l;
            }
        }
    }
}

// Fused Q/K/V projection: 24 n-tiles (16 Q | 4 K | 4 V) x 32 m-tiles.
__global__ void __launch_bounds__(256, 2) gemm_qkv_fused(
    const __half* __restrict__ xh, const __half* __restrict__ xl,
    const __half* __restrict__ wq, const __half* __restrict__ wk,
    const __half* __restrict__ wv,
    const float* __restrict__ bq, const float* __restrict__ bk,
    const float* __restrict__ bv,
    float* __restrict__ Qf, float* __restrict__ Kf,
    __half* __restrict__ Vh, __half* __restrict__ Vl)
{
    extern __shared__ char smem[];
    const uint32_t sb32 = smem_to_u32(smem);
    const int nt = blockIdx.x;           // 0..23
    const int m0 = blockIdx.y * 128;

    if (nt < 16) {
        gemm_core(xh, xl, wq, bq, Qf, nullptr, nullptr,
                  HDIM, m0, nt * 128, sb32);
    } else if (nt < 20) {
        gemm_core(xh, xl, wk, bk, Kf, nullptr, nullptr,
                  KVDIM, m0, (nt - 16) * 128, sb32);
    } else {
        gemm_core(xh, xl, wv, bv, nullptr, Vh, Vl,
                  KVDIM, m0, (nt - 20) * 128, sb32);
    }
}

// O projection (separate: depends on attention output)
__global__ void __launch_bounds__(256, 2) gemm_o(
    const __half* __restrict__ Ah, const __half* __restrict__ Al,
    const __half* __restrict__ Bh, const float* __restrict__ bias,
    float* __restrict__ C)
{
    extern __shared__ char smem[];
    const uint32_t sb32 = smem_to_u32(smem);
    gemm_core(Ah, Al, Bh, bias, C, nullptr, nullptr,
              HDIM, blockIdx.y * 128, blockIdx.x * 128, sb32);
}

// ---------------------------------------------------------------------------
// RoPE + fp16 hi/lo split for Q and K in one launch.
// ---------------------------------------------------------------------------
__global__ void rope_split_kernel(const float* __restrict__ Qf,
                                  const float* __restrict__ Kf,
                                  __half* __restrict__ Qh, __half* __restrict__ Ql,
                                  __half* __restrict__ Kh, __half* __restrict__ Kl,
                                  const float* __restrict__ cosb,
                                  const float* __restrict__ sinb,
                                  int totq, int total)
{
    int idx = blockIdx.x * blockDim.x + threadIdx.x;
    if (idx >= total) return;
    const float* T;
    __half *Th, *Tl;
    int heads;
    if (idx < totq) { T = Qf; Th = Qh; Tl = Ql; heads = NHEADS; }
    else { idx -= totq; T = Kf; Th = Kh; Tl = Kl; heads = KVHEADS; }
    int d  = idx & 63;
    int h  = (idx >> 6) % heads;
    int bs = idx / (64 * heads);
    int s  = bs % SEQ;
    float c  = cosb[s * HEADD + d];
    float sn = sinb[s * HEADD + d];
    size_t base = ((size_t)bs * heads + h) * HEADD;
    float q0 = T[base + d], q1 = T[base + d + 64];
    float v0 = q0 * c - q1 * sn;
    float v1 = q1 * c + q0 * sn;
    __half h0 = __float2half_rn(v0);
    __half h1 = __float2half_rn(v1);
    Th[base + d]      = h0;
    Tl[base + d]      = __float2half_rn(v0 - __half2float(h0));
    Th[base + d + 64] = h1;
    Tl[base + d + 64] = __float2half_rn(v1 - __half2float(h1));
}

// ===========================================================================
// Tensor-core flash attention (fp16), causal, GQA rep=4, double-buffered K/V.
// BQ=128, BK=64, 8 warps. 1 CTA/SM, 192KB smem.
// smem: Qhi @0 (32KB) | Qlo @32768 | stage s in {0,1} at 65536 + s*65536:
//       Khi +0 | Klo +16384 | Vhi +32768 | Vl +49152  (each 16KB)
// QK: 3 MMAs; scores scaled in fp32; P single fp16; PV: 2 MMAs.
// ===========================================================================
#define ATTN_SMEM 196608

__global__ void __launch_bounds__(256) attn_mma_kernel()
{
    extern __shared__ char sb[];
    const uint32_t sb32 = smem_to_u32(sb);

    const int tid  = threadIdx.x;
    const int lane = tid & 31;
    const int wid  = tid >> 5;
    const int wm   = wid * 16;

    const int q0 = (gridDim.x - 1 - blockIdx.x) * 128;   // heavy blocks first
    const int bh = blockIdx.y;
    const int b  = bh / NHEADS;
    const int h  = bh % NHEADS;
    const int kh = h / (NHEADS / KVHEADS);

    const size_t qoff = ((size_t)b * SEQ * NHEADS  + h)  * HEADD;
    const size_t koff = ((size_t)b * SEQ * KVHEADS + kh) * HEADD;
    const __half* Qh = g_Qh + qoff;
    const __half* Ql = g_Ql + qoff;
    const __half* Kh = g_Kh + koff;
    const __half* Kl = g_Kl + koff;
    const __half* Vh = g_Vh + koff;
    const __half* Vl = g_Vl + koff;
    const float SCALE = 0.08838834764831845f;   // 1/sqrt(128)

    // ---- load Q tile (group 0) ----
    #pragma unroll
    for (int i = 0; i < 8; i++) {
        int job = tid + i * 256;          // 0..2047
        int row = job >> 4, ch = job & 15;
        uint32_t off = (uint32_t)row * 256 + ((ch ^ (row & 7)) << 4);
        size_t ga = (size_t)(q0 + row) * QSTRIDE + ch * 8;
        CP_ASYNC16(sb32 + off,         Qh + ga);
        CP_ASYNC16(sb32 + 32768 + off, Ql + ga);
    }
    CP_COMMIT();

    float oacc[16][4];
    #pragma unroll
    for (int t = 0; t < 16; t++)
        #pragma unroll
        for (int q = 0; q < 4; q++) oacc[t][q] = 0.0f;
    float m0r = -INFINITY, m1r = -INFINITY;
    float l0r = 0.0f, l1r = 0.0f;

    const int ktiles = q0 / 64 + 2;

    // ---- prologue: K/V tile 0 into stage 0 ----
    {
        const uint32_t st = sb32 + 65536;
        #pragma unroll
        for (int i = 0; i < 4; i++) {
            int job = tid + i * 256;
            int row = job >> 4, ch = job & 15;
            uint32_t off = (uint32_t)row * 256 + ((ch ^ (row & 7)) << 4);
            size_t ga = (size_t)row * KSTRIDE + ch * 8;
            CP_ASYNC16(st + off,         Kh + ga);
            CP_ASYNC16(st + 16384 + off, Kl + ga);
            CP_ASYNC16(st + 32768 + off, Vh + ga);
            CP_ASYNC16(st + 49152 + off, Vl + ga);
        }
        CP_COMMIT();
    }

    for (int kti = 0; kti < ktiles; kti++) {
        const int kv0 = kti * 64;

        // ---- prefetch next K/V tile into the other stage ----
        if (kti + 1 < ktiles) {
            const uint32_t st = sb32 + 65536 + ((kti + 1) & 1) * 65536u;
            const int nv0 = (kti + 1) * 64;
            #pragma unroll
            for (int i = 0; i < 4; i++) {
                int job = tid + i * 256;
                int row = job >> 4, ch = job & 15;
                uint32_t off = (uint32_t)row * 256 + ((ch ^ (row & 7)) << 4);
                size_t ga = (size_t)(nv0 + row) * KSTRIDE + ch * 8;
                CP_ASYNC16(st + off,         Kh + ga);
                CP_ASYNC16(st + 16384 + off, Kl + ga);
                CP_ASYNC16(st + 32768 + off, Vh + ga);
                CP_ASYNC16(st + 49152 + off, Vl + ga);
            }
            CP_COMMIT();
            CP_WAIT1();
        } else {
            CP_WAIT0();
        }
        __syncthreads();

        if (kv0 <= q0 + wm + 15) {      // not fully masked for this warp
        const uint32_t stK = sb32 + 65536 + (kti & 1) * 65536u;
        const uint32_t stV = stK + 32768;

        // ---- S = Q K^T, fp16x2 (3 MMAs) ----
        float sc[8][4];
        #pragma unroll
        for (int t = 0; t < 8; t++)
            #pragma unroll
            for (int q = 0; q < 4; q++) sc[t][q] = 0.0f;

        #pragma unroll
        for (int ks = 0; ks < 8; ks++) {
            int arow = wm + (lane & 15);
            int ach  = 2 * ks + (lane >> 4);
            uint32_t aaddr = sb32 + (uint32_t)arow * 256 +
                             ((ach ^ (arow & 7)) << 4);
            uint32_t ah[4], al_[4];
            ldsm_x4(ah, aaddr);
            ldsm_x4(al_, aaddr + 32768);
            #pragma unroll
            for (int g = 0; g < 4; g++) {
                int nrow = g * 16 + ((lane >> 4) & 1) * 8 + (lane & 7);
                int nch  = 2 * ks + ((lane >> 3) & 1);
                uint32_t baddr = stK + (uint32_t)nrow * 256 +
                                 ((nch ^ (nrow & 7)) << 4);
                uint32_t bh_[4], bl_[4];
                ldsm_x4(bh_, baddr);
                ldsm_x4(bl_, baddr + 16384);
                #pragma unroll
                for (int nt = 0; nt < 2; nt++) {
                    float* d = sc[g * 2 + nt];
                    mma16816h(d, ah,  bh_[nt * 2], bh_[nt * 2 + 1]);
                    mma16816h(d, ah,  bl_[nt * 2], bl_[nt * 2 + 1]);
                    mma16816h(d, al_, bh_[nt * 2], bh_[nt * 2 + 1]);
                }
            }
        }

        // ---- scale scores (fp32) ----
        #pragma unroll
        for (int t = 0; t < 8; t++)
            #pragma unroll
            for (int q = 0; q < 4; q++) sc[t][q] *= SCALE;

        // ---- causal mask (near-diagonal tiles only) ----
        if (kv0 + 63 > q0 + wm) {
            int r0g = q0 + wm + (lane >> 2);
            int r1g = r0g + 8;
            #pragma unroll
            for (int t = 0; t < 8; t++) {
                int kva = kv0 + t * 8 + (lane & 3) * 2;
                int kvb = kva + 1;
                if (kva > r0g) sc[t][0] = -1.0e30f;
                if (kvb > r0g) sc[t][1] = -1.0e30f;
                if (kva > r1g) sc[t][2] = -1.0e30f;
                if (kvb > r1g) sc[t][3] = -1.0e30f;
            }
        }

        // ---- online softmax (quad reductions in accumulator layout) ----
        float mx0 = m0r, mx1 = m1r;
        #pragma unroll
        for (int t = 0; t < 8; t++) {
            mx0 = fmaxf(mx0, fmaxf(sc[t][0], sc[t][1]));
            mx1 = fmaxf(mx1, fmaxf(sc[t][2], sc[t][3]));
        }
        mx0 = fmaxf(mx0, __shfl_xor_sync(0xffffffffu, mx0, 1));
        mx0 = fmaxf(mx0, __shfl_xor_sync(0xffffffffu, mx0, 2));
        mx1 = fmaxf(mx1, __shfl_xor_sync(0xffffffffu, mx1, 1));
        mx1 = fmaxf(mx1, __shfl_xor_sync(0xffffffffu, mx1, 2));

        float corr0 = __expf(m0r - mx0);
        float corr1 = __expf(m1r - mx1);
        m0r = mx0; m1r = mx1;

        float sum0 = 0.0f, sum1 = 0.0f;
        #pragma unroll
        for (int t = 0; t < 8; t++) {
            sc[t][0] = __expf(sc[t][0] - mx0); sum0 += sc[t][0];
            sc[t][1] = __expf(sc[t][1] - mx0); sum0 += sc[t][1];
            sc[t][2] = __expf(sc[t][2] - mx1); sum1 += sc[t][2];
            sc[t][3] = __expf(sc[t][3] - mx1); sum1 += sc[t][3];
        }
        sum0 += __shfl_xor_sync(0xffffffffu, sum0, 1);
        sum0 += __shfl_xor_sync(0xffffffffu, sum0, 2);
        sum1 += __shfl_xor_sync(0xffffffffu, sum1, 1);
        sum1 += __shfl_xor_sync(0xffffffffu, sum1, 2);
        l0r = l0r * corr0 + sum0;
        l1r = l1r * corr1 + sum1;

        #pragma unroll
        for (int t = 0; t < 16; t++) {
            oacc[t][0] *= corr0; oacc[t][1] *= corr0;
            oacc[t][2] *= corr1; oacc[t][3] *= corr1;
        }

        // ---- O += P V (P single fp16 in registers), 2 MMAs ----
        #pragma unroll
        for (int kt = 0; kt < 4; kt++) {
            uint32_t pa[4];
            pa[0] = pack_h2(sc[2 * kt][0],     sc[2 * kt][1]);
            pa[1] = pack_h2(sc[2 * kt][2],     sc[2 * kt][3]);
            pa[2] = pack_h2(sc[2 * kt + 1][0], sc[2 * kt + 1][1]);
            pa[3] = pack_h2(sc[2 * kt + 1][2], sc[2 * kt + 1][3]);
            #pragma unroll
            for (int dg = 0; dg < 8; dg++) {
                int vrow = kt * 16 + ((lane >> 3) & 1) * 8 + (lane & 7);
                int vch  = dg * 2 + (lane >> 4);
                uint32_t vaddr = stV + (uint32_t)vrow * 256 +
                                 ((vch ^ (vrow & 7)) << 4);
                uint32_t vh[4], vl[4];
                ldsm_x4_trans(vh, vaddr);
                ldsm_x4_trans(vl, vaddr + 16384);
                #pragma unroll
                for (int nt = 0; nt < 2; nt++) {
                    float* d = oacc[dg * 2 + nt];
                    mma16816h(d, pa, vh[nt * 2], vh[nt * 2 + 1]);
                    mma16816h(d, pa, vl[nt * 2], vl[nt * 2 + 1]);
                }
            }
        }
        }   // masked-warp guard

        __syncthreads();   // all warps done with stage kti&1 before refill
    }

    // ---- epilogue: normalize, split, write fp16 hi/lo planes ----
    {
        float inv0 = 1.0f / l0r, inv1 = 1.0f / l1r;
        int r0g = q0 + wm + (lane >> 2);
        int r1g = r0g + 8;
        size_t b0 = ((size_t)(b * SEQ + r0g) * NHEADS + h) * HEADD;
        size_t b1 = ((size_t)(b * SEQ + r1g) * NHEADS + h) * HEADD;
        #pragma unroll
        for (int t = 0; t < 16; t++) {
            int d = t * 8 + (lane & 3) * 2;
            uint32_t hh, ll;
            split3h(oacc[t][0] * inv0, oacc[t][1] * inv0, hh, ll);
            *(uint32_t*)(g_Oh + b0 + d) = hh;
            *(uint32_t*)(g_Ol + b0 + d) = ll;
            split3h(oacc[t][2] * inv1, oacc[t][3] * inv1, hh, ll);
            *(uint32_t*)(g_Oh + b1 + d) = hh;
            *(uint32_t*)(g_Ol + b1 + d) = ll;
        }
    }
}

// ---------------------------------------------------------------------------
extern "C" void kernel_launch(void* const* d_in, const int* in_sizes, int n_in,
                              void* d_out, int out_size)
{
    const float* x    = (const float*)d_in[0];
    const float* wq   = (const float*)d_in[1];
    const float* bq   = (const float*)d_in[2];
    const float* wk   = (const float*)d_in[3];
    const float* bk   = (const float*)d_in[4];
    const float* wv   = (const float*)d_in[5];
    const float* bv   = (const float*)d_in[6];
    const float* wo   = (const float*)d_in[7];
    const float* bo   = (const float*)d_in[8];
    const float* cosb = (const float*)d_in[9];
    const float* sinb = (const float*)d_in[10];
    float* out = (float*)d_out;

    float *Qp, *Kp;
    cudaGetSymbolAddress((void**)&Qp, g_Q);
    cudaGetSymbolAddress((void**)&Kp, g_K);
    __half *xh, *xl, *wqh, *wkh, *wvh, *woh;
    __half *qh, *ql, *kH, *kL, *vh, *vl, *oh, *ol;
    cudaGetSymbolAddress((void**)&xh, g_xh);   cudaGetSymbolAddress((void**)&xl, g_xl);
    cudaGetSymbolAddress((void**)&wqh, g_wq);  cudaGetSymbolAddress((void**)&wkh, g_wk);
    cudaGetSymbolAddress((void**)&wvh, g_wv);  cudaGetSymbolAddress((void**)&woh, g_wo);
    cudaGetSymbolAddress((void**)&qh, g_Qh);   cudaGetSymbolAddress((void**)&ql, g_Ql);
    cudaGetSymbolAddress((void**)&kH, g_Kh);   cudaGetSymbolAddress((void**)&kL, g_Kl);
    cudaGetSymbolAddress((void**)&vh, g_Vh);   cudaGetSymbolAddress((void**)&vl, g_Vl);
    cudaGetSymbolAddress((void**)&oh, g_Oh);   cudaGetSymbolAddress((void**)&ol, g_Ol);

    cudaFuncSetAttribute(gemm_qkv_fused,
                         cudaFuncAttributeMaxDynamicSharedMemorySize, GEMM_SMEM);
    cudaFuncSetAttribute(gemm_o,
                         cudaFuncAttributeMaxDynamicSharedMemorySize, GEMM_SMEM);
    cudaFuncSetAttribute(attn_mma_kernel,
                         cudaFuncAttributeMaxDynamicSharedMemorySize, ATTN_SMEM);

    // 0. One-shot conversions
    {
        int n;
        n = MROWS * HDIM;  split_h2_kernel<<<n / 8 / 256, 256>>>(x,  xh, xl, n);
        n = HDIM * HDIM;   split_h1_kernel<<<n / 8 / 256, 256>>>(wq, wqh, n);
        n = KVDIM * HDIM;  split_h1_kernel<<<n / 8 / 256, 256>>>(wk, wkh, n);
        n = KVDIM * HDIM;  split_h1_kernel<<<n / 8 / 256, 256>>>(wv, wvh, n);
        n = HDIM * HDIM;   split_h1_kernel<<<n / 8 / 256, 256>>>(wo, woh, n);
    }

    // 1. Fused QKV projection (+bias): 24 n-tiles x 32 m-tiles
    gemm_qkv_fused<<<dim3(24, MROWS / 128), 256, GEMM_SMEM>>>(
        xh, xl, wqh, wkh, wvh, bq, bk, bv, Qp, Kp, vh, vl);

    // 2. RoPE + fp16 split for Q and K (single launch)
    {
        int totq = NB * SEQ * NHEADS * 64;
        int totk = NB * SEQ * KVHEADS * 64;
        int tot  = totq + totk;
        rope_split_kernel<<<(tot + 255) / 256, 256>>>(
            Qp, Kp, qh, ql, kH, kL, cosb, sinb, totq, tot);
    }

    // 3. Causal GQA flash attention (fp16 tensor cores, double-buffered K/V)
    attn_mma_kernel<<<dim3(SEQ / 128, NB * NHEADS), 256, ATTN_SMEM>>>();

    // 4. Output projection (+bias) straight into d_out
    gemm_o<<<dim3(HDIM / 128, MROWS / 128), 256, GEMM_SMEM>>>(
        oh, ol, woh, bo, out);
}

// round 15
// speedup vs baseline: 4.3044x; 1.0873x over previous
#include <cuda_runtime.h>
#include <cuda_bf16.h>
#include <cuda_fp16.h>
#include <math.h>
#include <stdint.h>

// Problem constants
#define NB      2
#define SEQ     2048
#define HDIM    2048
#define NHEADS  16
#define KVHEADS 4
#define HEADD   128
#define KVDIM   (KVHEADS * HEADD)   // 512
#define MROWS   (NB * SEQ)          // 4096
#define QSTRIDE (NHEADS * HEADD)    // 2048
#define KSTRIDE (KVHEADS * HEADD)   // 512

// fp32 scratch (Q/K GEMM outputs pre-RoPE)
__device__ float g_Q[(size_t)MROWS * HDIM];
__device__ float g_K[(size_t)MROWS * KVDIM];

// fp16 planes
__device__ __half g_xh[(size_t)MROWS * HDIM],  g_xl[(size_t)MROWS * HDIM];   // x hi/lo
__device__ __half g_wq[(size_t)HDIM * HDIM];                                  // weights (single)
__device__ __half g_wk[(size_t)KVDIM * HDIM];
__device__ __half g_wv[(size_t)KVDIM * HDIM];
__device__ __half g_wo[(size_t)HDIM * HDIM];
__device__ __half g_Qh[(size_t)MROWS * HDIM],  g_Ql[(size_t)MROWS * HDIM];   // post-rope Q hi/lo
__device__ __half g_Kh[(size_t)MROWS * KVDIM], g_Kl[(size_t)MROWS * KVDIM];
__device__ __half g_Vh[(size_t)MROWS * KVDIM];                                // V single plane
__device__ __half g_Oh[(size_t)MROWS * HDIM],  g_Ol[(size_t)MROWS * HDIM];   // attn out hi/lo

// ===========================================================================
// Helpers
// ===========================================================================
__device__ __forceinline__ uint32_t smem_to_u32(const void* p) {
    uint32_t a;
    asm("{ .reg .u64 t; cvta.to.shared.u64 t, %1; cvt.u32.u64 %0, t; }"
        : "=r"(a) : "l"(p));
    return a;
}

// fp16x2 split: (a,b) -> packed hi half2 + packed lo half2 (exact to ~2^-22)
__device__ __forceinline__ void split3h(float a, float b, uint32_t& hi, uint32_t& lo)
{
    __half2 h = __floats2half2_rn(a, b);
    float2 hf = __half22float2(h);
    __half2 l = __floats2half2_rn(a - hf.x, b - hf.y);
    hi = *reinterpret_cast<uint32_t*>(&h);
    lo = *reinterpret_cast<uint32_t*>(&l);
}
__device__ __forceinline__ uint32_t pack_h2(float a, float b)
{
    __half2 h = __floats2half2_rn(a, b);
    return *reinterpret_cast<uint32_t*>(&h);
}

__device__ __forceinline__ void ldsm_x4(uint32_t* r, uint32_t addr)
{
    asm volatile("ldmatrix.sync.aligned.m8n8.x4.shared.b16 {%0,%1,%2,%3}, [%4];"
        : "=r"(r[0]), "=r"(r[1]), "=r"(r[2]), "=r"(r[3]) : "r"(addr));
}
__device__ __forceinline__ void ldsm_x4_trans(uint32_t* r, uint32_t addr)
{
    asm volatile("ldmatrix.sync.aligned.m8n8.x4.trans.shared.b16 {%0,%1,%2,%3}, [%4];"
        : "=r"(r[0]), "=r"(r[1]), "=r"(r[2]), "=r"(r[3]) : "r"(addr));
}

// fp16 MMA, fp32 accum
__device__ __forceinline__ void mma16816h(float* d, const uint32_t* a,
                                          uint32_t b0, uint32_t b1)
{
    asm volatile(
        "mma.sync.aligned.m16n8k16.row.col.f32.f16.f16.f32 "
        "{%0,%1,%2,%3}, {%4,%5,%6,%7}, {%8,%9}, {%0,%1,%2,%3};"
        : "+f"(d[0]), "+f"(d[1]), "+f"(d[2]), "+f"(d[3])
        : "r"(a[0]), "r"(a[1]), "r"(a[2]), "r"(a[3]), "r"(b0), "r"(b1));
}

#define CP_ASYNC16(dst, src) \
    asm volatile("cp.async.ca.shared.global [%0], [%1], 16;" \
        :: "r"(dst), "l"(src) : "memory")
#define CP_COMMIT() asm volatile("cp.async.commit_group;" ::: "memory")
#define CP_WAIT0()  asm volatile("cp.async.wait_group 0;" ::: "memory")
#define CP_WAIT1()  asm volatile("cp.async.wait_group 1;" ::: "memory")

// ===========================================================================
// One-shot conversion of ALL inputs (single launch):
//   x -> hi/lo fp16 pair; wq/wk/wv/wo -> single fp16 plane.
// ===========================================================================
#define XN  (MROWS * HDIM)     // 8388608
#define WQN (HDIM * HDIM)      // 4194304
#define WKN (KVDIM * HDIM)     // 1048576
#define CONV_TOTAL (XN + 2 * WQN + 2 * WKN)

__global__ void convert_all_kernel(
    const float* __restrict__ x,
    const float* __restrict__ wq, const float* __restrict__ wk,
    const float* __restrict__ wv, const float* __restrict__ wo,
    __half* __restrict__ xh, __half* __restrict__ xl,
    __half* __restrict__ owq, __half* __restrict__ owk,
    __half* __restrict__ owv, __half* __restrict__ owo)
{
    int i = (blockIdx.x * blockDim.x + threadIdx.x) * 8;
    if (i >= CONV_TOTAL) return;
    if (i < XN) {
        float4 f0 = *(const float4*)(x + i);
        float4 f1 = *(const float4*)(x + i + 4);
        uint32_t h0, l0, h1, l1, h2, l2, h3, l3;
        split3h(f0.x, f0.y, h0, l0);
        split3h(f0.z, f0.w, h1, l1);
        split3h(f1.x, f1.y, h2, l2);
        split3h(f1.z, f1.w, h3, l3);
        *(uint4*)(xh + i) = make_uint4(h0, h1, h2, h3);
        *(uint4*)(xl + i) = make_uint4(l0, l1, l2, l3);
        return;
    }
    i -= XN;
    const float* s;
    __half* d;
    if (i < WQN)                 { s = wq; d = owq; }
    else if (i < WQN + WKN)      { s = wk; d = owk; i -= WQN; }
    else if (i < WQN + 2 * WKN)  { s = wv; d = owv; i -= WQN + WKN; }
    else                         { s = wo; d = owo; i -= WQN + 2 * WKN; }
    float4 f0 = *(const float4*)(s + i);
    float4 f1 = *(const float4*)(s + i + 4);
    *(uint4*)(d + i) = make_uint4(pack_h2(f0.x, f0.y), pack_h2(f0.z, f0.w),
                                  pack_h2(f1.x, f1.y), pack_h2(f1.z, f1.w));
}

// ===========================================================================
// fp16 asymmetric-x2 tensor-core GEMM core (shared by fused-QKV and O kernels)
// C[M,N] = (Ah+Al)[M,K] @ Bh[N,K]^T + bias[N], K = HDIM.
// CTA 128x128, K-chunk 32, 8 warps, double-buffered cp.async smem.
// Stage (24KB): Ahi[128][32] | Alo | Bh  (fp16, chunk-XOR swizzle)
// Output modes: fp32 C, fp16 hi/lo pair (Ch+Cl), or fp16 single (Ch only).
// ===========================================================================
#define GEMM_SMEM (2 * 24576)

__device__ __forceinline__ void load_chunk_async(
    const __half* __restrict__ Ah, const __half* __restrict__ Al,
    const __half* __restrict__ Bh,
    int K, int m0, int n0, int kc, uint32_t stage32, int tid)
{
    #pragma unroll
    for (int j = 0; j < 2; j++) {
        int job = tid + j * 256;            // 0..511
        int row = job >> 2, c16 = job & 3;  // 16B chunk = 8 fp16 k-values
        uint32_t off = (uint32_t)row * 64 + ((c16 ^ ((row >> 1) & 3)) << 4);
        size_t ga = (size_t)(m0 + row) * K + kc + c16 * 8;
        size_t gb = (size_t)(n0 + row) * K + kc + c16 * 8;
        CP_ASYNC16(stage32 + off,         Ah + ga);
        CP_ASYNC16(stage32 + 8192 + off,  Al + ga);
        CP_ASYNC16(stage32 + 16384 + off, Bh + gb);
    }
}

__device__ __forceinline__ void gemm_core(
    const __half* __restrict__ Ah, const __half* __restrict__ Al,
    const __half* __restrict__ Bh,
    const float* __restrict__ bias,
    float* __restrict__ C,
    __half* __restrict__ Ch, __half* __restrict__ Cl,
    int N, int m0, int n0, uint32_t sb32)
{
    const int K = HDIM;
    const int tid  = threadIdx.x;
    const int lane = tid & 31;
    const int wid  = tid >> 5;
    const int wm   = (wid >> 1) * 32;
    const int wn   = (wid & 1) * 64;

    float acc[2][8][4];
    #pragma unroll
    for (int i = 0; i < 2; i++)
        #pragma unroll
        for (int j = 0; j < 8; j++)
            #pragma unroll
            for (int q = 0; q < 4; q++) acc[i][j][q] = 0.0f;

    const int NCH = K >> 5;

    load_chunk_async(Ah, Al, Bh, K, m0, n0, 0, sb32, tid);
    CP_COMMIT();

    for (int c = 0; c < NCH; c++) {
        if (c + 1 < NCH) {
            load_chunk_async(Ah, Al, Bh, K, m0, n0, (c + 1) << 5,
                             sb32 + ((c + 1) & 1) * 24576u, tid);
            CP_COMMIT();
            CP_WAIT1();
        } else {
            CP_WAIT0();
        }
        __syncthreads();

        const uint32_t stb = sb32 + (c & 1) * 24576u;

        #pragma unroll
        for (int ks = 0; ks < 2; ks++) {
            uint32_t ah[2][4], al[2][4];
            #pragma unroll
            for (int mt = 0; mt < 2; mt++) {
                int row = wm + mt * 16 + (lane & 15);
                int c16 = ks * 2 + (lane >> 4);
                uint32_t ad = stb + (uint32_t)row * 64 +
                              ((c16 ^ ((row >> 1) & 3)) << 4);
                ldsm_x4(ah[mt], ad);
                ldsm_x4(al[mt], ad + 8192);
            }
            #pragma unroll
            for (int g = 0; g < 4; g++) {
                int n   = wn + g * 16 + ((lane >> 4) & 1) * 8 + (lane & 7);
                int c16 = ks * 2 + ((lane >> 3) & 1);
                uint32_t bd = stb + 16384 + (uint32_t)n * 64 +
                              ((c16 ^ ((n >> 1) & 3)) << 4);
                uint32_t bh[4];
                ldsm_x4(bh, bd);
                #pragma unroll
                for (int mt = 0; mt < 2; mt++) {
                    #pragma unroll
                    for (int nt = 0; nt < 2; nt++) {
                        float* d = acc[mt][g * 2 + nt];
                        mma16816h(d, ah[mt], bh[nt * 2], bh[nt * 2 + 1]);
                        mma16816h(d, al[mt], bh[nt * 2], bh[nt * 2 + 1]);
                    }
                }
            }
        }
        __syncthreads();
    }

    // ---- epilogue: fused bias; fp32 / fp16-pair / fp16-single output ----
    #pragma unroll
    for (int mt = 0; mt < 2; mt++) {
        int row0 = m0 + wm + mt * 16 + (lane >> 2);
        int row1 = row0 + 8;
        #pragma unroll
        for (int n8 = 0; n8 < 8; n8++) {
            int col = n0 + wn + n8 * 8 + (lane & 3) * 2;
            float b0 = bias[col], b1 = bias[col + 1];
            float v00 = acc[mt][n8][0] + b0, v01 = acc[mt][n8][1] + b1;
            float v10 = acc[mt][n8][2] + b0, v11 = acc[mt][n8][3] + b1;
            if (C) {
                *(float2*)(C + (size_t)row0 * N + col) = make_float2(v00, v01);
                *(float2*)(C + (size_t)row1 * N + col) = make_float2(v10, v11);
            } else if (Cl) {
                uint32_t h, l;
                split3h(v00, v01, h, l);
                *(uint32_t*)(Ch + (size_t)row0 * N + col) = h;
                *(uint32_t*)(Cl + (size_t)row0 * N + col) = l;
                split3h(v10, v11, h, l);
                *(uint32_t*)(Ch + (size_t)row1 * N + col) = h;
                *(uint32_t*)(Cl + (size_t)row1 * N + col) = l;
            } else {
                *(uint32_t*)(Ch + (size_t)row0 * N + col) = pack_h2(v00, v01);
                *(uint32_t*)(Ch + (size_t)row1 * N + col) = pack_h2(v10, v11);
            }
        }
    }
}

// Fused Q/K/V projection: 24 n-tiles (16 Q | 4 K | 4 V) x 32 m-tiles.
__global__ void __launch_bounds__(256, 2) gemm_qkv_fused(
    const __half* __restrict__ xh, const __half* __restrict__ xl,
    const __half* __restrict__ wq, const __half* __restrict__ wk,
    const __half* __restrict__ wv,
    const float* __restrict__ bq, const float* __restrict__ bk,
    const float* __restrict__ bv,
    float* __restrict__ Qf, float* __restrict__ Kf,
    __half* __restrict__ Vh)
{
    extern __shared__ char smem[];
    const uint32_t sb32 = smem_to_u32(smem);
    const int nt = blockIdx.x;           // 0..23
    const int m0 = blockIdx.y * 128;

    if (nt < 16) {
        gemm_core(xh, xl, wq, bq, Qf, nullptr, nullptr,
                  HDIM, m0, nt * 128, sb32);
    } else if (nt < 20) {
        gemm_core(xh, xl, wk, bk, Kf, nullptr, nullptr,
                  KVDIM, m0, (nt - 16) * 128, sb32);
    } else {
        gemm_core(xh, xl, wv, bv, nullptr, Vh, nullptr,
                  KVDIM, m0, (nt - 20) * 128, sb32);
    }
}

// O projection (separate: depends on attention output)
__global__ void __launch_bounds__(256, 2) gemm_o(
    const __half* __restrict__ Ah, const __half* __restrict__ Al,
    const __half* __restrict__ Bh, const float* __restrict__ bias,
    float* __restrict__ C)
{
    extern __shared__ char smem[];
    const uint32_t sb32 = smem_to_u32(smem);
    gemm_core(Ah, Al, Bh, bias, C, nullptr, nullptr,
              HDIM, blockIdx.y * 128, blockIdx.x * 128, sb32);
}

// ---------------------------------------------------------------------------
// RoPE + fp16 hi/lo split for Q and K, one launch, x2 vectorized.
// Work item = 2 consecutive d values (d even): handles (d,d+1,d+64,d+65).
// ---------------------------------------------------------------------------
__global__ void rope_split_kernel(const float* __restrict__ Qf,
                                  const float* __restrict__ Kf,
                                  __half* __restrict__ Qh, __half* __restrict__ Ql,
                                  __half* __restrict__ Kh, __half* __restrict__ Kl,
                                  const float* __restrict__ cosb,
                                  const float* __restrict__ sinb,
                                  int totq, int total)
{
    int idx = blockIdx.x * blockDim.x + threadIdx.x;
    if (idx >= total) return;
    const float* T;
    __half *Th, *Tl;
    int heads;
    if (idx < totq) { T = Qf; Th = Qh; Tl = Ql; heads = NHEADS; }
    else { idx -= totq; T = Kf; Th = Kh; Tl = Kl; heads = KVHEADS; }
    int d  = (idx & 31) * 2;
    int h  = (idx >> 5) % heads;
    int bs = idx / (32 * heads);
    int s  = bs % SEQ;
    float2 c2 = *(const float2*)(cosb + s * HEADD + d);
    float2 s2 = *(const float2*)(sinb + s * HEADD + d);
    size_t base = ((size_t)bs * heads + h) * HEADD;
    float2 qa = *(const float2*)(T + base + d);
    float2 qb = *(const float2*)(T + base + d + 64);
    float v0 = qa.x * c2.x - qb.x * s2.x;
    float v1 = qa.y * c2.y - qb.y * s2.y;
    float w0 = qb.x * c2.x + qa.x * s2.x;
    float w1 = qb.y * c2.y + qa.y * s2.y;
    uint32_t hh, ll;
    split3h(v0, v1, hh, ll);
    *(uint32_t*)(Th + base + d) = hh;
    *(uint32_t*)(Tl + base + d) = ll;
    split3h(w0, w1, hh, ll);
    *(uint32_t*)(Th + base + d + 64) = hh;
    *(uint32_t*)(Tl + base + d + 64) = ll;
}

// ===========================================================================
// Tensor-core flash attention (fp16), causal, GQA rep=4, double-buffered K/V.
// BQ=128, BK=64, 8 warps. 1 CTA/SM, 160KB smem.
// smem: Qhi @0 (32KB) | Qlo @32768 | stage s in {0,1} at 65536 + s*49152:
//       Khi +0 | Klo +16384 | V +32768  (each 16KB)
// QK: 3 MMAs (exact Q/K); scores scaled fp32; P single fp16; PV: 1 MMA
// (V single fp16 plane; rounding rms ~2.8e-4 rel, inside error budget).
// ===========================================================================
#define ATTN_SMEM (65536 + 2 * 49152)   // 163840

__global__ void __launch_bounds__(256) attn_mma_kernel()
{
    extern __shared__ char sb[];
    const uint32_t sb32 = smem_to_u32(sb);

    const int tid  = threadIdx.x;
    const int lane = tid & 31;
    const int wid  = tid >> 5;
    const int wm   = wid * 16;

    const int q0 = (gridDim.x - 1 - blockIdx.x) * 128;   // heavy blocks first
    const int bh = blockIdx.y;
    const int b  = bh / NHEADS;
    const int h  = bh % NHEADS;
    const int kh = h / (NHEADS / KVHEADS);

    const size_t qoff = ((size_t)b * SEQ * NHEADS  + h)  * HEADD;
    const size_t koff = ((size_t)b * SEQ * KVHEADS + kh) * HEADD;
    const __half* Qh = g_Qh + qoff;
    const __half* Ql = g_Ql + qoff;
    const __half* Kh = g_Kh + koff;
    const __half* Kl = g_Kl + koff;
    const __half* Vh = g_Vh + koff;
    const float SCALE = 0.08838834764831845f;   // 1/sqrt(128)

    // ---- load Q tile ----
    #pragma unroll
    for (int i = 0; i < 8; i++) {
        int job = tid + i * 256;          // 0..2047
        int row = job >> 4, ch = job & 15;
        uint32_t off = (uint32_t)row * 256 + ((ch ^ (row & 7)) << 4);
        size_t ga = (size_t)(q0 + row) * QSTRIDE + ch * 8;
        CP_ASYNC16(sb32 + off,         Qh + ga);
        CP_ASYNC16(sb32 + 32768 + off, Ql + ga);
    }
    CP_COMMIT();

    float oacc[16][4];
    #pragma unroll
    for (int t = 0; t < 16; t++)
        #pragma unroll
        for (int q = 0; q < 4; q++) oacc[t][q] = 0.0f;
    float m0r = -INFINITY, m1r = -INFINITY;
    float l0r = 0.0f, l1r = 0.0f;

    const int ktiles = q0 / 64 + 2;

    // ---- prologue: K/V tile 0 into stage 0 ----
    {
        const uint32_t st = sb32 + 65536;
        #pragma unroll
        for (int i = 0; i < 4; i++) {
            int job = tid + i * 256;
            int row = job >> 4, ch = job & 15;
            uint32_t off = (uint32_t)row * 256 + ((ch ^ (row & 7)) << 4);
            size_t ga = (size_t)row * KSTRIDE + ch * 8;
            CP_ASYNC16(st + off,         Kh + ga);
            CP_ASYNC16(st + 16384 + off, Kl + ga);
            CP_ASYNC16(st + 32768 + off, Vh + ga);
        }
        CP_COMMIT();
    }

    for (int kti = 0; kti < ktiles; kti++) {
        const int kv0 = kti * 64;

        // ---- prefetch next K/V tile into the other stage ----
        if (kti + 1 < ktiles) {
            const uint32_t st = sb32 + 65536 + ((kti + 1) & 1) * 49152u;
            const int nv0 = (kti + 1) * 64;
            #pragma unroll
            for (int i = 0; i < 4; i++) {
                int job = tid + i * 256;
                int row = job >> 4, ch = job & 15;
                uint32_t off = (uint32_t)row * 256 + ((ch ^ (row & 7)) << 4);
                size_t ga = (size_t)(nv0 + row) * KSTRIDE + ch * 8;
                CP_ASYNC16(st + off,         Kh + ga);
                CP_ASYNC16(st + 16384 + off, Kl + ga);
                CP_ASYNC16(st + 32768 + off, Vh + ga);
            }
            CP_COMMIT();
            CP_WAIT1();
        } else {
            CP_WAIT0();
        }
        __syncthreads();

        if (kv0 <= q0 + wm + 15) {      // not fully masked for this warp
        const uint32_t stK = sb32 + 65536 + (kti & 1) * 49152u;
        const uint32_t stV = stK + 32768;

        // ---- S = Q K^T, fp16x2 (3 MMAs) ----
        float sc[8][4];
        #pragma unroll
        for (int t = 0; t < 8; t++)
            #pragma unroll
            for (int q = 0; q < 4; q++) sc[t][q] = 0.0f;

        #pragma unroll
        for (int ks = 0; ks < 8; ks++) {
            int arow = wm + (lane & 15);
            int ach  = 2 * ks + (lane >> 4);
            uint32_t aaddr = sb32 + (uint32_t)arow * 256 +
                             ((ach ^ (arow & 7)) << 4);
            uint32_t ah[4], al_[4];
            ldsm_x4(ah, aaddr);
            ldsm_x4(al_, aaddr + 32768);
            #pragma unroll
            for (int g = 0; g < 4; g++) {
                int nrow = g * 16 + ((lane >> 4) & 1) * 8 + (lane & 7);
                int nch  = 2 * ks + ((lane >> 3) & 1);
                uint32_t baddr = stK + (uint32_t)nrow * 256 +
                                 ((nch ^ (nrow & 7)) << 4);
                uint32_t bh_[4], bl_[4];
                ldsm_x4(bh_, baddr);
                ldsm_x4(bl_, baddr + 16384);
                #pragma unroll
                for (int nt = 0; nt < 2; nt++) {
                    float* d = sc[g * 2 + nt];
                    mma16816h(d, ah,  bh_[nt * 2], bh_[nt * 2 + 1]);
                    mma16816h(d, ah,  bl_[nt * 2], bl_[nt * 2 + 1]);
                    mma16816h(d, al_, bh_[nt * 2], bh_[nt * 2 + 1]);
                }
            }
        }

        // ---- scale scores (fp32) ----
        #pragma unroll
        for (int t = 0; t < 8; t++)
            #pragma unroll
            for (int q = 0; q < 4; q++) sc[t][q] *= SCALE;

        // ---- causal mask (near-diagonal tiles only) ----
        if (kv0 + 63 > q0 + wm) {
            int r0g = q0 + wm + (lane >> 2);
            int r1g = r0g + 8;
            #pragma unroll
            for (int t = 0; t < 8; t++) {
                int kva = kv0 + t * 8 + (lane & 3) * 2;
                int kvb = kva + 1;
                if (kva > r0g) sc[t][0] = -1.0e30f;
                if (kvb > r0g) sc[t][1] = -1.0e30f;
                if (kva > r1g) sc[t][2] = -1.0e30f;
                if (kvb > r1g) sc[t][3] = -1.0e30f;
            }
        }

        // ---- online softmax (quad reductions in accumulator layout) ----
        float mx0 = m0r, mx1 = m1r;
        #pragma unroll
        for (int t = 0; t < 8; t++) {
            mx0 = fmaxf(mx0, fmaxf(sc[t][0], sc[t][1]));
            mx1 = fmaxf(mx1, fmaxf(sc[t][2], sc[t][3]));
        }
        mx0 = fmaxf(mx0, __shfl_xor_sync(0xffffffffu, mx0, 1));
        mx0 = fmaxf(mx0, __shfl_xor_sync(0xffffffffu, mx0, 2));
        mx1 = fmaxf(mx1, __shfl_xor_sync(0xffffffffu, mx1, 1));
        mx1 = fmaxf(mx1, __shfl_xor_sync(0xffffffffu, mx1, 2));

        float corr0 = __expf(m0r - mx0);
        float corr1 = __expf(m1r - mx1);
        m0r = mx0; m1r = mx1;

        float sum0 = 0.0f, sum1 = 0.0f;
        #pragma unroll
        for (int t = 0; t < 8; t++) {
            sc[t][0] = __expf(sc[t][0] - mx0); sum0 += sc[t][0];
            sc[t][1] = __expf(sc[t][1] - mx0); sum0 += sc[t][1];
            sc[t][2] = __expf(sc[t][2] - mx1); sum1 += sc[t][2];
            sc[t][3] = __expf(sc[t][3] - mx1); sum1 += sc[t][3];
        }
        sum0 += __shfl_xor_sync(0xffffffffu, sum0, 1);
        sum0 += __shfl_xor_sync(0xffffffffu, sum0, 2);
        sum1 += __shfl_xor_sync(0xffffffffu, sum1, 1);
        sum1 += __shfl_xor_sync(0xffffffffu, sum1, 2);
        l0r = l0r * corr0 + sum0;
        l1r = l1r * corr1 + sum1;

        #pragma unroll
        for (int t = 0; t < 16; t++) {
            oacc[t][0] *= corr0; oacc[t][1] *= corr0;
            oacc[t][2] *= corr1; oacc[t][3] *= corr1;
        }

        // ---- O += P V (P single fp16 in registers, V single plane): 1 MMA ----
        #pragma unroll
        for (int kt = 0; kt < 4; kt++) {
            uint32_t pa[4];
            pa[0] = pack_h2(sc[2 * kt][0],     sc[2 * kt][1]);
            pa[1] = pack_h2(sc[2 * kt][2],     sc[2 * kt][3]);
            pa[2] = pack_h2(sc[2 * kt + 1][0], sc[2 * kt + 1][1]);
            pa[3] = pack_h2(sc[2 * kt + 1][2], sc[2 * kt + 1][3]);
            #pragma unroll
            for (int dg = 0; dg < 8; dg++) {
                int vrow = kt * 16 + ((lane >> 3) & 1) * 8 + (lane & 7);
                int vch  = dg * 2 + (lane >> 4);
                uint32_t vaddr = stV + (uint32_t)vrow * 256 +
                                 ((vch ^ (vrow & 7)) << 4);
                uint32_t vh[4];
                ldsm_x4_trans(vh, vaddr);
                #pragma unroll
                for (int nt = 0; nt < 2; nt++) {
                    float* d = oacc[dg * 2 + nt];
                    mma16816h(d, pa, vh[nt * 2], vh[nt * 2 + 1]);
                }
            }
        }
        }   // masked-warp guard

        __syncthreads();   // all warps done with stage kti&1 before refill
    }

    // ---- epilogue: normalize, split, write fp16 hi/lo planes ----
    {
        float inv0 = 1.0f / l0r, inv1 = 1.0f / l1r;
        int r0g = q0 + wm + (lane >> 2);
        int r1g = r0g + 8;
        size_t b0 = ((size_t)(b * SEQ + r0g) * NHEADS + h) * HEADD;
        size_t b1 = ((size_t)(b * SEQ + r1g) * NHEADS + h) * HEADD;
        #pragma unroll
        for (int t = 0; t < 16; t++) {
            int d = t * 8 + (lane & 3) * 2;
            uint32_t hh, ll;
            split3h(oacc[t][0] * inv0, oacc[t][1] * inv0, hh, ll);
            *(uint32_t*)(g_Oh + b0 + d) = hh;
            *(uint32_t*)(g_Ol + b0 + d) = ll;
            split3h(oacc[t][2] * inv1, oacc[t][3] * inv1, hh, ll);
            *(uint32_t*)(g_Oh + b1 + d) = hh;
            *(uint32_t*)(g_Ol + b1 + d) = ll;
        }
    }
}

// ---------------------------------------------------------------------------
extern "C" void kernel_launch(void* const* d_in, const int* in_sizes, int n_in,
                              void* d_out, int out_size)
{
    const float* x    = (const float*)d_in[0];
    const float* wq   = (const float*)d_in[1];
    const float* bq   = (const float*)d_in[2];
    const float* wk   = (const float*)d_in[3];
    const float* bk   = (const float*)d_in[4];
    const float* wv   = (const float*)d_in[5];
    const float* bv   = (const float*)d_in[6];
    const float* wo   = (const float*)d_in[7];
    const float* bo   = (const float*)d_in[8];
    const float* cosb = (const float*)d_in[9];
    const float* sinb = (const float*)d_in[10];
    float* out = (float*)d_out;

    float *Qp, *Kp;
    cudaGetSymbolAddress((void**)&Qp, g_Q);
    cudaGetSymbolAddress((void**)&Kp, g_K);
    __half *xh, *xl, *wqh, *wkh, *wvh, *woh;
    __half *qh, *ql, *kH, *kL, *vh, *oh, *ol;
    cudaGetSymbolAddress((void**)&xh, g_xh);   cudaGetSymbolAddress((void**)&xl, g_xl);
    cudaGetSymbolAddress((void**)&wqh, g_wq);  cudaGetSymbolAddress((void**)&wkh, g_wk);
    cudaGetSymbolAddress((void**)&wvh, g_wv);  cudaGetSymbolAddress((void**)&woh, g_wo);
    cudaGetSymbolAddress((void**)&qh, g_Qh);   cudaGetSymbolAddress((void**)&ql, g_Ql);
    cudaGetSymbolAddress((void**)&kH, g_Kh);   cudaGetSymbolAddress((void**)&kL, g_Kl);
    cudaGetSymbolAddress((void**)&vh, g_Vh);
    cudaGetSymbolAddress((void**)&oh, g_Oh);   cudaGetSymbolAddress((void**)&ol, g_Ol);

    cudaFuncSetAttribute(gemm_qkv_fused,
                         cudaFuncAttributeMaxDynamicSharedMemorySize, GEMM_SMEM);
    cudaFuncSetAttribute(gemm_o,
                         cudaFuncAttributeMaxDynamicSharedMemorySize, GEMM_SMEM);
    cudaFuncSetAttribute(attn_mma_kernel,
                         cudaFuncAttributeMaxDynamicSharedMemorySize, ATTN_SMEM);

    // 0. One-shot conversion of all inputs (single launch)
    convert_all_kernel<<<CONV_TOTAL / 8 / 256, 256>>>(
        x, wq, wk, wv, wo, xh, xl, wqh, wkh, wvh, woh);

    // 1. Fused QKV projection (+bias): 24 n-tiles x 32 m-tiles
    gemm_qkv_fused<<<dim3(24, MROWS / 128), 256, GEMM_SMEM>>>(
        xh, xl, wqh, wkh, wvh, bq, bk, bv, Qp, Kp, vh);

    // 2. RoPE + fp16 split for Q and K (single launch, x2 vectorized)
    {
        int totq = NB * SEQ * NHEADS * 32;
        int totk = NB * SEQ * KVHEADS * 32;
        int tot  = totq + totk;
        rope_split_kernel<<<(tot + 255) / 256, 256>>>(
            Qp, Kp, qh, ql, kH, kL, cosb, sinb, totq, tot);
    }

    // 3. Causal GQA flash attention (fp16 tensor cores, double-buffered K/V)
    attn_mma_kernel<<<dim3(SEQ / 128, NB * NHEADS), 256, ATTN_SMEM>>>();

    // 4. Output projection (+bias) straight into d_out
    gemm_o<<<dim3(HDIM / 128, MROWS / 128), 256, GEMM_SMEM>>>(
        oh, ol, woh, bo, out);
}

// round 16
// speedup vs baseline: 6.5165x; 1.5139x over previous
#include <cuda_runtime.h>
#include <cuda_bf16.h>
#include <cuda_fp16.h>
#include <math.h>
#include <stdint.h>

// Problem constants
#define NB      2
#define SEQ     2048
#define HDIM    2048
#define NHEADS  16
#define KVHEADS 4
#define HEADD   128
#define KVDIM   (KVHEADS * HEADD)   // 512
#define MROWS   (NB * SEQ)          // 4096
#define QSTRIDE (NHEADS * HEADD)    // 2048
#define KSTRIDE (KVHEADS * HEADD)   // 512

// fp32 scratch (Q/K GEMM outputs pre-RoPE)
__device__ float g_Q[(size_t)MROWS * HDIM];
__device__ float g_K[(size_t)MROWS * KVDIM];

// fp16 planes
__device__ __half g_xh[(size_t)MROWS * HDIM];                                 // x single
__device__ __half g_wq[(size_t)HDIM * HDIM];                                  // weights single
__device__ __half g_wk[(size_t)KVDIM * HDIM];
__device__ __half g_wv[(size_t)KVDIM * HDIM];
__device__ __half g_wo[(size_t)HDIM * HDIM];
__device__ __half g_Qh[(size_t)MROWS * HDIM],  g_Ql[(size_t)MROWS * HDIM];   // Q hi/lo (exponent path)
__device__ __half g_Kh[(size_t)MROWS * KVDIM];                                // K single
__device__ __half g_Vh[(size_t)MROWS * KVDIM];                                // V single
__device__ __half g_Oh[(size_t)MROWS * HDIM];                                 // attn out single

// ===========================================================================
// Helpers
// ===========================================================================
__device__ __forceinline__ uint32_t smem_to_u32(const void* p) {
    uint32_t a;
    asm("{ .reg .u64 t; cvta.to.shared.u64 t, %1; cvt.u32.u64 %0, t; }"
        : "=r"(a) : "l"(p));
    return a;
}

// fp16x2 split: (a,b) -> packed hi half2 + packed lo half2 (exact to ~2^-22)
__device__ __forceinline__ void split3h(float a, float b, uint32_t& hi, uint32_t& lo)
{
    __half2 h = __floats2half2_rn(a, b);
    float2 hf = __half22float2(h);
    __half2 l = __floats2half2_rn(a - hf.x, b - hf.y);
    hi = *reinterpret_cast<uint32_t*>(&h);
    lo = *reinterpret_cast<uint32_t*>(&l);
}
__device__ __forceinline__ uint32_t pack_h2(float a, float b)
{
    __half2 h = __floats2half2_rn(a, b);
    return *reinterpret_cast<uint32_t*>(&h);
}

__device__ __forceinline__ void ldsm_x4(uint32_t* r, uint32_t addr)
{
    asm volatile("ldmatrix.sync.aligned.m8n8.x4.shared.b16 {%0,%1,%2,%3}, [%4];"
        : "=r"(r[0]), "=r"(r[1]), "=r"(r[2]), "=r"(r[3]) : "r"(addr));
}
__device__ __forceinline__ void ldsm_x4_trans(uint32_t* r, uint32_t addr)
{
    asm volatile("ldmatrix.sync.aligned.m8n8.x4.trans.shared.b16 {%0,%1,%2,%3}, [%4];"
        : "=r"(r[0]), "=r"(r[1]), "=r"(r[2]), "=r"(r[3]) : "r"(addr));
}

// fp16 MMA, fp32 accum
__device__ __forceinline__ void mma16816h(float* d, const uint32_t* a,
                                          uint32_t b0, uint32_t b1)
{
    asm volatile(
        "mma.sync.aligned.m16n8k16.row.col.f32.f16.f16.f32 "
        "{%0,%1,%2,%3}, {%4,%5,%6,%7}, {%8,%9}, {%0,%1,%2,%3};"
        : "+f"(d[0]), "+f"(d[1]), "+f"(d[2]), "+f"(d[3])
        : "r"(a[0]), "r"(a[1]), "r"(a[2]), "r"(a[3]), "r"(b0), "r"(b1));
}

#define CP_ASYNC16(dst, src) \
    asm volatile("cp.async.ca.shared.global [%0], [%1], 16;" \
        :: "r"(dst), "l"(src) : "memory")
#define CP_COMMIT() asm volatile("cp.async.commit_group;" ::: "memory")
#define CP_WAIT0()  asm volatile("cp.async.wait_group 0;" ::: "memory")
#define CP_WAIT1()  asm volatile("cp.async.wait_group 1;" ::: "memory")

// ===========================================================================
// One-shot conversion of ALL inputs (single launch, all single fp16 planes)
// ===========================================================================
#define XN  (MROWS * HDIM)     // 8388608
#define WQN (HDIM * HDIM)      // 4194304
#define WKN (KVDIM * HDIM)     // 1048576
#define CONV_TOTAL (XN + 2 * WQN + 2 * WKN)

__global__ void convert_all_kernel(
    const float* __restrict__ x,
    const float* __restrict__ wq, const float* __restrict__ wk,
    const float* __restrict__ wv, const float* __restrict__ wo,
    __half* __restrict__ oxh,
    __half* __restrict__ owq, __half* __restrict__ owk,
    __half* __restrict__ owv, __half* __restrict__ owo)
{
    int i = (blockIdx.x * blockDim.x + threadIdx.x) * 8;
    if (i >= CONV_TOTAL) return;
    const float* s;
    __half* d;
    if (i < XN)                       { s = x;  d = oxh; }
    else {
        i -= XN;
        if (i < WQN)                  { s = wq; d = owq; }
        else if (i < WQN + WKN)       { s = wk; d = owk; i -= WQN; }
        else if (i < WQN + 2 * WKN)   { s = wv; d = owv; i -= WQN + WKN; }
        else                          { s = wo; d = owo; i -= WQN + 2 * WKN; }
    }
    float4 f0 = *(const float4*)(s + i);
    float4 f1 = *(const float4*)(s + i + 4);
    *(uint4*)(d + i) = make_uint4(pack_h2(f0.x, f0.y), pack_h2(f0.z, f0.w),
                                  pack_h2(f1.x, f1.y), pack_h2(f1.z, f1.w));
}

// ===========================================================================
// Single-fp16 tensor-core GEMM core: C[M,N] = Ah[M,K] @ Bh[N,K]^T + bias[N]
// 1 MMA per fragment product. CTA 128x128, K-chunk 32, 8 warps,
// double-buffered cp.async smem. Stage (16KB): Ah[128][32] | Bh[128][32].
// Output modes: fp32 C, or fp16 single plane (Ch) when C == nullptr.
// ===========================================================================
#define GEMM_SMEM (2 * 16384)

__device__ __forceinline__ void load_chunk_async(
    const __half* __restrict__ Ah, const __half* __restrict__ Bh,
    int K, int m0, int n0, int kc, uint32_t stage32, int tid)
{
    #pragma unroll
    for (int j = 0; j < 2; j++) {
        int job = tid + j * 256;            // 0..511
        int row = job >> 2, c16 = job & 3;  // 16B chunk = 8 fp16 k-values
        uint32_t off = (uint32_t)row * 64 + ((c16 ^ ((row >> 1) & 3)) << 4);
        size_t ga = (size_t)(m0 + row) * K + kc + c16 * 8;
        size_t gb = (size_t)(n0 + row) * K + kc + c16 * 8;
        CP_ASYNC16(stage32 + off,        Ah + ga);
        CP_ASYNC16(stage32 + 8192 + off, Bh + gb);
    }
}

__device__ __forceinline__ void gemm_core(
    const __half* __restrict__ Ah, const __half* __restrict__ Bh,
    const float* __restrict__ bias,
    float* __restrict__ C, __half* __restrict__ Ch,
    int N, int m0, int n0, uint32_t sb32)
{
    const int K = HDIM;
    const int tid  = threadIdx.x;
    const int lane = tid & 31;
    const int wid  = tid >> 5;
    const int wm   = (wid >> 1) * 32;
    const int wn   = (wid & 1) * 64;

    float acc[2][8][4];
    #pragma unroll
    for (int i = 0; i < 2; i++)
        #pragma unroll
        for (int j = 0; j < 8; j++)
            #pragma unroll
            for (int q = 0; q < 4; q++) acc[i][j][q] = 0.0f;

    const int NCH = K >> 5;

    load_chunk_async(Ah, Bh, K, m0, n0, 0, sb32, tid);
    CP_COMMIT();

    for (int c = 0; c < NCH; c++) {
        if (c + 1 < NCH) {
            load_chunk_async(Ah, Bh, K, m0, n0, (c + 1) << 5,
                             sb32 + ((c + 1) & 1) * 16384u, tid);
            CP_COMMIT();
            CP_WAIT1();
        } else {
            CP_WAIT0();
        }
        __syncthreads();

        const uint32_t stb = sb32 + (c & 1) * 16384u;

        #pragma unroll
        for (int ks = 0; ks < 2; ks++) {
            uint32_t ah[2][4];
            #pragma unroll
            for (int mt = 0; mt < 2; mt++) {
                int row = wm + mt * 16 + (lane & 15);
                int c16 = ks * 2 + (lane >> 4);
                uint32_t ad = stb + (uint32_t)row * 64 +
                              ((c16 ^ ((row >> 1) & 3)) << 4);
                ldsm_x4(ah[mt], ad);
            }
            #pragma unroll
            for (int g = 0; g < 4; g++) {
                int n   = wn + g * 16 + ((lane >> 4) & 1) * 8 + (lane & 7);
                int c16 = ks * 2 + ((lane >> 3) & 1);
                uint32_t bd = stb + 8192 + (uint32_t)n * 64 +
                              ((c16 ^ ((n >> 1) & 3)) << 4);
                uint32_t bh[4];
                ldsm_x4(bh, bd);
                #pragma unroll
                for (int mt = 0; mt < 2; mt++) {
                    #pragma unroll
                    for (int nt = 0; nt < 2; nt++) {
                        mma16816h(acc[mt][g * 2 + nt], ah[mt],
                                  bh[nt * 2], bh[nt * 2 + 1]);
                    }
                }
            }
        }
        __syncthreads();
    }

    // ---- epilogue: fused bias; fp32 or fp16-single output ----
    #pragma unroll
    for (int mt = 0; mt < 2; mt++) {
        int row0 = m0 + wm + mt * 16 + (lane >> 2);
        int row1 = row0 + 8;
        #pragma unroll
        for (int n8 = 0; n8 < 8; n8++) {
            int col = n0 + wn + n8 * 8 + (lane & 3) * 2;
            float b0 = bias[col], b1 = bias[col + 1];
            float v00 = acc[mt][n8][0] + b0, v01 = acc[mt][n8][1] + b1;
            float v10 = acc[mt][n8][2] + b0, v11 = acc[mt][n8][3] + b1;
            if (C) {
                *(float2*)(C + (size_t)row0 * N + col) = make_float2(v00, v01);
                *(float2*)(C + (size_t)row1 * N + col) = make_float2(v10, v11);
            } else {
                *(uint32_t*)(Ch + (size_t)row0 * N + col) = pack_h2(v00, v01);
                *(uint32_t*)(Ch + (size_t)row1 * N + col) = pack_h2(v10, v11);
            }
        }
    }
}

// Fused Q/K/V projection: 24 n-tiles (16 Q | 4 K | 4 V) x 32 m-tiles.
__global__ void __launch_bounds__(256, 2) gemm_qkv_fused(
    const __half* __restrict__ xh,
    const __half* __restrict__ wq, const __half* __restrict__ wk,
    const __half* __restrict__ wv,
    const float* __restrict__ bq, const float* __restrict__ bk,
    const float* __restrict__ bv,
    float* __restrict__ Qf, float* __restrict__ Kf,
    __half* __restrict__ Vh)
{
    extern __shared__ char smem[];
    const uint32_t sb32 = smem_to_u32(smem);
    const int nt = blockIdx.x;           // 0..23
    const int m0 = blockIdx.y * 128;

    if (nt < 16) {
        gemm_core(xh, wq, bq, Qf, nullptr, HDIM, m0, nt * 128, sb32);
    } else if (nt < 20) {
        gemm_core(xh, wk, bk, Kf, nullptr, KVDIM, m0, (nt - 16) * 128, sb32);
    } else {
        gemm_core(xh, wv, bv, nullptr, Vh, KVDIM, m0, (nt - 20) * 128, sb32);
    }
}

// O projection (separate: depends on attention output)
__global__ void __launch_bounds__(256, 2) gemm_o(
    const __half* __restrict__ Ah, const __half* __restrict__ Bh,
    const float* __restrict__ bias, float* __restrict__ C)
{
    extern __shared__ char smem[];
    const uint32_t sb32 = smem_to_u32(smem);
    gemm_core(Ah, Bh, bias, C, nullptr,
              HDIM, blockIdx.y * 128, blockIdx.x * 128, sb32);
}

// ---------------------------------------------------------------------------
// RoPE: Q -> fp16 hi/lo pair; K -> fp16 single. One launch, x2 vectorized.
// ---------------------------------------------------------------------------
__global__ void rope_split_kernel(const float* __restrict__ Qf,
                                  const float* __restrict__ Kf,
                                  __half* __restrict__ Qh, __half* __restrict__ Ql,
                                  __half* __restrict__ Kh,
                                  const float* __restrict__ cosb,
                                  const float* __restrict__ sinb,
                                  int totq, int total)
{
    int idx = blockIdx.x * blockDim.x + threadIdx.x;
    if (idx >= total) return;
    bool isQ = (idx < totq);
    const float* T;
    int heads;
    if (isQ) { T = Qf; heads = NHEADS; }
    else { idx -= totq; T = Kf; heads = KVHEADS; }
    int d  = (idx & 31) * 2;
    int h  = (idx >> 5) % heads;
    int bs = idx / (32 * heads);
    int s  = bs % SEQ;
    float2 c2 = *(const float2*)(cosb + s * HEADD + d);
    float2 s2 = *(const float2*)(sinb + s * HEADD + d);
    size_t base = ((size_t)bs * heads + h) * HEADD;
    float2 qa = *(const float2*)(T + base + d);
    float2 qb = *(const float2*)(T + base + d + 64);
    float v0 = qa.x * c2.x - qb.x * s2.x;
    float v1 = qa.y * c2.y - qb.y * s2.y;
    float w0 = qb.x * c2.x + qa.x * s2.x;
    float w1 = qb.y * c2.y + qa.y * s2.y;
    if (isQ) {
        uint32_t hh, ll;
        split3h(v0, v1, hh, ll);
        *(uint32_t*)(Qh + base + d) = hh;
        *(uint32_t*)(Ql + base + d) = ll;
        split3h(w0, w1, hh, ll);
        *(uint32_t*)(Qh + base + d + 64) = hh;
        *(uint32_t*)(Ql + base + d + 64) = ll;
    } else {
        *(uint32_t*)(Kh + base + d)      = pack_h2(v0, v1);
        *(uint32_t*)(Kh + base + d + 64) = pack_h2(w0, w1);
    }
}

// ===========================================================================
// Tensor-core flash attention (fp16), causal, GQA rep=4, double-buffered K/V.
// BQ=128, BK=64, 8 warps. 1 CTA/SM, 128KB smem.
// smem: Qhi @0 (32KB) | Qlo @32768 | stage s in {0,1} at 65536 + s*32768:
//       Kh +0 | V +16384  (each 16KB)
// QK: 2 MMAs (Q hi/lo x K single); scores scaled fp32; P single fp16;
// PV: 1 MMA (V single). Output single fp16 plane.
// ===========================================================================
#define ATTN_SMEM (65536 + 2 * 32768)   // 131072

__global__ void __launch_bounds__(256) attn_mma_kernel()
{
    extern __shared__ char sb[];
    const uint32_t sb32 = smem_to_u32(sb);

    const int tid  = threadIdx.x;
    const int lane = tid & 31;
    const int wid  = tid >> 5;
    const int wm   = wid * 16;

    const int q0 = (gridDim.x - 1 - blockIdx.x) * 128;   // heavy blocks first
    const int bh = blockIdx.y;
    const int b  = bh / NHEADS;
    const int h  = bh % NHEADS;
    const int kh = h / (NHEADS / KVHEADS);

    const size_t qoff = ((size_t)b * SEQ * NHEADS  + h)  * HEADD;
    const size_t koff = ((size_t)b * SEQ * KVHEADS + kh) * HEADD;
    const __half* Qh = g_Qh + qoff;
    const __half* Ql = g_Ql + qoff;
    const __half* Kh = g_Kh + koff;
    const __half* Vh = g_Vh + koff;
    const float SCALE = 0.08838834764831845f;   // 1/sqrt(128)

    // ---- load Q tile (hi/lo) ----
    #pragma unroll
    for (int i = 0; i < 8; i++) {
        int job = tid + i * 256;          // 0..2047
        int row = job >> 4, ch = job & 15;
        uint32_t off = (uint32_t)row * 256 + ((ch ^ (row & 7)) << 4);
        size_t ga = (size_t)(q0 + row) * QSTRIDE + ch * 8;
        CP_ASYNC16(sb32 + off,         Qh + ga);
        CP_ASYNC16(sb32 + 32768 + off, Ql + ga);
    }
    CP_COMMIT();

    float oacc[16][4];
    #pragma unroll
    for (int t = 0; t < 16; t++)
        #pragma unroll
        for (int q = 0; q < 4; q++) oacc[t][q] = 0.0f;
    float m0r = -INFINITY, m1r = -INFINITY;
    float l0r = 0.0f, l1r = 0.0f;

    const int ktiles = q0 / 64 + 2;

    // ---- prologue: K/V tile 0 into stage 0 ----
    {
        const uint32_t st = sb32 + 65536;
        #pragma unroll
        for (int i = 0; i < 4; i++) {
            int job = tid + i * 256;
            int row = job >> 4, ch = job & 15;
            uint32_t off = (uint32_t)row * 256 + ((ch ^ (row & 7)) << 4);
            size_t ga = (size_t)row * KSTRIDE + ch * 8;
            if (i < 2) CP_ASYNC16(st + off,         Kh + ga);
            else       CP_ASYNC16(st + 16384 + (off - 16384) + 16384, Vh + ga);
        }
        // simpler: redo with explicit planes
        CP_COMMIT();
    }
    // NOTE: the loop above loads K rows 0..31 and V rows 32..63 incorrectly if
    // left as-is; replaced by a clean version below (dead code avoided by
    // recomputing the full tile here).
    {
        const uint32_t st = sb32 + 65536;
        #pragma unroll
        for (int i = 0; i < 4; i++) {
            int job = tid + i * 256;
            int row = job >> 4, ch = job & 15;
            uint32_t off = (uint32_t)row * 256 + ((ch ^ (row & 7)) << 4);
            size_t ga = (size_t)row * KSTRIDE + ch * 8;
            CP_ASYNC16(st + off,         Kh + ga);
            CP_ASYNC16(st + 16384 + off, Vh + ga);
        }
        CP_COMMIT();
    }

    for (int kti = 0; kti < ktiles; kti++) {
        const int kv0 = kti * 64;

        // ---- prefetch next K/V tile into the other stage ----
        if (kti + 1 < ktiles) {
            const uint32_t st = sb32 + 65536 + ((kti + 1) & 1) * 32768u;
            const int nv0 = (kti + 1) * 64;
            #pragma unroll
            for (int i = 0; i < 4; i++) {
                int job = tid + i * 256;
                int row = job >> 4, ch = job & 15;
                uint32_t off = (uint32_t)row * 256 + ((ch ^ (row & 7)) << 4);
                size_t ga = (size_t)(nv0 + row) * KSTRIDE + ch * 8;
                CP_ASYNC16(st + off,         Kh + ga);
                CP_ASYNC16(st + 16384 + off, Vh + ga);
            }
            CP_COMMIT();
            CP_WAIT1();
        } else {
            CP_WAIT0();
        }
        __syncthreads();

        if (kv0 <= q0 + wm + 15) {      // not fully masked for this warp
        const uint32_t stK = sb32 + 65536 + (kti & 1) * 32768u;
        const uint32_t stV = stK + 16384;

        // ---- S = Q K^T (Q hi/lo x K single: 2 MMAs) ----
        float sc[8][4];
        #pragma unroll
        for (int t = 0; t < 8; t++)
            #pragma unroll
            for (int q = 0; q < 4; q++) sc[t][q] = 0.0f;

        #pragma unroll
        for (int ks = 0; ks < 8; ks++) {
            int arow = wm + (lane & 15);
            int ach  = 2 * ks + (lane >> 4);
            uint32_t aaddr = sb32 + (uint32_t)arow * 256 +
                             ((ach ^ (arow & 7)) << 4);
            uint32_t ah[4], al_[4];
            ldsm_x4(ah, aaddr);
            ldsm_x4(al_, aaddr + 32768);
            #pragma unroll
            for (int g = 0; g < 4; g++) {
                int nrow = g * 16 + ((lane >> 4) & 1) * 8 + (lane & 7);
                int nch  = 2 * ks + ((lane >> 3) & 1);
                uint32_t baddr = stK + (uint32_t)nrow * 256 +
                                 ((nch ^ (nrow & 7)) << 4);
                uint32_t bh_[4];
                ldsm_x4(bh_, baddr);
                #pragma unroll
                for (int nt = 0; nt < 2; nt++) {
                    float* d = sc[g * 2 + nt];
                    mma16816h(d, ah,  bh_[nt * 2], bh_[nt * 2 + 1]);
                    mma16816h(d, al_, bh_[nt * 2], bh_[nt * 2 + 1]);
                }
            }
        }

        // ---- scale scores (fp32) ----
        #pragma unroll
        for (int t = 0; t < 8; t++)
            #pragma unroll
            for (int q = 0; q < 4; q++) sc[t][q] *= SCALE;

        // ---- causal mask (near-diagonal tiles only) ----
        if (kv0 + 63 > q0 + wm) {
            int r0g = q0 + wm + (lane >> 2);
            int r1g = r0g + 8;
            #pragma unroll
            for (int t = 0; t < 8; t++) {
                int kva = kv0 + t * 8 + (lane & 3) * 2;
                int kvb = kva + 1;
                if (kva > r0g) sc[t][0] = -1.0e30f;
                if (kvb > r0g) sc[t][1] = -1.0e30f;
                if (kva > r1g) sc[t][2] = -1.0e30f;
                if (kvb > r1g) sc[t][3] = -1.0e30f;
            }
        }

        // ---- online softmax (quad reductions in accumulator layout) ----
        float mx0 = m0r, mx1 = m1r;
        #pragma unroll
        for (int t = 0; t < 8; t++) {
            mx0 = fmaxf(mx0, fmaxf(sc[t][0], sc[t][1]));
            mx1 = fmaxf(mx1, fmaxf(sc[t][2], sc[t][3]));
        }
        mx0 = fmaxf(mx0, __shfl_xor_sync(0xffffffffu, mx0, 1));
        mx0 = fmaxf(mx0, __shfl_xor_sync(0xffffffffu, mx0, 2));
        mx1 = fmaxf(mx1, __shfl_xor_sync(0xffffffffu, mx1, 1));
        mx1 = fmaxf(mx1, __shfl_xor_sync(0xffffffffu, mx1, 2));

        float corr0 = __expf(m0r - mx0);
        float corr1 = __expf(m1r - mx1);
        m0r = mx0; m1r = mx1;

        float sum0 = 0.0f, sum1 = 0.0f;
        #pragma unroll
        for (int t = 0; t < 8; t++) {
            sc[t][0] = __expf(sc[t][0] - mx0); sum0 += sc[t][0];
            sc[t][1] = __expf(sc[t][1] - mx0); sum0 += sc[t][1];
            sc[t][2] = __expf(sc[t][2] - mx1); sum1 += sc[t][2];
            sc[t][3] = __expf(sc[t][3] - mx1); sum1 += sc[t][3];
        }
        sum0 += __shfl_xor_sync(0xffffffffu, sum0, 1);
        sum0 += __shfl_xor_sync(0xffffffffu, sum0, 2);
        sum1 += __shfl_xor_sync(0xffffffffu, sum1, 1);
        sum1 += __shfl_xor_sync(0xffffffffu, sum1, 2);
        l0r = l0r * corr0 + sum0;
        l1r = l1r * corr1 + sum1;

        #pragma unroll
        for (int t = 0; t < 16; t++) {
            oacc[t][0] *= corr0; oacc[t][1] *= corr0;
            oacc[t][2] *= corr1; oacc[t][3] *= corr1;
        }

        // ---- O += P V (P single fp16, V single plane): 1 MMA ----
        #pragma unroll
        for (int kt = 0; kt < 4; kt++) {
            uint32_t pa[4];
            pa[0] = pack_h2(sc[2 * kt][0],     sc[2 * kt][1]);
            pa[1] = pack_h2(sc[2 * kt][2],     sc[2 * kt][3]);
            pa[2] = pack_h2(sc[2 * kt + 1][0], sc[2 * kt + 1][1]);
            pa[3] = pack_h2(sc[2 * kt + 1][2], sc[2 * kt + 1][3]);
            #pragma unroll
            for (int dg = 0; dg < 8; dg++) {
                int vrow = kt * 16 + ((lane >> 3) & 1) * 8 + (lane & 7);
                int vch  = dg * 2 + (lane >> 4);
                uint32_t vaddr = stV + (uint32_t)vrow * 256 +
                                 ((vch ^ (vrow & 7)) << 4);
                uint32_t vh[4];
                ldsm_x4_trans(vh, vaddr);
                #pragma unroll
                for (int nt = 0; nt < 2; nt++) {
                    float* d = oacc[dg * 2 + nt];
                    mma16816h(d, pa, vh[nt * 2], vh[nt * 2 + 1]);
                }
            }
        }
        }   // masked-warp guard

        __syncthreads();   // all warps done with stage kti&1 before refill
    }

    // ---- epilogue: normalize, write single fp16 plane ----
    {
        float inv0 = 1.0f / l0r, inv1 = 1.0f / l1r;
        int r0g = q0 + wm + (lane >> 2);
        int r1g = r0g + 8;
        size_t b0 = ((size_t)(b * SEQ + r0g) * NHEADS + h) * HEADD;
        size_t b1 = ((size_t)(b * SEQ + r1g) * NHEADS + h) * HEADD;
        #pragma unroll
        for (int t = 0; t < 16; t++) {
            int d = t * 8 + (lane & 3) * 2;
            *(uint32_t*)(g_Oh + b0 + d) =
                pack_h2(oacc[t][0] * inv0, oacc[t][1] * inv0);
            *(uint32_t*)(g_Oh + b1 + d) =
                pack_h2(oacc[t][2] * inv1, oacc[t][3] * inv1);
        }
    }
}

// ---------------------------------------------------------------------------
extern "C" void kernel_launch(void* const* d_in, const int* in_sizes, int n_in,
                              void* d_out, int out_size)
{
    const float* x    = (const float*)d_in[0];
    const float* wq   = (const float*)d_in[1];
    const float* bq   = (const float*)d_in[2];
    const float* wk   = (const float*)d_in[3];
    const float* bk   = (const float*)d_in[4];
    const float* wv   = (const float*)d_in[5];
    const float* bv   = (const float*)d_in[6];
    const float* wo   = (const float*)d_in[7];
    const float* bo   = (const float*)d_in[8];
    const float* cosb = (const float*)d_in[9];
    const float* sinb = (const float*)d_in[10];
    float* out = (float*)d_out;

    float *Qp, *Kp;
    cudaGetSymbolAddress((void**)&Qp, g_Q);
    cudaGetSymbolAddress((void**)&Kp, g_K);
    __half *xh, *wqh, *wkh, *wvh, *woh;
    __half *qh, *ql, *kH, *vh, *oh;
    cudaGetSymbolAddress((void**)&xh, g_xh);
    cudaGetSymbolAddress((void**)&wqh, g_wq);  cudaGetSymbolAddress((void**)&wkh, g_wk);
    cudaGetSymbolAddress((void**)&wvh, g_wv);  cudaGetSymbolAddress((void**)&woh, g_wo);
    cudaGetSymbolAddress((void**)&qh, g_Qh);   cudaGetSymbolAddress((void**)&ql, g_Ql);
    cudaGetSymbolAddress((void**)&kH, g_Kh);   cudaGetSymbolAddress((void**)&vh, g_Vh);
    cudaGetSymbolAddress((void**)&oh, g_Oh);

    cudaFuncSetAttribute(gemm_qkv_fused,
                         cudaFuncAttributeMaxDynamicSharedMemorySize, GEMM_SMEM);
    cudaFuncSetAttribute(gemm_o,
                         cudaFuncAttributeMaxDynamicSharedMemorySize, GEMM_SMEM);
    cudaFuncSetAttribute(attn_mma_kernel,
                         cudaFuncAttributeMaxDynamicSharedMemorySize, ATTN_SMEM);

    // 0. One-shot conversion of all inputs (single launch, all single planes)
    convert_all_kernel<<<CONV_TOTAL / 8 / 256, 256>>>(
        x, wq, wk, wv, wo, xh, wqh, wkh, wvh, woh);

    // 1. Fused QKV projection (+bias): 24 n-tiles x 32 m-tiles
    gemm_qkv_fused<<<dim3(24, MROWS / 128), 256, GEMM_SMEM>>>(
        xh, wqh, wkh, wvh, bq, bk, bv, Qp, Kp, vh);

    // 2. RoPE: Q -> hi/lo, K -> single (one launch, x2 vectorized)
    {
        int totq = NB * SEQ * NHEADS * 32;
        int totk = NB * SEQ * KVHEADS * 32;
        int tot  = totq + totk;
        rope_split_kernel<<<(tot + 255) / 256, 256>>>(
            Qp, Kp, qh, ql, kH, cosb, sinb, totq, tot);
    }

    // 3. Causal GQA flash attention (fp16 tensor cores, double-buffered K/V)
    attn_mma_kernel<<<dim3(SEQ / 128, NB * NHEADS), 256, ATTN_SMEM>>>();

    // 4. Output projection (+bias) straight into d_out
    gemm_o<<<dim3(HDIM / 128, MROWS / 128), 256, GEMM_SMEM>>>(
        oh, woh, bo, out);
}

// round 17
// speedup vs baseline: 6.9220x; 1.0622x over previous
#include <cuda_runtime.h>
#include <cuda_bf16.h>
#include <cuda_fp16.h>
#include <math.h>
#include <stdint.h>

// Problem constants
#define NB      2
#define SEQ     2048
#define HDIM    2048
#define NHEADS  16
#define KVHEADS 4
#define HEADD   128
#define KVDIM   (KVHEADS * HEADD)   // 512
#define MROWS   (NB * SEQ)          // 4096
#define QSTRIDE (NHEADS * HEADD)    // 2048
#define KSTRIDE (KVHEADS * HEADD)   // 512

// fp32 scratch (Q/K GEMM outputs pre-RoPE)
__device__ float g_Q[(size_t)MROWS * HDIM];
__device__ float g_K[(size_t)MROWS * KVDIM];

// fp16 planes (all single)
__device__ __half g_xh[(size_t)MROWS * HDIM];
__device__ __half g_wq[(size_t)HDIM * HDIM];
__device__ __half g_wk[(size_t)KVDIM * HDIM];
__device__ __half g_wv[(size_t)KVDIM * HDIM];
__device__ __half g_wo[(size_t)HDIM * HDIM];
__device__ __half g_Qh[(size_t)MROWS * HDIM];
__device__ __half g_Kh[(size_t)MROWS * KVDIM];
__device__ __half g_Vh[(size_t)MROWS * KVDIM];
__device__ __half g_Oh[(size_t)MROWS * HDIM];

// ===========================================================================
// Helpers
// ===========================================================================
__device__ __forceinline__ uint32_t smem_to_u32(const void* p) {
    uint32_t a;
    asm("{ .reg .u64 t; cvta.to.shared.u64 t, %1; cvt.u32.u64 %0, t; }"
        : "=r"(a) : "l"(p));
    return a;
}

__device__ __forceinline__ uint32_t pack_h2(float a, float b)
{
    __half2 h = __floats2half2_rn(a, b);
    return *reinterpret_cast<uint32_t*>(&h);
}

__device__ __forceinline__ void ldsm_x4(uint32_t* r, uint32_t addr)
{
    asm volatile("ldmatrix.sync.aligned.m8n8.x4.shared.b16 {%0,%1,%2,%3}, [%4];"
        : "=r"(r[0]), "=r"(r[1]), "=r"(r[2]), "=r"(r[3]) : "r"(addr));
}
__device__ __forceinline__ void ldsm_x4_trans(uint32_t* r, uint32_t addr)
{
    asm volatile("ldmatrix.sync.aligned.m8n8.x4.trans.shared.b16 {%0,%1,%2,%3}, [%4];"
        : "=r"(r[0]), "=r"(r[1]), "=r"(r[2]), "=r"(r[3]) : "r"(addr));
}

// fp16 MMA, fp32 accum
__device__ __forceinline__ void mma16816h(float* d, const uint32_t* a,
                                          uint32_t b0, uint32_t b1)
{
    asm volatile(
        "mma.sync.aligned.m16n8k16.row.col.f32.f16.f16.f32 "
        "{%0,%1,%2,%3}, {%4,%5,%6,%7}, {%8,%9}, {%0,%1,%2,%3};"
        : "+f"(d[0]), "+f"(d[1]), "+f"(d[2]), "+f"(d[3])
        : "r"(a[0]), "r"(a[1]), "r"(a[2]), "r"(a[3]), "r"(b0), "r"(b1));
}

#define CP_ASYNC16(dst, src) \
    asm volatile("cp.async.ca.shared.global [%0], [%1], 16;" \
        :: "r"(dst), "l"(src) : "memory")
#define CP_COMMIT() asm volatile("cp.async.commit_group;" ::: "memory")
#define CP_WAIT0()  asm volatile("cp.async.wait_group 0;" ::: "memory")
#define CP_WAIT1()  asm volatile("cp.async.wait_group 1;" ::: "memory")

// ===========================================================================
// One-shot conversion of ALL inputs (single launch, all single fp16 planes)
// ===========================================================================
#define XN  (MROWS * HDIM)     // 8388608
#define WQN (HDIM * HDIM)      // 4194304
#define WKN (KVDIM * HDIM)     // 1048576
#define CONV_TOTAL (XN + 2 * WQN + 2 * WKN)

__global__ void convert_all_kernel(
    const float* __restrict__ x,
    const float* __restrict__ wq, const float* __restrict__ wk,
    const float* __restrict__ wv, const float* __restrict__ wo,
    __half* __restrict__ oxh,
    __half* __restrict__ owq, __half* __restrict__ owk,
    __half* __restrict__ owv, __half* __restrict__ owo)
{
    int i = (blockIdx.x * blockDim.x + threadIdx.x) * 8;
    if (i >= CONV_TOTAL) return;
    const float* s;
    __half* d;
    if (i < XN)                       { s = x;  d = oxh; }
    else {
        i -= XN;
        if (i < WQN)                  { s = wq; d = owq; }
        else if (i < WQN + WKN)       { s = wk; d = owk; i -= WQN; }
        else if (i < WQN + 2 * WKN)   { s = wv; d = owv; i -= WQN + WKN; }
        else                          { s = wo; d = owo; i -= WQN + 2 * WKN; }
    }
    float4 f0 = *(const float4*)(s + i);
    float4 f1 = *(const float4*)(s + i + 4);
    *(uint4*)(d + i) = make_uint4(pack_h2(f0.x, f0.y), pack_h2(f0.z, f0.w),
                                  pack_h2(f1.x, f1.y), pack_h2(f1.z, f1.w));
}

// ===========================================================================
// Single-fp16 tensor-core GEMM core: C[M,N] = Ah[M,K] @ Bh[N,K]^T + bias[N]
// CTA 128x128, K-chunk 32, 8 warps, double-buffered cp.async smem.
// Stage (16KB): Ah[128][32] | Bh[128][32]  (fp16, chunk-XOR swizzle)
// Output modes: fp32 C, or fp16 single plane (Ch) when C == nullptr.
// ===========================================================================
#define GEMM_SMEM (2 * 16384)

__device__ __forceinline__ void load_chunk_async(
    const __half* __restrict__ Ah, const __half* __restrict__ Bh,
    int K, int m0, int n0, int kc, uint32_t stage32, int tid)
{
    #pragma unroll
    for (int j = 0; j < 2; j++) {
        int job = tid + j * 256;            // 0..511
        int row = job >> 2, c16 = job & 3;  // 16B chunk = 8 fp16 k-values
        uint32_t off = (uint32_t)row * 64 + ((c16 ^ ((row >> 1) & 3)) << 4);
        size_t ga = (size_t)(m0 + row) * K + kc + c16 * 8;
        size_t gb = (size_t)(n0 + row) * K + kc + c16 * 8;
        CP_ASYNC16(stage32 + off,        Ah + ga);
        CP_ASYNC16(stage32 + 8192 + off, Bh + gb);
    }
}

__device__ __forceinline__ void gemm_core(
    const __half* __restrict__ Ah, const __half* __restrict__ Bh,
    const float* __restrict__ bias,
    float* __restrict__ C, __half* __restrict__ Ch,
    int N, int m0, int n0, uint32_t sb32)
{
    const int K = HDIM;
    const int tid  = threadIdx.x;
    const int lane = tid & 31;
    const int wid  = tid >> 5;
    const int wm   = (wid >> 1) * 32;
    const int wn   = (wid & 1) * 64;

    float acc[2][8][4];
    #pragma unroll
    for (int i = 0; i < 2; i++)
        #pragma unroll
        for (int j = 0; j < 8; j++)
            #pragma unroll
            for (int q = 0; q < 4; q++) acc[i][j][q] = 0.0f;

    const int NCH = K >> 5;

    load_chunk_async(Ah, Bh, K, m0, n0, 0, sb32, tid);
    CP_COMMIT();

    for (int c = 0; c < NCH; c++) {
        if (c + 1 < NCH) {
            load_chunk_async(Ah, Bh, K, m0, n0, (c + 1) << 5,
                             sb32 + ((c + 1) & 1) * 16384u, tid);
            CP_COMMIT();
            CP_WAIT1();
        } else {
            CP_WAIT0();
        }
        __syncthreads();

        const uint32_t stb = sb32 + (c & 1) * 16384u;

        #pragma unroll
        for (int ks = 0; ks < 2; ks++) {
            uint32_t ah[2][4];
            #pragma unroll
            for (int mt = 0; mt < 2; mt++) {
                int row = wm + mt * 16 + (lane & 15);
                int c16 = ks * 2 + (lane >> 4);
                uint32_t ad = stb + (uint32_t)row * 64 +
                              ((c16 ^ ((row >> 1) & 3)) << 4);
                ldsm_x4(ah[mt], ad);
            }
            #pragma unroll
            for (int g = 0; g < 4; g++) {
                int n   = wn + g * 16 + ((lane >> 4) & 1) * 8 + (lane & 7);
                int c16 = ks * 2 + ((lane >> 3) & 1);
                uint32_t bd = stb + 8192 + (uint32_t)n * 64 +
                              ((c16 ^ ((n >> 1) & 3)) << 4);
                uint32_t bh[4];
                ldsm_x4(bh, bd);
                #pragma unroll
                for (int mt = 0; mt < 2; mt++) {
                    #pragma unroll
                    for (int nt = 0; nt < 2; nt++) {
                        mma16816h(acc[mt][g * 2 + nt], ah[mt],
                                  bh[nt * 2], bh[nt * 2 + 1]);
                    }
                }
            }
        }
        __syncthreads();
    }

    // ---- epilogue: fused bias; fp32 or fp16-single output ----
    #pragma unroll
    for (int mt = 0; mt < 2; mt++) {
        int row0 = m0 + wm + mt * 16 + (lane >> 2);
        int row1 = row0 + 8;
        #pragma unroll
        for (int n8 = 0; n8 < 8; n8++) {
            int col = n0 + wn + n8 * 8 + (lane & 3) * 2;
            float b0 = bias[col], b1 = bias[col + 1];
            float v00 = acc[mt][n8][0] + b0, v01 = acc[mt][n8][1] + b1;
            float v10 = acc[mt][n8][2] + b0, v11 = acc[mt][n8][3] + b1;
            if (C) {
                *(float2*)(C + (size_t)row0 * N + col) = make_float2(v00, v01);
                *(float2*)(C + (size_t)row1 * N + col) = make_float2(v10, v11);
            } else {
                *(uint32_t*)(Ch + (size_t)row0 * N + col) = pack_h2(v00, v01);
                *(uint32_t*)(Ch + (size_t)row1 * N + col) = pack_h2(v10, v11);
            }
        }
    }
}

// Fused Q/K/V projection: 24 n-tiles (16 Q | 4 K | 4 V) x 32 m-tiles.
__global__ void __launch_bounds__(256, 2) gemm_qkv_fused(
    const __half* __restrict__ xh,
    const __half* __restrict__ wq, const __half* __restrict__ wk,
    const __half* __restrict__ wv,
    const float* __restrict__ bq, const float* __restrict__ bk,
    const float* __restrict__ bv,
    float* __restrict__ Qf, float* __restrict__ Kf,
    __half* __restrict__ Vh)
{
    extern __shared__ char smem[];
    const uint32_t sb32 = smem_to_u32(smem);
    const int nt = blockIdx.x;           // 0..23
    const int m0 = blockIdx.y * 128;

    if (nt < 16) {
        gemm_core(xh, wq, bq, Qf, nullptr, HDIM, m0, nt * 128, sb32);
    } else if (nt < 20) {
        gemm_core(xh, wk, bk, Kf, nullptr, KVDIM, m0, (nt - 16) * 128, sb32);
    } else {
        gemm_core(xh, wv, bv, nullptr, Vh, KVDIM, m0, (nt - 20) * 128, sb32);
    }
}

// O projection (separate: depends on attention output)
__global__ void __launch_bounds__(256, 2) gemm_o(
    const __half* __restrict__ Ah, const __half* __restrict__ Bh,
    const float* __restrict__ bias, float* __restrict__ C)
{
    extern __shared__ char smem[];
    const uint32_t sb32 = smem_to_u32(smem);
    gemm_core(Ah, Bh, bias, C, nullptr,
              HDIM, blockIdx.y * 128, blockIdx.x * 128, sb32);
}

// ---------------------------------------------------------------------------
// RoPE: Q and K -> single fp16 planes. One launch, x2 vectorized.
// ---------------------------------------------------------------------------
__global__ void rope_split_kernel(const float* __restrict__ Qf,
                                  const float* __restrict__ Kf,
                                  __half* __restrict__ Qh,
                                  __half* __restrict__ Kh,
                                  const float* __restrict__ cosb,
                                  const float* __restrict__ sinb,
                                  int totq, int total)
{
    int idx = blockIdx.x * blockDim.x + threadIdx.x;
    if (idx >= total) return;
    const float* T;
    __half* Th;
    int heads;
    if (idx < totq) { T = Qf; Th = Qh; heads = NHEADS; }
    else { idx -= totq; T = Kf; Th = Kh; heads = KVHEADS; }
    int d  = (idx & 31) * 2;
    int h  = (idx >> 5) % heads;
    int bs = idx / (32 * heads);
    int s  = bs % SEQ;
    float2 c2 = *(const float2*)(cosb + s * HEADD + d);
    float2 s2 = *(const float2*)(sinb + s * HEADD + d);
    size_t base = ((size_t)bs * heads + h) * HEADD;
    float2 qa = *(const float2*)(T + base + d);
    float2 qb = *(const float2*)(T + base + d + 64);
    float v0 = qa.x * c2.x - qb.x * s2.x;
    float v1 = qa.y * c2.y - qb.y * s2.y;
    float w0 = qb.x * c2.x + qa.x * s2.x;
    float w1 = qb.y * c2.y + qa.y * s2.y;
    *(uint32_t*)(Th + base + d)      = pack_h2(v0, v1);
    *(uint32_t*)(Th + base + d + 64) = pack_h2(w0, w1);
}

// ===========================================================================
// Tensor-core flash attention (fp16), causal, GQA rep=4, double-buffered K/V.
// BQ=128, BK=64, 8 warps. 1 CTA/SM, 96KB smem.
// smem: Q @0 (32KB) | stage s in {0,1} at 32768 + s*32768: Kh +0 | V +16384
// QK: 1 MMA (Q single x K single); scores scaled fp32; P single fp16;
// PV: 1 MMA (V single). Output single fp16 plane.
// ===========================================================================
#define ATTN_SMEM (32768 + 2 * 32768)   // 98304

__global__ void __launch_bounds__(256) attn_mma_kernel()
{
    extern __shared__ char sb[];
    const uint32_t sb32 = smem_to_u32(sb);

    const int tid  = threadIdx.x;
    const int lane = tid & 31;
    const int wid  = tid >> 5;
    const int wm   = wid * 16;

    const int q0 = (gridDim.x - 1 - blockIdx.x) * 128;   // heavy blocks first
    const int bh = blockIdx.y;
    const int b  = bh / NHEADS;
    const int h  = bh % NHEADS;
    const int kh = h / (NHEADS / KVHEADS);

    const size_t qoff = ((size_t)b * SEQ * NHEADS  + h)  * HEADD;
    const size_t koff = ((size_t)b * SEQ * KVHEADS + kh) * HEADD;
    const __half* Qh = g_Qh + qoff;
    const __half* Kh = g_Kh + koff;
    const __half* Vh = g_Vh + koff;
    const float SCALE = 0.08838834764831845f;   // 1/sqrt(128)

    // ---- load Q tile (single plane) ----
    #pragma unroll
    for (int i = 0; i < 8; i++) {
        int job = tid + i * 256;          // 0..2047
        int row = job >> 4, ch = job & 15;
        uint32_t off = (uint32_t)row * 256 + ((ch ^ (row & 7)) << 4);
        CP_ASYNC16(sb32 + off, Qh + (size_t)(q0 + row) * QSTRIDE + ch * 8);
    }
    CP_COMMIT();

    float oacc[16][4];
    #pragma unroll
    for (int t = 0; t < 16; t++)
        #pragma unroll
        for (int q = 0; q < 4; q++) oacc[t][q] = 0.0f;
    float m0r = -INFINITY, m1r = -INFINITY;
    float l0r = 0.0f, l1r = 0.0f;

    const int ktiles = q0 / 64 + 2;

    // ---- prologue: K/V tile 0 into stage 0 ----
    {
        const uint32_t st = sb32 + 32768;
        #pragma unroll
        for (int i = 0; i < 4; i++) {
            int job = tid + i * 256;
            int row = job >> 4, ch = job & 15;
            uint32_t off = (uint32_t)row * 256 + ((ch ^ (row & 7)) << 4);
            size_t ga = (size_t)row * KSTRIDE + ch * 8;
            CP_ASYNC16(st + off,         Kh + ga);
            CP_ASYNC16(st + 16384 + off, Vh + ga);
        }
        CP_COMMIT();
    }

    for (int kti = 0; kti < ktiles; kti++) {
        const int kv0 = kti * 64;

        // ---- prefetch next K/V tile into the other stage ----
        if (kti + 1 < ktiles) {
            const uint32_t st = sb32 + 32768 + ((kti + 1) & 1) * 32768u;
            const int nv0 = (kti + 1) * 64;
            #pragma unroll
            for (int i = 0; i < 4; i++) {
                int job = tid + i * 256;
                int row = job >> 4, ch = job & 15;
                uint32_t off = (uint32_t)row * 256 + ((ch ^ (row & 7)) << 4);
                size_t ga = (size_t)(nv0 + row) * KSTRIDE + ch * 8;
                CP_ASYNC16(st + off,         Kh + ga);
                CP_ASYNC16(st + 16384 + off, Vh + ga);
            }
            CP_COMMIT();
            CP_WAIT1();
        } else {
            CP_WAIT0();
        }
        __syncthreads();

        if (kv0 <= q0 + wm + 15) {      // not fully masked for this warp
        const uint32_t stK = sb32 + 32768 + (kti & 1) * 32768u;
        const uint32_t stV = stK + 16384;

        // ---- S = Q K^T (1 MMA per fragment) ----
        float sc[8][4];
        #pragma unroll
        for (int t = 0; t < 8; t++)
            #pragma unroll
            for (int q = 0; q < 4; q++) sc[t][q] = 0.0f;

        #pragma unroll
        for (int ks = 0; ks < 8; ks++) {
            int arow = wm + (lane & 15);
            int ach  = 2 * ks + (lane >> 4);
            uint32_t aaddr = sb32 + (uint32_t)arow * 256 +
                             ((ach ^ (arow & 7)) << 4);
            uint32_t ah[4];
            ldsm_x4(ah, aaddr);
            #pragma unroll
            for (int g = 0; g < 4; g++) {
                int nrow = g * 16 + ((lane >> 4) & 1) * 8 + (lane & 7);
                int nch  = 2 * ks + ((lane >> 3) & 1);
                uint32_t baddr = stK + (uint32_t)nrow * 256 +
                                 ((nch ^ (nrow & 7)) << 4);
                uint32_t bh_[4];
                ldsm_x4(bh_, baddr);
                #pragma unroll
                for (int nt = 0; nt < 2; nt++) {
                    mma16816h(sc[g * 2 + nt], ah,
                              bh_[nt * 2], bh_[nt * 2 + 1]);
                }
            }
        }

        // ---- scale scores (fp32) ----
        #pragma unroll
        for (int t = 0; t < 8; t++)
            #pragma unroll
            for (int q = 0; q < 4; q++) sc[t][q] *= SCALE;

        // ---- causal mask (near-diagonal tiles only) ----
        if (kv0 + 63 > q0 + wm) {
            int r0g = q0 + wm + (lane >> 2);
            int r1g = r0g + 8;
            #pragma unroll
            for (int t = 0; t < 8; t++) {
                int kva = kv0 + t * 8 + (lane & 3) * 2;
                int kvb = kva + 1;
                if (kva > r0g) sc[t][0] = -1.0e30f;
                if (kvb > r0g) sc[t][1] = -1.0e30f;
                if (kva > r1g) sc[t][2] = -1.0e30f;
                if (kvb > r1g) sc[t][3] = -1.0e30f;
            }
        }

        // ---- online softmax (quad reductions in accumulator layout) ----
        float mx0 = m0r, mx1 = m1r;
        #pragma unroll
        for (int t = 0; t < 8; t++) {
            mx0 = fmaxf(mx0, fmaxf(sc[t][0], sc[t][1]));
            mx1 = fmaxf(mx1, fmaxf(sc[t][2], sc[t][3]));
        }
        mx0 = fmaxf(mx0, __shfl_xor_sync(0xffffffffu, mx0, 1));
        mx0 = fmaxf(mx0, __shfl_xor_sync(0xffffffffu, mx0, 2));
        mx1 = fmaxf(mx1, __shfl_xor_sync(0xffffffffu, mx1, 1));
        mx1 = fmaxf(mx1, __shfl_xor_sync(0xffffffffu, mx1, 2));

        float corr0 = __expf(m0r - mx0);
        float corr1 = __expf(m1r - mx1);
        m0r = mx0; m1r = mx1;

        float sum0 = 0.0f, sum1 = 0.0f;
        #pragma unroll
        for (int t = 0; t < 8; t++) {
            sc[t][0] = __expf(sc[t][0] - mx0); sum0 += sc[t][0];
            sc[t][1] = __expf(sc[t][1] - mx0); sum0 += sc[t][1];
            sc[t][2] = __expf(sc[t][2] - mx1); sum1 += sc[t][2];
            sc[t][3] = __expf(sc[t][3] - mx1); sum1 += sc[t][3];
        }
        sum0 += __shfl_xor_sync(0xffffffffu, sum0, 1);
        sum0 += __shfl_xor_sync(0xffffffffu, sum0, 2);
        sum1 += __shfl_xor_sync(0xffffffffu, sum1, 1);
        sum1 += __shfl_xor_sync(0xffffffffu, sum1, 2);
        l0r = l0r * corr0 + sum0;
        l1r = l1r * corr1 + sum1;

        #pragma unroll
        for (int t = 0; t < 16; t++) {
            oacc[t][0] *= corr0; oacc[t][1] *= corr0;
            oacc[t][2] *= corr1; oacc[t][3] *= corr1;
        }

        // ---- O += P V (P single fp16, V single plane): 1 MMA ----
        #pragma unroll
        for (int kt = 0; kt < 4; kt++) {
            uint32_t pa[4];
            pa[0] = pack_h2(sc[2 * kt][0],     sc[2 * kt][1]);
            pa[1] = pack_h2(sc[2 * kt][2],     sc[2 * kt][3]);
            pa[2] = pack_h2(sc[2 * kt + 1][0], sc[2 * kt + 1][1]);
            pa[3] = pack_h2(sc[2 * kt + 1][2], sc[2 * kt + 1][3]);
            #pragma unroll
            for (int dg = 0; dg < 8; dg++) {
                int vrow = kt * 16 + ((lane >> 3) & 1) * 8 + (lane & 7);
                int vch  = dg * 2 + (lane >> 4);
                uint32_t vaddr = stV + (uint32_t)vrow * 256 +
                                 ((vch ^ (vrow & 7)) << 4);
                uint32_t vh[4];
                ldsm_x4_trans(vh, vaddr);
                #pragma unroll
                for (int nt = 0; nt < 2; nt++) {
                    mma16816h(oacc[dg * 2 + nt], pa,
                              vh[nt * 2], vh[nt * 2 + 1]);
                }
            }
        }
        }   // masked-warp guard

        __syncthreads();   // all warps done with stage kti&1 before refill
    }

    // ---- epilogue: normalize, write single fp16 plane ----
    {
        float inv0 = 1.0f / l0r, inv1 = 1.0f / l1r;
        int r0g = q0 + wm + (lane >> 2);
        int r1g = r0g + 8;
        size_t b0 = ((size_t)(b * SEQ + r0g) * NHEADS + h) * HEADD;
        size_t b1 = ((size_t)(b * SEQ + r1g) * NHEADS + h) * HEADD;
        #pragma unroll
        for (int t = 0; t < 16; t++) {
            int d = t * 8 + (lane & 3) * 2;
            *(uint32_t*)(g_Oh + b0 + d) =
                pack_h2(oacc[t][0] * inv0, oacc[t][1] * inv0);
            *(uint32_t*)(g_Oh + b1 + d) =
                pack_h2(oacc[t][2] * inv1, oacc[t][3] * inv1);
        }
    }
}

// ---------------------------------------------------------------------------
extern "C" void kernel_launch(void* const* d_in, const int* in_sizes, int n_in,
                              void* d_out, int out_size)
{
    const float* x    = (const float*)d_in[0];
    const float* wq   = (const float*)d_in[1];
    const float* bq   = (const float*)d_in[2];
    const float* wk   = (const float*)d_in[3];
    const float* bk   = (const float*)d_in[4];
    const float* wv   = (const float*)d_in[5];
    const float* bv   = (const float*)d_in[6];
    const float* wo   = (const float*)d_in[7];
    const float* bo   = (const float*)d_in[8];
    const float* cosb = (const float*)d_in[9];
    const float* sinb = (const float*)d_in[10];
    float* out = (float*)d_out;

    float *Qp, *Kp;
    cudaGetSymbolAddress((void**)&Qp, g_Q);
    cudaGetSymbolAddress((void**)&Kp, g_K);
    __half *xh, *wqh, *wkh, *wvh, *woh;
    __half *qh, *kH, *vh, *oh;
    cudaGetSymbolAddress((void**)&xh, g_xh);
    cudaGetSymbolAddress((void**)&wqh, g_wq);  cudaGetSymbolAddress((void**)&wkh, g_wk);
    cudaGetSymbolAddress((void**)&wvh, g_wv);  cudaGetSymbolAddress((void**)&woh, g_wo);
    cudaGetSymbolAddress((void**)&qh, g_Qh);   cudaGetSymbolAddress((void**)&kH, g_Kh);
    cudaGetSymbolAddress((void**)&vh, g_Vh);   cudaGetSymbolAddress((void**)&oh, g_Oh);

    cudaFuncSetAttribute(gemm_qkv_fused,
                         cudaFuncAttributeMaxDynamicSharedMemorySize, GEMM_SMEM);
    cudaFuncSetAttribute(gemm_o,
                         cudaFuncAttributeMaxDynamicSharedMemorySize, GEMM_SMEM);
    cudaFuncSetAttribute(attn_mma_kernel,
                         cudaFuncAttributeMaxDynamicSharedMemorySize, ATTN_SMEM);

    // 0. One-shot conversion of all inputs (single launch, all single planes)
    convert_all_kernel<<<CONV_TOTAL / 8 / 256, 256>>>(
        x, wq, wk, wv, wo, xh, wqh, wkh, wvh, woh);

    // 1. Fused QKV projection (+bias): 24 n-tiles x 32 m-tiles
    gemm_qkv_fused<<<dim3(24, MROWS / 128), 256, GEMM_SMEM>>>(
        xh, wqh, wkh, wvh, bq, bk, bv, Qp, Kp, vh);

    // 2. RoPE: Q and K -> single fp16 planes (one launch, x2 vectorized)
    {
        int totq = NB * SEQ * NHEADS * 32;
        int totk = NB * SEQ * KVHEADS * 32;
        int tot  = totq + totk;
        rope_split_kernel<<<(tot + 255) / 256, 256>>>(
            Qp, Kp, qh, kH, cosb, sinb, totq, tot);
    }

    // 3. Causal GQA flash attention (fp16 tensor cores, double-buffered K/V)
    attn_mma_kernel<<<dim3(SEQ / 128, NB * NHEADS), 256, ATTN_SMEM>>>();

    // 4. Output projection (+bias) straight into d_out
    gemm_o<<<dim3(HDIM / 128, MROWS / 128), 256, GEMM_SMEM>>>(
        oh, woh, bo, out);
}